// round 1
// baseline (speedup 1.0000x reference)
#include <cuda_runtime.h>
#include <math.h>
#include <stdint.h>

#define NB 16
#define NS 4096
#define NDIN 64
#define NE 512
#define NM 128
#define NL 4
#define ROWS (NB*NS)        /* 65536 */
#define HID (4*NE)          /* 2048 */

// ---------------- scratch (device globals; no allocations allowed) ----------
__device__ float g_h [(size_t)ROWS*NE];
__device__ float g_q [(size_t)ROWS*NE];
__device__ float g_k [(size_t)ROWS*NE];
__device__ float g_v [(size_t)ROWS*NE];
__device__ float g_pq[(size_t)ROWS*NM];
__device__ float g_pk[(size_t)ROWS*NM];
__device__ float g_kv[(size_t)NB*NM*NE];
__device__ float g_z [NB*NM];
__device__ float g_ff[(size_t)ROWS*HID];
__device__ float g_part[ROWS];
__device__ float g_max[1];
__device__ float g_r1[16*256];

// ---------------- generic SGEMM: C = op(A)*B (+bias) (+act) -----------------
// A row-major [M,K] (or transA: element (m,k) = A[k*lda+m]); B row-major [K,N].
// Requires K % 8 == 0. Handles partial M/N tiles. batch via blockIdx.z.
#define BM 128
#define BN 128
#define BK 8

template<int TRANS_A, int ACT>
__global__ __launch_bounds__(256)
void gemm_k(const float* __restrict__ A, int lda, size_t sA,
            const float* __restrict__ Bm, int ldb, size_t sB,
            float* __restrict__ C, int ldc, size_t sC,
            const float* __restrict__ bias,
            int M, int N, int K)
{
    int bz = blockIdx.z;
    A  += (size_t)bz * sA;
    Bm += (size_t)bz * sB;
    C  += (size_t)bz * sC;
    int m0 = blockIdx.y * BM;
    int n0 = blockIdx.x * BN;

    __shared__ float As[BK][BM];
    __shared__ float Bs[BK][BN];

    int tid = threadIdx.x;        // 256
    int tx = tid & 15, ty = tid >> 4;

    float acc[8][8];
#pragma unroll
    for (int i = 0; i < 8; i++)
#pragma unroll
        for (int j = 0; j < 8; j++) acc[i][j] = 0.f;

    float ar[8], br[8];

    for (int k0 = 0; k0 < K; k0 += BK) {
        // ---- load A tile ----
        if (TRANS_A) {
            int k = tid >> 5;           // 0..7
            int m = (tid & 31) * 4;     // 0..124
            const float* src = A + (size_t)(k0 + k) * lda + m0 + m;
#pragma unroll
            for (int i = 0; i < 4; i++) {
                float vv = 0.f;
                if (m0 + m + i < M) vv = src[i];
                As[k][m + i] = vv;
            }
        } else {
            int m  = tid >> 1;          // 0..127
            int kk = (tid & 1) * 4;     // 0 or 4
            const float* src = A + (size_t)(m0 + m) * lda + k0 + kk;
            bool mok = (m0 + m) < M;
#pragma unroll
            for (int i = 0; i < 4; i++)
                As[kk + i][m] = mok ? src[i] : 0.f;
        }
        // ---- load B tile ----
        {
            int k = tid >> 5;
            int n = (tid & 31) * 4;
            const float* src = Bm + (size_t)(k0 + k) * ldb + n0 + n;
#pragma unroll
            for (int i = 0; i < 4; i++) {
                float vv = 0.f;
                if (n0 + n + i < N) vv = src[i];
                Bs[k][n + i] = vv;
            }
        }
        __syncthreads();
#pragma unroll
        for (int k = 0; k < BK; k++) {
            *(float4*)&ar[0] = *(float4*)&As[k][ty * 4];
            *(float4*)&ar[4] = *(float4*)&As[k][64 + ty * 4];
            *(float4*)&br[0] = *(float4*)&Bs[k][tx * 4];
            *(float4*)&br[4] = *(float4*)&Bs[k][64 + tx * 4];
#pragma unroll
            for (int i = 0; i < 8; i++)
#pragma unroll
                for (int j = 0; j < 8; j++)
                    acc[i][j] = fmaf(ar[i], br[j], acc[i][j]);
        }
        __syncthreads();
    }

#pragma unroll
    for (int i = 0; i < 8; i++) {
        int m = m0 + ((i < 4) ? (ty * 4 + i) : (64 + ty * 4 + i - 4));
        if (m >= M) continue;
#pragma unroll
        for (int j = 0; j < 8; j++) {
            int n = n0 + ((j < 4) ? (tx * 4 + j) : (64 + tx * 4 + j - 4));
            if (n >= N) continue;
            float vv = acc[i][j];
            if (bias) vv += bias[n];
            if (ACT == 1) vv = 0.5f * vv * (1.f + erff(vv * 0.7071067811865476f));
            else if (ACT == 2) vv = fmaxf(vv, 0.f);
            C[(size_t)m * ldc + n] = vv;
        }
    }
}

// ---------------- elementwise / reduction kernels ---------------------------

__global__ void addpos_k(float* __restrict__ h, const float* __restrict__ pos) {
    size_t i = (size_t)blockIdx.x * 256 + threadIdx.x;
    if (i < (size_t)ROWS * NE) h[i] += pos[i % ((size_t)NS * NE)];
}

__global__ void add_k(float* __restrict__ a, const float* __restrict__ b, size_t n) {
    size_t i = (size_t)blockIdx.x * 256 + threadIdx.x;
    if (i < n) a[i] += b[i];
}

__global__ void zero_k(float* p, int n) {
    int i = blockIdx.x * 256 + threadIdx.x;
    if (i < n) p[i] = 0.f;
}

// logits (in-place over G = q@R), block = one row of 128 logits; also per-row max.
__global__ void phi_logits_k(float* __restrict__ G, const float* __restrict__ U,
                             float* __restrict__ part) {
    int row = blockIdx.x;
    int t = threadIdx.x;             // 128
    __shared__ float sh[128];
    const float* u = U + (size_t)row * NE;
    float s = 0.f;
#pragma unroll
    for (int j = 0; j < NE; j += 128) { float x = u[t + j]; s = fmaf(x, x, s); }
    sh[t] = s; __syncthreads();
    for (int o = 64; o > 0; o >>= 1) { if (t < o) sh[t] += sh[t + o]; __syncthreads(); }
    float norm2 = sh[0];
    const float scale  = 0.21022410381342865f;  // 512^-0.25
    const float scale2 = 0.04419417382415922f;  // 512^-0.5
    float* g = G + (size_t)row * NM;
    float l = fmaf(scale, g[t], -0.5f * scale2 * norm2);
    g[t] = l;
    __syncthreads();
    sh[t] = l; __syncthreads();
    for (int o = 64; o > 0; o >>= 1) { if (t < o) sh[t] = fmaxf(sh[t], sh[t + o]); __syncthreads(); }
    if (t == 0) part[row] = sh[0];
}

__global__ void maxred_k(const float* __restrict__ part, int n, float* __restrict__ out) {
    __shared__ float sh[1024];
    int t = threadIdx.x;
    float m = -INFINITY;
    for (int i = t; i < n; i += 1024) m = fmaxf(m, part[i]);
    sh[t] = m; __syncthreads();
    for (int o = 512; o > 0; o >>= 1) { if (t < o) sh[t] = fmaxf(sh[t], sh[t + o]); __syncthreads(); }
    if (t == 0) out[0] = sh[0];
}

__global__ void phiexp_k(float* __restrict__ G, const float* __restrict__ mx, size_t n) {
    size_t i = (size_t)blockIdx.x * 256 + threadIdx.x;
    if (i < n) G[i] = expf(G[i] - mx[0]) * 0.08838834764831845f; // 1/sqrt(128)
}

// z[b,m] = sum_s pk[b,s,m]; grid (NB, 32), block 128
__global__ void colsum_k(const float* __restrict__ pk, float* __restrict__ z) {
    int b = blockIdx.x, chunk = blockIdx.y, m = threadIdx.x;
    const float* p = pk + (size_t)b * NS * NM + (size_t)chunk * 128 * NM + m;
    float s = 0.f;
    for (int i = 0; i < 128; i++) s += p[(size_t)i * NM];
    atomicAdd(&z[b * NM + m], s);
}

// num[row,:] /= (pq[row,:].z[b,:] + 1e-6); one warp per row.
__global__ void divden_k(float* __restrict__ num, const float* __restrict__ pq,
                         const float* __restrict__ z) {
    int warp = threadIdx.x >> 5, lane = threadIdx.x & 31;
    int row = blockIdx.x * 8 + warp;
    int b = row / NS;
    const float* p  = pq + (size_t)row * NM;
    const float* zz = z + b * NM;
    float s = 0.f;
#pragma unroll
    for (int j = 0; j < 4; j++) s = fmaf(p[lane + 32 * j], zz[lane + 32 * j], s);
#pragma unroll
    for (int o = 16; o > 0; o >>= 1) s += __shfl_xor_sync(0xffffffffu, s, o);
    float inv = 1.f / (s + 1e-6f);
    float* nm = num + (size_t)row * NE;
#pragma unroll
    for (int j = 0; j < NE / 32; j++) nm[lane + 32 * j] *= inv;
}

// LayerNorm over E=512, one block (256 thr) per row, two-pass mean/var.
__global__ void ln_k(const float* __restrict__ in, float* __restrict__ out,
                     const float* __restrict__ g, const float* __restrict__ b) {
    int row = blockIdx.x, t = threadIdx.x;
    __shared__ float sh[256];
    const float* a = in + (size_t)row * NE;
    float x0 = a[t], x1 = a[t + 256];
    sh[t] = x0 + x1; __syncthreads();
    for (int o = 128; o > 0; o >>= 1) { if (t < o) sh[t] += sh[t + o]; __syncthreads(); }
    float mu = sh[0] * (1.f / NE);
    __syncthreads();
    float d0 = x0 - mu, d1 = x1 - mu;
    sh[t] = d0 * d0 + d1 * d1; __syncthreads();
    for (int o = 128; o > 0; o >>= 1) { if (t < o) sh[t] += sh[t + o]; __syncthreads(); }
    float rstd = rsqrtf(sh[0] * (1.f / NE) + 1e-5f);
    out[(size_t)row * NE + t]       = d0 * rstd * g[t] + b[t];
    out[(size_t)row * NE + t + 256] = d1 * rstd * g[t + 256] + b[t + 256];
}

// ---------------- host-side dispatch ----------------------------------------

static void gemm(int ta, int act,
                 const float* A, int lda, size_t sA,
                 const float* Bm, int ldb, size_t sB,
                 float* C, int ldc, size_t sC,
                 const float* bias, int M, int N, int K, int batch)
{
    dim3 grid((N + BN - 1) / BN, (M + BM - 1) / BM, batch);
    dim3 blk(256);
    if (ta == 1)            gemm_k<1,0><<<grid,blk>>>(A,lda,sA,Bm,ldb,sB,C,ldc,sC,bias,M,N,K);
    else if (act == 1)      gemm_k<0,1><<<grid,blk>>>(A,lda,sA,Bm,ldb,sB,C,ldc,sC,bias,M,N,K);
    else if (act == 2)      gemm_k<0,2><<<grid,blk>>>(A,lda,sA,Bm,ldb,sB,C,ldc,sC,bias,M,N,K);
    else                    gemm_k<0,0><<<grid,blk>>>(A,lda,sA,Bm,ldb,sB,C,ldc,sC,bias,M,N,K);
}

extern "C" void kernel_launch(void* const* d_in, const int* in_sizes, int n_in,
                              void* d_out, int out_size)
{
    const float* x    = (const float*)d_in[0];
    const float* Wi   = (const float*)d_in[1];
    const float* bi   = (const float*)d_in[2];
    const float* pos  = (const float*)d_in[3];
    const float* Wq   = (const float*)d_in[4];
    const float* bq   = (const float*)d_in[5];
    const float* Wk   = (const float*)d_in[6];
    const float* bk   = (const float*)d_in[7];
    const float* Wv   = (const float*)d_in[8];
    const float* bv   = (const float*)d_in[9];
    const float* Wo   = (const float*)d_in[10];
    const float* bo   = (const float*)d_in[11];
    const float* R    = (const float*)d_in[12];
    const float* lng  = (const float*)d_in[13];
    const float* lnb  = (const float*)d_in[14];
    const float* W1   = (const float*)d_in[15];
    const float* b1   = (const float*)d_in[16];
    const float* W2   = (const float*)d_in[17];
    const float* b2   = (const float*)d_in[18];
    const float* Wr1  = (const float*)d_in[19];
    const float* br1  = (const float*)d_in[20];
    const float* Wr2  = (const float*)d_in[21];
    const float* br2  = (const float*)d_in[22];
    float* out = (float*)d_out;

    float *h,*q,*k,*v,*pq,*pk,*kv,*z,*ff,*part,*mx,*r1;
    cudaGetSymbolAddress((void**)&h,  g_h);
    cudaGetSymbolAddress((void**)&q,  g_q);
    cudaGetSymbolAddress((void**)&k,  g_k);
    cudaGetSymbolAddress((void**)&v,  g_v);
    cudaGetSymbolAddress((void**)&pq, g_pq);
    cudaGetSymbolAddress((void**)&pk, g_pk);
    cudaGetSymbolAddress((void**)&kv, g_kv);
    cudaGetSymbolAddress((void**)&z,  g_z);
    cudaGetSymbolAddress((void**)&ff, g_ff);
    cudaGetSymbolAddress((void**)&part, g_part);
    cudaGetSymbolAddress((void**)&mx, g_max);
    cudaGetSymbolAddress((void**)&r1, g_r1);

    const size_t nHE = (size_t)ROWS * NE;
    const size_t nHM = (size_t)ROWS * NM;
    int ew_grid = (int)((nHE + 255) / 256);
    int pm_grid = (int)((nHM + 255) / 256);

    // h = x @ Wi + bi + pos
    gemm(0,0, x, NDIN,0, Wi, NE,0, h, NE,0, bi, ROWS, NE, NDIN, 1);
    addpos_k<<<ew_grid,256>>>(h, pos);

    for (int i = 0; i < NL; i++) {
        const float* Wq_i = Wq + (size_t)i*NE*NE;   const float* bq_i = bq + (size_t)i*NE;
        const float* Wk_i = Wk + (size_t)i*NE*NE;   const float* bk_i = bk + (size_t)i*NE;
        const float* Wv_i = Wv + (size_t)i*NE*NE;   const float* bv_i = bv + (size_t)i*NE;
        const float* Wo_i = Wo + (size_t)i*NE*NE;   const float* bo_i = bo + (size_t)i*NE;
        const float* R_i  = R  + (size_t)i*NE*NM;
        const float* g_i  = lng + (size_t)i*NE;     const float* b_i  = lnb + (size_t)i*NE;
        const float* W1_i = W1 + (size_t)i*NE*HID;  const float* b1_i = b1 + (size_t)i*HID;
        const float* W2_i = W2 + (size_t)i*HID*NE;  const float* b2_i = b2 + (size_t)i*NE;

        // projections
        gemm(0,0, h, NE,0, Wq_i, NE,0, q, NE,0, bq_i, ROWS, NE, NE, 1);
        gemm(0,0, h, NE,0, Wk_i, NE,0, k, NE,0, bk_i, ROWS, NE, NE, 1);
        gemm(0,0, h, NE,0, Wv_i, NE,0, v, NE,0, bv_i, ROWS, NE, NE, 1);

        // pq = phi(q*scale, R)
        gemm(0,0, q, NE,0, R_i, NM,0, pq, NM,0, nullptr, ROWS, NM, NE, 1);
        phi_logits_k<<<ROWS,128>>>(pq, q, part);
        maxred_k<<<1,1024>>>(part, ROWS, mx);
        phiexp_k<<<pm_grid,256>>>(pq, mx, nHM);

        // pk = phi(k*scale, R)
        gemm(0,0, k, NE,0, R_i, NM,0, pk, NM,0, nullptr, ROWS, NM, NE, 1);
        phi_logits_k<<<ROWS,128>>>(pk, k, part);
        maxred_k<<<1,1024>>>(part, ROWS, mx);
        phiexp_k<<<pm_grid,256>>>(pk, mx, nHM);

        // kv[b] = pk[b]^T @ v[b]   (batched, transA)
        gemm(1,0, pk, NM, (size_t)NS*NM, v, NE, (size_t)NS*NE,
             kv, NE, (size_t)NM*NE, nullptr, NM, NE, NS, NB);

        // z[b] = sum_s pk[b,s,:]
        zero_k<<<(NB*NM+255)/256,256>>>(z, NB*NM);
        colsum_k<<<dim3(NB,32),128>>>(pk, z);

        // num -> q (batched)
        gemm(0,0, pq, NM, (size_t)NS*NM, kv, NE, (size_t)NM*NE,
             q, NE, (size_t)NS*NE, nullptr, NS, NE, NM, NB);

        // q /= (pq . z + 1e-6)
        divden_k<<<ROWS/8,256>>>(q, pq, z);

        // a -> k
        gemm(0,0, q, NE,0, Wo_i, NE,0, k, NE,0, bo_i, ROWS, NE, NE, 1);

        // y -> v (LayerNorm)
        ln_k<<<ROWS,256>>>(k, v, g_i, b_i);

        // ff1 = gelu(y @ W1 + b1)
        gemm(0,1, v, NE,0, W1_i, HID,0, ff, HID,0, b1_i, ROWS, HID, NE, 1);
        // ff2 -> q
        gemm(0,0, ff, HID,0, W2_i, NE,0, q, NE,0, b2_i, ROWS, NE, HID, 1);
        // h += ff2
        add_k<<<ew_grid,256>>>(h, q, nHE);
    }

    // head: pooled = h[:,0,:] (row stride S*E)
    gemm(0,2, h, NS*NE,0, Wr1, 256,0, r1, 256,0, br1, NB, 256, NE, 1);
    gemm(0,0, r1, 256,0, Wr2, 1,0, out, 1,0, br2, NB, 1, 256, 1);
}

// round 2
// speedup vs baseline: 1.0001x; 1.0001x over previous
#include <cuda_runtime.h>
#include <math.h>
#include <stdint.h>

#define NB 16
#define NS 4096
#define NDIN 64
#define NE 512
#define NM 128
#define NL 4
#define ROWS (NB*NS)        /* 65536 */
#define HID (4*NE)          /* 2048 */

// ---------------- scratch (device globals; no allocations allowed) ----------
__device__ float g_h [(size_t)ROWS*NE];
__device__ float g_q [(size_t)ROWS*NE];
__device__ float g_k [(size_t)ROWS*NE];
__device__ float g_v [(size_t)ROWS*NE];
__device__ float g_pq[(size_t)ROWS*NM];
__device__ float g_pk[(size_t)ROWS*NM];
__device__ float g_kv[(size_t)NB*NM*NE];
__device__ float g_z [NB*NM];
__device__ float g_ff[(size_t)ROWS*HID];
__device__ float g_part[ROWS];
__device__ float g_max[1];
__device__ float g_r1[16*256];

// ---------------- generic SGEMM: C = op(A)*B (+bias) (+act) -----------------
// A row-major [M,K] (or transA: element (m,k) = A[k*lda+m]); B row-major [K,N].
// Requires K % 8 == 0. Handles partial M/N tiles. batch via blockIdx.z.
#define BM 128
#define BN 128
#define BK 8

template<int TRANS_A, int ACT>
__global__ __launch_bounds__(256)
void gemm_k(const float* __restrict__ A, int lda, size_t sA,
            const float* __restrict__ Bm, int ldb, size_t sB,
            float* __restrict__ C, int ldc, size_t sC,
            const float* __restrict__ bias,
            int M, int N, int K)
{
    int bz = blockIdx.z;
    A  += (size_t)bz * sA;
    Bm += (size_t)bz * sB;
    C  += (size_t)bz * sC;
    int m0 = blockIdx.y * BM;
    int n0 = blockIdx.x * BN;

    __shared__ float As[BK][BM];
    __shared__ float Bs[BK][BN];

    int tid = threadIdx.x;        // 256
    int tx = tid & 15, ty = tid >> 4;

    float acc[8][8];
#pragma unroll
    for (int i = 0; i < 8; i++)
#pragma unroll
        for (int j = 0; j < 8; j++) acc[i][j] = 0.f;

    float ar[8], br[8];

    for (int k0 = 0; k0 < K; k0 += BK) {
        // ---- load A tile ----
        if (TRANS_A) {
            int k = tid >> 5;           // 0..7
            int m = (tid & 31) * 4;     // 0..124
            const float* src = A + (size_t)(k0 + k) * lda + m0 + m;
#pragma unroll
            for (int i = 0; i < 4; i++) {
                float vv = 0.f;
                if (m0 + m + i < M) vv = src[i];
                As[k][m + i] = vv;
            }
        } else {
            int m  = tid >> 1;          // 0..127
            int kk = (tid & 1) * 4;     // 0 or 4
            const float* src = A + (size_t)(m0 + m) * lda + k0 + kk;
            bool mok = (m0 + m) < M;
#pragma unroll
            for (int i = 0; i < 4; i++)
                As[kk + i][m] = mok ? src[i] : 0.f;
        }
        // ---- load B tile ----
        {
            int k = tid >> 5;
            int n = (tid & 31) * 4;
            const float* src = Bm + (size_t)(k0 + k) * ldb + n0 + n;
#pragma unroll
            for (int i = 0; i < 4; i++) {
                float vv = 0.f;
                if (n0 + n + i < N) vv = src[i];
                Bs[k][n + i] = vv;
            }
        }
        __syncthreads();
#pragma unroll
        for (int k = 0; k < BK; k++) {
            *(float4*)&ar[0] = *(float4*)&As[k][ty * 4];
            *(float4*)&ar[4] = *(float4*)&As[k][64 + ty * 4];
            *(float4*)&br[0] = *(float4*)&Bs[k][tx * 4];
            *(float4*)&br[4] = *(float4*)&Bs[k][64 + tx * 4];
#pragma unroll
            for (int i = 0; i < 8; i++)
#pragma unroll
                for (int j = 0; j < 8; j++)
                    acc[i][j] = fmaf(ar[i], br[j], acc[i][j]);
        }
        __syncthreads();
    }

#pragma unroll
    for (int i = 0; i < 8; i++) {
        int m = m0 + ((i < 4) ? (ty * 4 + i) : (64 + ty * 4 + i - 4));
        if (m >= M) continue;
#pragma unroll
        for (int j = 0; j < 8; j++) {
            int n = n0 + ((j < 4) ? (tx * 4 + j) : (64 + tx * 4 + j - 4));
            if (n >= N) continue;
            float vv = acc[i][j];
            if (bias) vv += bias[n];
            if (ACT == 1) vv = 0.5f * vv * (1.f + erff(vv * 0.7071067811865476f));
            else if (ACT == 2) vv = fmaxf(vv, 0.f);
            C[(size_t)m * ldc + n] = vv;
        }
    }
}

// ---------------- elementwise / reduction kernels ---------------------------

__global__ void addpos_k(float* __restrict__ h, const float* __restrict__ pos) {
    size_t i = (size_t)blockIdx.x * 256 + threadIdx.x;
    if (i < (size_t)ROWS * NE) h[i] += pos[i % ((size_t)NS * NE)];
}

__global__ void add_k(float* __restrict__ a, const float* __restrict__ b, size_t n) {
    size_t i = (size_t)blockIdx.x * 256 + threadIdx.x;
    if (i < n) a[i] += b[i];
}

__global__ void zero_k(float* p, int n) {
    int i = blockIdx.x * 256 + threadIdx.x;
    if (i < n) p[i] = 0.f;
}

// logits (in-place over G = q@R), block = one row of 128 logits; also per-row max.
__global__ void phi_logits_k(float* __restrict__ G, const float* __restrict__ U,
                             float* __restrict__ part) {
    int row = blockIdx.x;
    int t = threadIdx.x;             // 128
    __shared__ float sh[128];
    const float* u = U + (size_t)row * NE;
    float s = 0.f;
#pragma unroll
    for (int j = 0; j < NE; j += 128) { float x = u[t + j]; s = fmaf(x, x, s); }
    sh[t] = s; __syncthreads();
    for (int o = 64; o > 0; o >>= 1) { if (t < o) sh[t] += sh[t + o]; __syncthreads(); }
    float norm2 = sh[0];
    const float scale  = 0.21022410381342865f;  // 512^-0.25
    const float scale2 = 0.04419417382415922f;  // 512^-0.5
    float* g = G + (size_t)row * NM;
    float l = fmaf(scale, g[t], -0.5f * scale2 * norm2);
    g[t] = l;
    __syncthreads();
    sh[t] = l; __syncthreads();
    for (int o = 64; o > 0; o >>= 1) { if (t < o) sh[t] = fmaxf(sh[t], sh[t + o]); __syncthreads(); }
    if (t == 0) part[row] = sh[0];
}

__global__ void maxred_k(const float* __restrict__ part, int n, float* __restrict__ out) {
    __shared__ float sh[1024];
    int t = threadIdx.x;
    float m = -INFINITY;
    for (int i = t; i < n; i += 1024) m = fmaxf(m, part[i]);
    sh[t] = m; __syncthreads();
    for (int o = 512; o > 0; o >>= 1) { if (t < o) sh[t] = fmaxf(sh[t], sh[t + o]); __syncthreads(); }
    if (t == 0) out[0] = sh[0];
}

__global__ void phiexp_k(float* __restrict__ G, const float* __restrict__ mx, size_t n) {
    size_t i = (size_t)blockIdx.x * 256 + threadIdx.x;
    if (i < n) G[i] = expf(G[i] - mx[0]) * 0.08838834764831845f; // 1/sqrt(128)
}

// z[b,m] = sum_s pk[b,s,m]; grid (NB, 32), block 128
__global__ void colsum_k(const float* __restrict__ pk, float* __restrict__ z) {
    int b = blockIdx.x, chunk = blockIdx.y, m = threadIdx.x;
    const float* p = pk + (size_t)b * NS * NM + (size_t)chunk * 128 * NM + m;
    float s = 0.f;
    for (int i = 0; i < 128; i++) s += p[(size_t)i * NM];
    atomicAdd(&z[b * NM + m], s);
}

// num[row,:] /= (pq[row,:].z[b,:] + 1e-6); one warp per row.
__global__ void divden_k(float* __restrict__ num, const float* __restrict__ pq,
                         const float* __restrict__ z) {
    int warp = threadIdx.x >> 5, lane = threadIdx.x & 31;
    int row = blockIdx.x * 8 + warp;
    int b = row / NS;
    const float* p  = pq + (size_t)row * NM;
    const float* zz = z + b * NM;
    float s = 0.f;
#pragma unroll
    for (int j = 0; j < 4; j++) s = fmaf(p[lane + 32 * j], zz[lane + 32 * j], s);
#pragma unroll
    for (int o = 16; o > 0; o >>= 1) s += __shfl_xor_sync(0xffffffffu, s, o);
    float inv = 1.f / (s + 1e-6f);
    float* nm = num + (size_t)row * NE;
#pragma unroll
    for (int j = 0; j < NE / 32; j++) nm[lane + 32 * j] *= inv;
}

// LayerNorm over E=512, one block (256 thr) per row, two-pass mean/var.
__global__ void ln_k(const float* __restrict__ in, float* __restrict__ out,
                     const float* __restrict__ g, const float* __restrict__ b) {
    int row = blockIdx.x, t = threadIdx.x;
    __shared__ float sh[256];
    const float* a = in + (size_t)row * NE;
    float x0 = a[t], x1 = a[t + 256];
    sh[t] = x0 + x1; __syncthreads();
    for (int o = 128; o > 0; o >>= 1) { if (t < o) sh[t] += sh[t + o]; __syncthreads(); }
    float mu = sh[0] * (1.f / NE);
    __syncthreads();
    float d0 = x0 - mu, d1 = x1 - mu;
    sh[t] = d0 * d0 + d1 * d1; __syncthreads();
    for (int o = 128; o > 0; o >>= 1) { if (t < o) sh[t] += sh[t + o]; __syncthreads(); }
    float rstd = rsqrtf(sh[0] * (1.f / NE) + 1e-5f);
    out[(size_t)row * NE + t]       = d0 * rstd * g[t] + b[t];
    out[(size_t)row * NE + t + 256] = d1 * rstd * g[t + 256] + b[t + 256];
}

// ---------------- host-side dispatch ----------------------------------------

static void gemm(int ta, int act,
                 const float* A, int lda, size_t sA,
                 const float* Bm, int ldb, size_t sB,
                 float* C, int ldc, size_t sC,
                 const float* bias, int M, int N, int K, int batch)
{
    dim3 grid((N + BN - 1) / BN, (M + BM - 1) / BM, batch);
    dim3 blk(256);
    if (ta == 1)            gemm_k<1,0><<<grid,blk>>>(A,lda,sA,Bm,ldb,sB,C,ldc,sC,bias,M,N,K);
    else if (act == 1)      gemm_k<0,1><<<grid,blk>>>(A,lda,sA,Bm,ldb,sB,C,ldc,sC,bias,M,N,K);
    else if (act == 2)      gemm_k<0,2><<<grid,blk>>>(A,lda,sA,Bm,ldb,sB,C,ldc,sC,bias,M,N,K);
    else                    gemm_k<0,0><<<grid,blk>>>(A,lda,sA,Bm,ldb,sB,C,ldc,sC,bias,M,N,K);
}

extern "C" void kernel_launch(void* const* d_in, const int* in_sizes, int n_in,
                              void* d_out, int out_size)
{
    const float* x    = (const float*)d_in[0];
    const float* Wi   = (const float*)d_in[1];
    const float* bi   = (const float*)d_in[2];
    const float* pos  = (const float*)d_in[3];
    const float* Wq   = (const float*)d_in[4];
    const float* bq   = (const float*)d_in[5];
    const float* Wk   = (const float*)d_in[6];
    const float* bk   = (const float*)d_in[7];
    const float* Wv   = (const float*)d_in[8];
    const float* bv   = (const float*)d_in[9];
    const float* Wo   = (const float*)d_in[10];
    const float* bo   = (const float*)d_in[11];
    const float* R    = (const float*)d_in[12];
    const float* lng  = (const float*)d_in[13];
    const float* lnb  = (const float*)d_in[14];
    const float* W1   = (const float*)d_in[15];
    const float* b1   = (const float*)d_in[16];
    const float* W2   = (const float*)d_in[17];
    const float* b2   = (const float*)d_in[18];
    const float* Wr1  = (const float*)d_in[19];
    const float* br1  = (const float*)d_in[20];
    const float* Wr2  = (const float*)d_in[21];
    const float* br2  = (const float*)d_in[22];
    float* out = (float*)d_out;

    float *h,*q,*k,*v,*pq,*pk,*kv,*z,*ff,*part,*mx,*r1;
    cudaGetSymbolAddress((void**)&h,  g_h);
    cudaGetSymbolAddress((void**)&q,  g_q);
    cudaGetSymbolAddress((void**)&k,  g_k);
    cudaGetSymbolAddress((void**)&v,  g_v);
    cudaGetSymbolAddress((void**)&pq, g_pq);
    cudaGetSymbolAddress((void**)&pk, g_pk);
    cudaGetSymbolAddress((void**)&kv, g_kv);
    cudaGetSymbolAddress((void**)&z,  g_z);
    cudaGetSymbolAddress((void**)&ff, g_ff);
    cudaGetSymbolAddress((void**)&part, g_part);
    cudaGetSymbolAddress((void**)&mx, g_max);
    cudaGetSymbolAddress((void**)&r1, g_r1);

    const size_t nHE = (size_t)ROWS * NE;
    const size_t nHM = (size_t)ROWS * NM;
    int ew_grid = (int)((nHE + 255) / 256);
    int pm_grid = (int)((nHM + 255) / 256);

    // h = x @ Wi + bi + pos
    gemm(0,0, x, NDIN,0, Wi, NE,0, h, NE,0, bi, ROWS, NE, NDIN, 1);
    addpos_k<<<ew_grid,256>>>(h, pos);

    for (int i = 0; i < NL; i++) {
        const float* Wq_i = Wq + (size_t)i*NE*NE;   const float* bq_i = bq + (size_t)i*NE;
        const float* Wk_i = Wk + (size_t)i*NE*NE;   const float* bk_i = bk + (size_t)i*NE;
        const float* Wv_i = Wv + (size_t)i*NE*NE;   const float* bv_i = bv + (size_t)i*NE;
        const float* Wo_i = Wo + (size_t)i*NE*NE;   const float* bo_i = bo + (size_t)i*NE;
        const float* R_i  = R  + (size_t)i*NE*NM;
        const float* g_i  = lng + (size_t)i*NE;     const float* b_i  = lnb + (size_t)i*NE;
        const float* W1_i = W1 + (size_t)i*NE*HID;  const float* b1_i = b1 + (size_t)i*HID;
        const float* W2_i = W2 + (size_t)i*HID*NE;  const float* b2_i = b2 + (size_t)i*NE;

        // projections
        gemm(0,0, h, NE,0, Wq_i, NE,0, q, NE,0, bq_i, ROWS, NE, NE, 1);
        gemm(0,0, h, NE,0, Wk_i, NE,0, k, NE,0, bk_i, ROWS, NE, NE, 1);
        gemm(0,0, h, NE,0, Wv_i, NE,0, v, NE,0, bv_i, ROWS, NE, NE, 1);

        // pq = phi(q*scale, R)
        gemm(0,0, q, NE,0, R_i, NM,0, pq, NM,0, nullptr, ROWS, NM, NE, 1);
        phi_logits_k<<<ROWS,128>>>(pq, q, part);
        maxred_k<<<1,1024>>>(part, ROWS, mx);
        phiexp_k<<<pm_grid,256>>>(pq, mx, nHM);

        // pk = phi(k*scale, R)
        gemm(0,0, k, NE,0, R_i, NM,0, pk, NM,0, nullptr, ROWS, NM, NE, 1);
        phi_logits_k<<<ROWS,128>>>(pk, k, part);
        maxred_k<<<1,1024>>>(part, ROWS, mx);
        phiexp_k<<<pm_grid,256>>>(pk, mx, nHM);

        // kv[b] = pk[b]^T @ v[b]   (batched, transA)
        gemm(1,0, pk, NM, (size_t)NS*NM, v, NE, (size_t)NS*NE,
             kv, NE, (size_t)NM*NE, nullptr, NM, NE, NS, NB);

        // z[b] = sum_s pk[b,s,:]
        zero_k<<<(NB*NM+255)/256,256>>>(z, NB*NM);
        colsum_k<<<dim3(NB,32),128>>>(pk, z);

        // num -> q (batched)
        gemm(0,0, pq, NM, (size_t)NS*NM, kv, NE, (size_t)NM*NE,
             q, NE, (size_t)NS*NE, nullptr, NS, NE, NM, NB);

        // q /= (pq . z + 1e-6)
        divden_k<<<ROWS/8,256>>>(q, pq, z);

        // a -> k
        gemm(0,0, q, NE,0, Wo_i, NE,0, k, NE,0, bo_i, ROWS, NE, NE, 1);

        // y -> v (LayerNorm)
        ln_k<<<ROWS,256>>>(k, v, g_i, b_i);

        // ff1 = gelu(y @ W1 + b1)
        gemm(0,1, v, NE,0, W1_i, HID,0, ff, HID,0, b1_i, ROWS, HID, NE, 1);
        // ff2 -> q
        gemm(0,0, ff, HID,0, W2_i, NE,0, q, NE,0, b2_i, ROWS, NE, HID, 1);
        // h += ff2
        add_k<<<ew_grid,256>>>(h, q, nHE);
    }

    // head: pooled = h[:,0,:] (row stride S*E)
    gemm(0,2, h, NS*NE,0, Wr1, 256,0, r1, 256,0, br1, NB, 256, NE, 1);
    gemm(0,0, r1, 256,0, Wr2, 1,0, out, 1,0, br2, NB, 1, 256, 1);
}

// round 4
// speedup vs baseline: 1.2290x; 1.2289x over previous
#include <cuda_runtime.h>
#include <math.h>
#include <stdint.h>

#define NB 16
#define NS 4096
#define NDIN 64
#define NE 512
#define NM 128
#define NL 4
#define ROWS (NB*NS)        /* 65536 */
#define HID (4*NE)          /* 2048 */

// ---------------- scratch (device globals; no allocations allowed) ----------
__device__ float g_h [(size_t)ROWS*NE];
__device__ float g_q [(size_t)ROWS*NE];
__device__ float g_k [(size_t)ROWS*NE];
__device__ float g_v [(size_t)ROWS*NE];
__device__ float g_pq[(size_t)ROWS*NM];
__device__ float g_pk[(size_t)ROWS*NM];
__device__ float g_kv[(size_t)NB*NM*NE];
__device__ float g_z [NB*NM];
__device__ float g_ff[(size_t)ROWS*HID];
__device__ float g_part[ROWS];
__device__ float g_max[1];
__device__ float g_r1[16*256];

// ================= helpers =================
__device__ __forceinline__ uint32_t f2tf(float f) {
    uint32_t r;
    asm("cvt.rna.tf32.f32 %0, %1;" : "=r"(r) : "f"(f));
    return r;
}

__device__ __forceinline__ void mma_tf32(float c[4], const uint32_t a[4], const uint32_t b[2]) {
    asm volatile(
        "mma.sync.aligned.m16n8k8.row.col.f32.tf32.tf32.f32 "
        "{%0,%1,%2,%3}, {%4,%5,%6,%7}, {%8,%9}, {%0,%1,%2,%3};"
        : "+f"(c[0]), "+f"(c[1]), "+f"(c[2]), "+f"(c[3])
        : "r"(a[0]), "r"(a[1]), "r"(a[2]), "r"(a[3]), "r"(b[0]), "r"(b[1]));
}

// ================= mma.sync tf32 GEMM =================
// C[M,N] = op(A)[M,K] @ B[K,N] (+bias)(+gelu). fp32 in/out, tf32 mma, fp32 acc.
// Requires M%128==0, N%128==0, K%32==0. Batch via blockIdx.z.
// CTA tile 128x128, BK=32, double-buffered smem in fragment-order layout:
//   A: [mblk(8)][kstep(4)][lane(32)][4 regs]   (16KB / buffer)
//   B: [nblk(16)][kstep(4)][lane(32)][2 regs]  (16KB / buffer)
// Fragment loads are single LDS.128 / LDS.64, conflict-free.
// 8 warps: warp tile 64(m) x 32(n): wm=wid&1, wn=wid>>1.

#define TC_SMEM_BYTES 65536

template<int TRANS_A>
__device__ __forceinline__ void tc_ldA(const float* A, int lda, int m0, int kof,
                                       float4 r[4], int tid) {
#pragma unroll
    for (int i = 0; i < 4; i++) {
        int lin = i * 256 + tid;
        if (!TRANS_A) {
            int row = lin >> 3, f4 = lin & 7;
            r[i] = *(const float4*)(A + (size_t)(m0 + row) * lda + kof + (f4 << 2));
        } else {
            int kr = lin >> 5, f4m = lin & 31;
            r[i] = *(const float4*)(A + (size_t)(kof + kr) * lda + m0 + (f4m << 2));
        }
    }
}

__device__ __forceinline__ void tc_ldB(const float* B, int ldb, int n0, int kof,
                                       float4 r[4], int tid) {
#pragma unroll
    for (int i = 0; i < 4; i++) {
        int lin = i * 256 + tid;
        int kr = lin >> 5, f4n = lin & 31;
        r[i] = *(const float4*)(B + (size_t)(kof + kr) * ldb + n0 + (f4n << 2));
    }
}

template<int TRANS_A>
__device__ __forceinline__ void tc_stA(uint32_t* sA, const float4 r[4], int tid) {
#pragma unroll
    for (int i = 0; i < 4; i++) {
        int lin = i * 256 + tid;
        float v[4] = {r[i].x, r[i].y, r[i].z, r[i].w};
        if (!TRANS_A) {
            int row = lin >> 3, f4 = lin & 7;
            int mblk = row >> 4, g = row & 7, hi_m = (row >> 3) & 1;
            int ks = f4 >> 1, hi_k = f4 & 1;
            int base = (((mblk << 2) + ks) * 32 + (g << 2)) * 4 + hi_m + (hi_k << 1);
#pragma unroll
            for (int j = 0; j < 4; j++) sA[base + (j << 2)] = f2tf(v[j]);
        } else {
            int kr = lin >> 5, f4m = lin & 31;
            int ks = kr >> 3, kk = kr & 7;
            int t4 = kk & 3, hi_k = kk >> 2;
#pragma unroll
            for (int j = 0; j < 4; j++) {
                int m = (f4m << 2) + j;
                int mblk = m >> 4, g = m & 7, hi_m = (m >> 3) & 1;
                int idx = ((((mblk << 2) + ks) * 32) + (g << 2) + t4) * 4 + hi_m + (hi_k << 1);
                sA[idx] = f2tf(v[j]);
            }
        }
    }
}

__device__ __forceinline__ void tc_stB(uint32_t* sB, const float4 r[4], int tid) {
#pragma unroll
    for (int i = 0; i < 4; i++) {
        int lin = i * 256 + tid;
        int kr = lin >> 5, f4n = lin & 31;
        int ks = kr >> 3, kk = kr & 7;
        int t4 = kk & 3, rb = kk >> 2;
        float v[4] = {r[i].x, r[i].y, r[i].z, r[i].w};
#pragma unroll
        for (int j = 0; j < 4; j++) {
            int nn = (f4n << 2) + j;
            int nblk = nn >> 3, g = nn & 7;
            int idx = ((((nblk << 2) + ks) * 32) + (g << 2) + t4) * 2 + rb;
            sB[idx] = f2tf(v[j]);
        }
    }
}

template<int TRANS_A, int ACT>
__global__ __launch_bounds__(256, 1)
void tc_gemm_k(const float* __restrict__ A, int lda, size_t sAs,
               const float* __restrict__ B, int ldb, size_t sBs,
               float* __restrict__ C, int ldc, size_t sCs,
               const float* __restrict__ bias, int K)
{
    extern __shared__ uint32_t sm[];   // 16384 u32 = 64KB
    int tid = threadIdx.x;
    int wid = tid >> 5, lane = tid & 31;

    A += (size_t)blockIdx.z * sAs;
    B += (size_t)blockIdx.z * sBs;
    C += (size_t)blockIdx.z * sCs;
    int m0 = blockIdx.y << 7;
    int n0 = blockIdx.x << 7;

    int wm = wid & 1, wn = wid >> 1;
    int mblk0 = wm << 2;        // 4 m-frags of 16 rows
    int nblk0 = wn << 2;        // 4 n-frags of 8 cols

    float c[4][4][4];
#pragma unroll
    for (int a = 0; a < 4; a++)
#pragma unroll
        for (int b = 0; b < 4; b++)
#pragma unroll
            for (int r = 0; r < 4; r++) c[a][b][r] = 0.f;

    int nk = K >> 5;
    float4 rA[4], rB[4];

    // prefill buffer 0
    tc_ldA<TRANS_A>(A, lda, m0, 0, rA, tid);
    tc_ldB(B, ldb, n0, 0, rB, tid);
    tc_stA<TRANS_A>(sm, rA, tid);
    tc_stB(sm + 8192, rB, tid);
    __syncthreads();

    for (int kt = 0; kt < nk; kt++) {
        int buf = kt & 1;
        bool next = (kt + 1) < nk;
        if (next) {
            tc_ldA<TRANS_A>(A, lda, m0, (kt + 1) << 5, rA, tid);
            tc_ldB(B, ldb, n0, (kt + 1) << 5, rB, tid);
        }
        const uint32_t* sA = sm + buf * 4096;
        const uint32_t* sB = sm + 8192 + buf * 4096;
#pragma unroll
        for (int ks = 0; ks < 4; ks++) {
            uint32_t af[4][4];
            uint32_t bf[4][2];
#pragma unroll
            for (int mi = 0; mi < 4; mi++) {
                uint4 t = *(const uint4*)&sA[((((mblk0 + mi) << 2) + ks) * 32 + lane) * 4];
                af[mi][0] = t.x; af[mi][1] = t.y; af[mi][2] = t.z; af[mi][3] = t.w;
            }
#pragma unroll
            for (int ni = 0; ni < 4; ni++) {
                uint2 t = *(const uint2*)&sB[((((nblk0 + ni) << 2) + ks) * 32 + lane) * 2];
                bf[ni][0] = t.x; bf[ni][1] = t.y;
            }
#pragma unroll
            for (int mi = 0; mi < 4; mi++)
#pragma unroll
                for (int ni = 0; ni < 4; ni++)
                    mma_tf32(c[mi][ni], af[mi], bf[ni]);
        }
        if (next) {
            tc_stA<TRANS_A>(sm + (buf ^ 1) * 4096, rA, tid);
            tc_stB(sm + 8192 + (buf ^ 1) * 4096, rB, tid);
            __syncthreads();
        }
    }

    // ---- epilogue ----
    int g = lane >> 2, t4 = lane & 3;
    const float GK = 0.7071067811865476f;
#pragma unroll
    for (int mi = 0; mi < 4; mi++) {
        int mrow = m0 + (wm << 6) + (mi << 4) + g;
#pragma unroll
        for (int ni = 0; ni < 4; ni++) {
            int nn = n0 + (wn << 5) + (ni << 3) + (t4 << 1);
            float v0 = c[mi][ni][0], v1 = c[mi][ni][1];
            float v2 = c[mi][ni][2], v3 = c[mi][ni][3];
            if (bias) {
                float b0 = __ldg(bias + nn), b1 = __ldg(bias + nn + 1);
                v0 += b0; v1 += b1; v2 += b0; v3 += b1;
            }
            if (ACT == 1) {
                v0 = 0.5f * v0 * (1.f + erff(v0 * GK));
                v1 = 0.5f * v1 * (1.f + erff(v1 * GK));
                v2 = 0.5f * v2 * (1.f + erff(v2 * GK));
                v3 = 0.5f * v3 * (1.f + erff(v3 * GK));
            }
            float2 p0 = make_float2(v0, v1);
            float2 p1 = make_float2(v2, v3);
            *(float2*)(C + (size_t)mrow * ldc + nn) = p0;
            *(float2*)(C + (size_t)(mrow + 8) * ldc + nn) = p1;
        }
    }
}

// ================= fp32 fallback SGEMM (small/ragged shapes) =================
#define BM 128
#define BN 128
#define BK 8

template<int TRANS_A, int ACT>
__global__ __launch_bounds__(256)
void gemm_k(const float* __restrict__ A, int lda, size_t sA,
            const float* __restrict__ Bm, int ldb, size_t sB,
            float* __restrict__ C, int ldc, size_t sC,
            const float* __restrict__ bias,
            int M, int N, int K)
{
    int bz = blockIdx.z;
    A  += (size_t)bz * sA;
    Bm += (size_t)bz * sB;
    C  += (size_t)bz * sC;
    int m0 = blockIdx.y * BM;
    int n0 = blockIdx.x * BN;

    __shared__ float As[BK][BM];
    __shared__ float Bs[BK][BN];

    int tid = threadIdx.x;
    int tx = tid & 15, ty = tid >> 4;

    float acc[8][8];
#pragma unroll
    for (int i = 0; i < 8; i++)
#pragma unroll
        for (int j = 0; j < 8; j++) acc[i][j] = 0.f;

    float ar[8], br[8];

    for (int k0 = 0; k0 < K; k0 += BK) {
        if (TRANS_A) {
            int k = tid >> 5;
            int m = (tid & 31) * 4;
            const float* src = A + (size_t)(k0 + k) * lda + m0 + m;
#pragma unroll
            for (int i = 0; i < 4; i++) {
                float vv = 0.f;
                if (m0 + m + i < M) vv = src[i];
                As[k][m + i] = vv;
            }
        } else {
            int m  = tid >> 1;
            int kk = (tid & 1) * 4;
            const float* src = A + (size_t)(m0 + m) * lda + k0 + kk;
            bool mok = (m0 + m) < M;
#pragma unroll
            for (int i = 0; i < 4; i++)
                As[kk + i][m] = mok ? src[i] : 0.f;
        }
        {
            int k = tid >> 5;
            int n = (tid & 31) * 4;
            const float* src = Bm + (size_t)(k0 + k) * ldb + n0 + n;
#pragma unroll
            for (int i = 0; i < 4; i++) {
                float vv = 0.f;
                if (n0 + n + i < N) vv = src[i];
                Bs[k][n + i] = vv;
            }
        }
        __syncthreads();
#pragma unroll
        for (int k = 0; k < BK; k++) {
            *(float4*)&ar[0] = *(float4*)&As[k][ty * 4];
            *(float4*)&ar[4] = *(float4*)&As[k][64 + ty * 4];
            *(float4*)&br[0] = *(float4*)&Bs[k][tx * 4];
            *(float4*)&br[4] = *(float4*)&Bs[k][64 + tx * 4];
#pragma unroll
            for (int i = 0; i < 8; i++)
#pragma unroll
                for (int j = 0; j < 8; j++)
                    acc[i][j] = fmaf(ar[i], br[j], acc[i][j]);
        }
        __syncthreads();
    }

#pragma unroll
    for (int i = 0; i < 8; i++) {
        int m = m0 + ((i < 4) ? (ty * 4 + i) : (64 + ty * 4 + i - 4));
        if (m >= M) continue;
#pragma unroll
        for (int j = 0; j < 8; j++) {
            int n = n0 + ((j < 4) ? (tx * 4 + j) : (64 + tx * 4 + j - 4));
            if (n >= N) continue;
            float vv = acc[i][j];
            if (bias) vv += bias[n];
            if (ACT == 1) vv = 0.5f * vv * (1.f + erff(vv * 0.7071067811865476f));
            else if (ACT == 2) vv = fmaxf(vv, 0.f);
            C[(size_t)m * ldc + n] = vv;
        }
    }
}

// ---------------- elementwise / reduction kernels ---------------------------

__global__ void addpos_k(float* __restrict__ h, const float* __restrict__ pos) {
    size_t i = (size_t)blockIdx.x * 256 + threadIdx.x;
    if (i < (size_t)ROWS * NE) h[i] += pos[i % ((size_t)NS * NE)];
}

__global__ void add_k(float* __restrict__ a, const float* __restrict__ b, size_t n) {
    size_t i = (size_t)blockIdx.x * 256 + threadIdx.x;
    if (i < n) a[i] += b[i];
}

__global__ void zero_k(float* p, int n) {
    int i = blockIdx.x * 256 + threadIdx.x;
    if (i < n) p[i] = 0.f;
}

__global__ void phi_logits_k(float* __restrict__ G, const float* __restrict__ U,
                             float* __restrict__ part) {
    int row = blockIdx.x;
    int t = threadIdx.x;             // 128
    __shared__ float sh[128];
    const float* u = U + (size_t)row * NE;
    float s = 0.f;
#pragma unroll
    for (int j = 0; j < NE; j += 128) { float x = u[t + j]; s = fmaf(x, x, s); }
    sh[t] = s; __syncthreads();
    for (int o = 64; o > 0; o >>= 1) { if (t < o) sh[t] += sh[t + o]; __syncthreads(); }
    float norm2 = sh[0];
    const float scale  = 0.21022410381342865f;  // 512^-0.25
    const float scale2 = 0.04419417382415922f;  // 512^-0.5
    float* g = G + (size_t)row * NM;
    float l = fmaf(scale, g[t], -0.5f * scale2 * norm2);
    g[t] = l;
    __syncthreads();
    sh[t] = l; __syncthreads();
    for (int o = 64; o > 0; o >>= 1) { if (t < o) sh[t] = fmaxf(sh[t], sh[t + o]); __syncthreads(); }
    if (t == 0) part[row] = sh[0];
}

__global__ void maxred_k(const float* __restrict__ part, int n, float* __restrict__ out) {
    __shared__ float sh[1024];
    int t = threadIdx.x;
    float m = -INFINITY;
    for (int i = t; i < n; i += 1024) m = fmaxf(m, part[i]);
    sh[t] = m; __syncthreads();
    for (int o = 512; o > 0; o >>= 1) { if (t < o) sh[t] = fmaxf(sh[t], sh[t + o]); __syncthreads(); }
    if (t == 0) out[0] = sh[0];
}

__global__ void phiexp_k(float* __restrict__ G, const float* __restrict__ mx, size_t n) {
    size_t i = (size_t)blockIdx.x * 256 + threadIdx.x;
    if (i < n) G[i] = expf(G[i] - mx[0]) * 0.08838834764831845f; // 1/sqrt(128)
}

__global__ void colsum_k(const float* __restrict__ pk, float* __restrict__ z) {
    int b = blockIdx.x, chunk = blockIdx.y, m = threadIdx.x;
    const float* p = pk + (size_t)b * NS * NM + (size_t)chunk * 128 * NM + m;
    float s = 0.f;
    for (int i = 0; i < 128; i++) s += p[(size_t)i * NM];
    atomicAdd(&z[b * NM + m], s);
}

__global__ void divden_k(float* __restrict__ num, const float* __restrict__ pq,
                         const float* __restrict__ z) {
    int warp = threadIdx.x >> 5, lane = threadIdx.x & 31;
    int row = blockIdx.x * 8 + warp;
    int b = row / NS;
    const float* p  = pq + (size_t)row * NM;
    const float* zz = z + b * NM;
    float s = 0.f;
#pragma unroll
    for (int j = 0; j < 4; j++) s = fmaf(p[lane + 32 * j], zz[lane + 32 * j], s);
#pragma unroll
    for (int o = 16; o > 0; o >>= 1) s += __shfl_xor_sync(0xffffffffu, s, o);
    float inv = 1.f / (s + 1e-6f);
    float* nm = num + (size_t)row * NE;
#pragma unroll
    for (int j = 0; j < NE / 32; j++) nm[lane + 32 * j] *= inv;
}

__global__ void ln_k(const float* __restrict__ in, float* __restrict__ out,
                     const float* __restrict__ g, const float* __restrict__ b) {
    int row = blockIdx.x, t = threadIdx.x;
    __shared__ float sh[256];
    const float* a = in + (size_t)row * NE;
    float x0 = a[t], x1 = a[t + 256];
    sh[t] = x0 + x1; __syncthreads();
    for (int o = 128; o > 0; o >>= 1) { if (t < o) sh[t] += sh[t + o]; __syncthreads(); }
    float mu = sh[0] * (1.f / NE);
    __syncthreads();
    float d0 = x0 - mu, d1 = x1 - mu;
    sh[t] = d0 * d0 + d1 * d1; __syncthreads();
    for (int o = 128; o > 0; o >>= 1) { if (t < o) sh[t] += sh[t + o]; __syncthreads(); }
    float rstd = rsqrtf(sh[0] * (1.f / NE) + 1e-5f);
    out[(size_t)row * NE + t]       = d0 * rstd * g[t] + b[t];
    out[(size_t)row * NE + t + 256] = d1 * rstd * g[t + 256] + b[t + 256];
}

// ---------------- host-side dispatch ----------------------------------------

static void gemm(int ta, int act,
                 const float* A, int lda, size_t sA,
                 const float* Bm, int ldb, size_t sB,
                 float* C, int ldc, size_t sC,
                 const float* bias, int M, int N, int K, int batch)
{
    dim3 grid((N + BN - 1) / BN, (M + BM - 1) / BM, batch);
    dim3 blk(256);
    if (ta == 1)            gemm_k<1,0><<<grid,blk>>>(A,lda,sA,Bm,ldb,sB,C,ldc,sC,bias,M,N,K);
    else if (act == 1)      gemm_k<0,1><<<grid,blk>>>(A,lda,sA,Bm,ldb,sB,C,ldc,sC,bias,M,N,K);
    else if (act == 2)      gemm_k<0,2><<<grid,blk>>>(A,lda,sA,Bm,ldb,sB,C,ldc,sC,bias,M,N,K);
    else                    gemm_k<0,0><<<grid,blk>>>(A,lda,sA,Bm,ldb,sB,C,ldc,sC,bias,M,N,K);
}

template<int TRANS_A, int ACT>
static void tc_gemm(const float* A, int lda, size_t sA,
                    const float* Bm, int ldb, size_t sB,
                    float* C, int ldc, size_t sC,
                    const float* bias, int M, int N, int K, int batch)
{
    cudaFuncSetAttribute(tc_gemm_k<TRANS_A, ACT>,
                         cudaFuncAttributeMaxDynamicSharedMemorySize, TC_SMEM_BYTES);
    dim3 grid(N >> 7, M >> 7, batch);
    tc_gemm_k<TRANS_A, ACT><<<grid, 256, TC_SMEM_BYTES>>>(A, lda, sA, Bm, ldb, sB, C, ldc, sC, bias, K);
}

extern "C" void kernel_launch(void* const* d_in, const int* in_sizes, int n_in,
                              void* d_out, int out_size)
{
    const float* x    = (const float*)d_in[0];
    const float* Wi   = (const float*)d_in[1];
    const float* bi   = (const float*)d_in[2];
    const float* pos  = (const float*)d_in[3];
    const float* Wq   = (const float*)d_in[4];
    const float* bq   = (const float*)d_in[5];
    const float* Wk   = (const float*)d_in[6];
    const float* bk   = (const float*)d_in[7];
    const float* Wv   = (const float*)d_in[8];
    const float* bv   = (const float*)d_in[9];
    const float* Wo   = (const float*)d_in[10];
    const float* bo   = (const float*)d_in[11];
    const float* R    = (const float*)d_in[12];
    const float* lng  = (const float*)d_in[13];
    const float* lnb  = (const float*)d_in[14];
    const float* W1   = (const float*)d_in[15];
    const float* b1   = (const float*)d_in[16];
    const float* W2   = (const float*)d_in[17];
    const float* b2   = (const float*)d_in[18];
    const float* Wr1  = (const float*)d_in[19];
    const float* br1  = (const float*)d_in[20];
    const float* Wr2  = (const float*)d_in[21];
    const float* br2  = (const float*)d_in[22];
    float* out = (float*)d_out;

    float *h,*q,*k,*v,*pq,*pk,*kv,*z,*ff,*part,*mx,*r1;
    cudaGetSymbolAddress((void**)&h,  g_h);
    cudaGetSymbolAddress((void**)&q,  g_q);
    cudaGetSymbolAddress((void**)&k,  g_k);
    cudaGetSymbolAddress((void**)&v,  g_v);
    cudaGetSymbolAddress((void**)&pq, g_pq);
    cudaGetSymbolAddress((void**)&pk, g_pk);
    cudaGetSymbolAddress((void**)&kv, g_kv);
    cudaGetSymbolAddress((void**)&z,  g_z);
    cudaGetSymbolAddress((void**)&ff, g_ff);
    cudaGetSymbolAddress((void**)&part, g_part);
    cudaGetSymbolAddress((void**)&mx, g_max);
    cudaGetSymbolAddress((void**)&r1, g_r1);

    const size_t nHE = (size_t)ROWS * NE;
    const size_t nHM = (size_t)ROWS * NM;
    int ew_grid = (int)((nHE + 255) / 256);
    int pm_grid = (int)((nHM + 255) / 256);

    // h = x @ Wi + bi + pos   (K=64, tf32 tensor path)
    tc_gemm<0,0>(x, NDIN,0, Wi, NE,0, h, NE,0, bi, ROWS, NE, NDIN, 1);
    addpos_k<<<ew_grid,256>>>(h, pos);

    for (int i = 0; i < NL; i++) {
        const float* Wq_i = Wq + (size_t)i*NE*NE;   const float* bq_i = bq + (size_t)i*NE;
        const float* Wk_i = Wk + (size_t)i*NE*NE;   const float* bk_i = bk + (size_t)i*NE;
        const float* Wv_i = Wv + (size_t)i*NE*NE;   const float* bv_i = bv + (size_t)i*NE;
        const float* Wo_i = Wo + (size_t)i*NE*NE;   const float* bo_i = bo + (size_t)i*NE;
        const float* R_i  = R  + (size_t)i*NE*NM;
        const float* g_i  = lng + (size_t)i*NE;     const float* b_i  = lnb + (size_t)i*NE;
        const float* W1_i = W1 + (size_t)i*NE*HID;  const float* b1_i = b1 + (size_t)i*HID;
        const float* W2_i = W2 + (size_t)i*HID*NE;  const float* b2_i = b2 + (size_t)i*NE;

        // projections (tensor core tf32)
        tc_gemm<0,0>(h, NE,0, Wq_i, NE,0, q, NE,0, bq_i, ROWS, NE, NE, 1);
        tc_gemm<0,0>(h, NE,0, Wk_i, NE,0, k, NE,0, bk_i, ROWS, NE, NE, 1);
        tc_gemm<0,0>(h, NE,0, Wv_i, NE,0, v, NE,0, bv_i, ROWS, NE, NE, 1);

        // pq = phi(q*scale, R)
        tc_gemm<0,0>(q, NE,0, R_i, NM,0, pq, NM,0, nullptr, ROWS, NM, NE, 1);
        phi_logits_k<<<ROWS,128>>>(pq, q, part);
        maxred_k<<<1,1024>>>(part, ROWS, mx);
        phiexp_k<<<pm_grid,256>>>(pq, mx, nHM);

        // pk = phi(k*scale, R)
        tc_gemm<0,0>(k, NE,0, R_i, NM,0, pk, NM,0, nullptr, ROWS, NM, NE, 1);
        phi_logits_k<<<ROWS,128>>>(pk, k, part);
        maxred_k<<<1,1024>>>(part, ROWS, mx);
        phiexp_k<<<pm_grid,256>>>(pk, mx, nHM);

        // kv[b] = pk[b]^T @ v[b]   (batched, transA, tensor core, K=4096)
        tc_gemm<1,0>(pk, NM, (size_t)NS*NM, v, NE, (size_t)NS*NE,
                     kv, NE, (size_t)NM*NE, nullptr, NM, NE, NS, NB);

        // z[b] = sum_s pk[b,s,:]
        zero_k<<<(NB*NM+255)/256,256>>>(z, NB*NM);
        colsum_k<<<dim3(NB,32),128>>>(pk, z);

        // num -> q (batched, tensor core)
        tc_gemm<0,0>(pq, NM, (size_t)NS*NM, kv, NE, (size_t)NM*NE,
                     q, NE, (size_t)NS*NE, nullptr, NS, NE, NM, NB);

        // q /= (pq . z + 1e-6)
        divden_k<<<ROWS/8,256>>>(q, pq, z);

        // a -> k
        tc_gemm<0,0>(q, NE,0, Wo_i, NE,0, k, NE,0, bo_i, ROWS, NE, NE, 1);

        // y -> v (LayerNorm)
        ln_k<<<ROWS,256>>>(k, v, g_i, b_i);

        // ff1 = gelu(y @ W1 + b1)
        tc_gemm<0,1>(v, NE,0, W1_i, HID,0, ff, HID,0, b1_i, ROWS, HID, NE, 1);
        // ff2 -> q
        tc_gemm<0,0>(ff, HID,0, W2_i, NE,0, q, NE,0, b2_i, ROWS, NE, HID, 1);
        // h += ff2
        add_k<<<ew_grid,256>>>(h, q, nHE);
    }

    // head: pooled = h[:,0,:] (row stride S*E) — tiny, fp32 path
    gemm(0,2, h, NS*NE,0, Wr1, 256,0, r1, 256,0, br1, NB, 256, NE, 1);
    gemm(0,0, r1, 256,0, Wr2, 1,0, out, 1,0, br2, NB, 1, 256, 1);
}

// round 5
// speedup vs baseline: 3.8374x; 3.1223x over previous
#include <cuda_runtime.h>
#include <math.h>
#include <stdint.h>

#define NB 16
#define NS 4096
#define NDIN 64
#define NE 512
#define NM 128
#define NL 4
#define ROWS (NB*NS)        /* 65536 */
#define HID (4*NE)          /* 2048 */

// ---------------- scratch (device globals; no allocations allowed) ----------
__device__ float g_h [(size_t)ROWS*NE];
__device__ float g_q [(size_t)ROWS*NE];
__device__ float g_k [(size_t)ROWS*NE];
__device__ float g_v [(size_t)ROWS*NE];
__device__ float g_pq[(size_t)ROWS*NM];
__device__ float g_pk[(size_t)ROWS*NM];
__device__ float g_kv[(size_t)NB*NM*NE];
__device__ float g_z [NB*NM];
__device__ float g_ff[(size_t)ROWS*HID];
__device__ float g_part[ROWS];
__device__ float g_max[1];
__device__ float g_r1[16*256];

// ================= helpers =================
__device__ __forceinline__ uint32_t smem_u32(const void* p) {
    uint32_t r;
    asm("{ .reg .u64 t; cvta.to.shared.u64 t, %1; cvt.u32.u64 %0, t; }" : "=r"(r) : "l"(p));
    return r;
}
__device__ __forceinline__ uint32_t f2tf(float f) {
    uint32_t r;
    asm("cvt.rna.tf32.f32 %0, %1;" : "=r"(r) : "f"(f));
    return r;
}
__device__ __forceinline__ void cp_async16(uint32_t saddr, const void* g) {
    asm volatile("cp.async.cg.shared.global [%0], [%1], 16;" :: "r"(saddr), "l"(g));
}
__device__ __forceinline__ void mma_tf32(float c[4], const uint32_t a[4], const uint32_t b[2]) {
    asm volatile(
        "mma.sync.aligned.m16n8k8.row.col.f32.tf32.tf32.f32 "
        "{%0,%1,%2,%3}, {%4,%5,%6,%7}, {%8,%9}, {%0,%1,%2,%3};"
        : "+f"(c[0]), "+f"(c[1]), "+f"(c[2]), "+f"(c[3])
        : "r"(a[0]), "r"(a[1]), "r"(a[2]), "r"(a[3]), "r"(b[0]), "r"(b[1]));
}

// ================= cp.async-pipelined mma.sync tf32 GEMM =================
// C[M,N] = op(A)[M,K] @ B[K,N] (+bias)(+gelu). fp32 in/out, tf32 mma (rna cvt
// at fragment load), fp32 acc. Requires M%128==0, N%128==0, K%32==0.
// CTA tile 128x128, BK=32, 3-stage cp.async pipeline.
// smem layouts (fp32 words):
//   A (non-trans): [128 m][32 k], row stride 36  (36 % 32 == 4 -> frag LDS conflict-free)
//   A (trans) & B: [32 k][128 mn], row stride 136 (136 % 32 == 8 -> conflict-free)
// 8 warps: warp tile 64(m) x 32(n): wm=wid&1, wn=wid>>1.

#define TC_STAGES 3
#define A_STRIDE 36
#define B_STRIDE 136
#define A_WORDS (128*A_STRIDE)                  /* 4608 */
#define B_WORDS (32*B_STRIDE)                   /* 4352 */
#define STAGE_WORDS (A_WORDS + B_WORDS)         /* 8960 */
#define TC_SMEM_BYTES (TC_STAGES*STAGE_WORDS*4) /* 107520 */

template<int TRANS_A>
__device__ __forceinline__ void tc_fill(const float* __restrict__ A, int lda,
                                        const float* __restrict__ B, int ldb,
                                        int m0, int n0, int kof,
                                        uint32_t sa, uint32_t sb, int tid) {
    if (!TRANS_A) {
#pragma unroll
        for (int i = 0; i < 4; i++) {
            int lin = (i << 8) + tid;
            int row = lin >> 3, c = lin & 7;          // 128 rows x 8 chunks
            cp_async16(sa + (uint32_t)(row * A_STRIDE + (c << 2)) * 4,
                       A + (size_t)(m0 + row) * lda + kof + (c << 2));
        }
    } else {
#pragma unroll
        for (int i = 0; i < 4; i++) {
            int lin = (i << 8) + tid;
            int row = lin >> 5, c = lin & 31;         // 32 k-rows x 32 chunks
            cp_async16(sa + (uint32_t)(row * B_STRIDE + (c << 2)) * 4,
                       A + (size_t)(kof + row) * lda + m0 + (c << 2));
        }
    }
#pragma unroll
    for (int i = 0; i < 4; i++) {
        int lin = (i << 8) + tid;
        int row = lin >> 5, c = lin & 31;
        cp_async16(sb + (uint32_t)(row * B_STRIDE + (c << 2)) * 4,
                   B + (size_t)(kof + row) * ldb + n0 + (c << 2));
    }
}

template<int TRANS_A, int ACT>
__global__ __launch_bounds__(256, 2)
void tc_gemm_k(const float* __restrict__ A, int lda, size_t sAs,
               const float* __restrict__ B, int ldb, size_t sBs,
               float* __restrict__ C, int ldc, size_t sCs,
               const float* __restrict__ bias, int K)
{
    extern __shared__ float sm[];
    uint32_t smb = smem_u32(sm);
    int tid = threadIdx.x;
    int wid = tid >> 5, lane = tid & 31;
    int g = lane >> 2, t4 = lane & 3;

    A += (size_t)blockIdx.z * sAs;
    B += (size_t)blockIdx.z * sBs;
    C += (size_t)blockIdx.z * sCs;
    int m0 = blockIdx.y << 7;
    int n0 = blockIdx.x << 7;

    int wm = wid & 1, wn = wid >> 1;

    float c[4][4][4];
#pragma unroll
    for (int a = 0; a < 4; a++)
#pragma unroll
        for (int b = 0; b < 4; b++)
#pragma unroll
            for (int r = 0; r < 4; r++) c[a][b][r] = 0.f;

    int nk = K >> 5;

    // prologue: stages 0..S-2
#pragma unroll
    for (int s = 0; s < TC_STAGES - 1; s++) {
        if (s < nk) {
            uint32_t sa = smb + (uint32_t)(s * STAGE_WORDS) * 4;
            tc_fill<TRANS_A>(A, lda, B, ldb, m0, n0, s << 5, sa, sa + A_WORDS * 4, tid);
        }
        asm volatile("cp.async.commit_group;");
    }

    for (int kt = 0; kt < nk; kt++) {
        asm volatile("cp.async.wait_group %0;" :: "n"(TC_STAGES - 2));
        __syncthreads();

        int nxt = kt + TC_STAGES - 1;
        if (nxt < nk) {
            int st = nxt % TC_STAGES;
            uint32_t sa = smb + (uint32_t)(st * STAGE_WORDS) * 4;
            tc_fill<TRANS_A>(A, lda, B, ldb, m0, n0, nxt << 5, sa, sa + A_WORDS * 4, tid);
        }
        asm volatile("cp.async.commit_group;");

        const float* sa = sm + (kt % TC_STAGES) * STAGE_WORDS;
        const float* sb = sa + A_WORDS;
#pragma unroll
        for (int ks = 0; ks < 4; ks++) {
            uint32_t af[4][4];
            uint32_t bf[4][2];
#pragma unroll
            for (int mi = 0; mi < 4; mi++) {
                if (!TRANS_A) {
                    int base = ((wm << 6) + (mi << 4) + g) * A_STRIDE + (ks << 3) + t4;
                    af[mi][0] = f2tf(sa[base]);
                    af[mi][1] = f2tf(sa[base + 8 * A_STRIDE]);
                    af[mi][2] = f2tf(sa[base + 4]);
                    af[mi][3] = f2tf(sa[base + 8 * A_STRIDE + 4]);
                } else {
                    int base = ((ks << 3) + t4) * B_STRIDE + (wm << 6) + (mi << 4) + g;
                    af[mi][0] = f2tf(sa[base]);
                    af[mi][1] = f2tf(sa[base + 8]);
                    af[mi][2] = f2tf(sa[base + 4 * B_STRIDE]);
                    af[mi][3] = f2tf(sa[base + 4 * B_STRIDE + 8]);
                }
            }
#pragma unroll
            for (int ni = 0; ni < 4; ni++) {
                int base = ((ks << 3) + t4) * B_STRIDE + (wn << 5) + (ni << 3) + g;
                bf[ni][0] = f2tf(sb[base]);
                bf[ni][1] = f2tf(sb[base + 4 * B_STRIDE]);
            }
#pragma unroll
            for (int mi = 0; mi < 4; mi++)
#pragma unroll
                for (int ni = 0; ni < 4; ni++)
                    mma_tf32(c[mi][ni], af[mi], bf[ni]);
        }
    }

    // ---- epilogue ----
    const float GK = 0.7071067811865476f;
#pragma unroll
    for (int mi = 0; mi < 4; mi++) {
        int mrow = m0 + (wm << 6) + (mi << 4) + g;
#pragma unroll
        for (int ni = 0; ni < 4; ni++) {
            int nn = n0 + (wn << 5) + (ni << 3) + (t4 << 1);
            float v0 = c[mi][ni][0], v1 = c[mi][ni][1];
            float v2 = c[mi][ni][2], v3 = c[mi][ni][3];
            if (bias) {
                float b0 = __ldg(bias + nn), b1 = __ldg(bias + nn + 1);
                v0 += b0; v1 += b1; v2 += b0; v3 += b1;
            }
            if (ACT == 1) {
                v0 = 0.5f * v0 * (1.f + erff(v0 * GK));
                v1 = 0.5f * v1 * (1.f + erff(v1 * GK));
                v2 = 0.5f * v2 * (1.f + erff(v2 * GK));
                v3 = 0.5f * v3 * (1.f + erff(v3 * GK));
            }
            *(float2*)(C + (size_t)mrow * ldc + nn) = make_float2(v0, v1);
            *(float2*)(C + (size_t)(mrow + 8) * ldc + nn) = make_float2(v2, v3);
        }
    }
}

// ================= fp32 fallback SGEMM (small/ragged shapes) =================
#define BM 128
#define BN 128
#define BK 8

template<int TRANS_A, int ACT>
__global__ __launch_bounds__(256)
void gemm_k(const float* __restrict__ A, int lda, size_t sA,
            const float* __restrict__ Bm, int ldb, size_t sB,
            float* __restrict__ C, int ldc, size_t sC,
            const float* __restrict__ bias,
            int M, int N, int K)
{
    int bz = blockIdx.z;
    A  += (size_t)bz * sA;
    Bm += (size_t)bz * sB;
    C  += (size_t)bz * sC;
    int m0 = blockIdx.y * BM;
    int n0 = blockIdx.x * BN;

    __shared__ float As[BK][BM];
    __shared__ float Bs[BK][BN];

    int tid = threadIdx.x;
    int tx = tid & 15, ty = tid >> 4;

    float acc[8][8];
#pragma unroll
    for (int i = 0; i < 8; i++)
#pragma unroll
        for (int j = 0; j < 8; j++) acc[i][j] = 0.f;

    float ar[8], br[8];

    for (int k0 = 0; k0 < K; k0 += BK) {
        if (TRANS_A) {
            int k = tid >> 5;
            int m = (tid & 31) * 4;
            const float* src = A + (size_t)(k0 + k) * lda + m0 + m;
#pragma unroll
            for (int i = 0; i < 4; i++) {
                float vv = 0.f;
                if (m0 + m + i < M) vv = src[i];
                As[k][m + i] = vv;
            }
        } else {
            int m  = tid >> 1;
            int kk = (tid & 1) * 4;
            const float* src = A + (size_t)(m0 + m) * lda + k0 + kk;
            bool mok = (m0 + m) < M;
#pragma unroll
            for (int i = 0; i < 4; i++)
                As[kk + i][m] = mok ? src[i] : 0.f;
        }
        {
            int k = tid >> 5;
            int n = (tid & 31) * 4;
            const float* src = Bm + (size_t)(k0 + k) * ldb + n0 + n;
#pragma unroll
            for (int i = 0; i < 4; i++) {
                float vv = 0.f;
                if (n0 + n + i < N) vv = src[i];
                Bs[k][n + i] = vv;
            }
        }
        __syncthreads();
#pragma unroll
        for (int k = 0; k < BK; k++) {
            *(float4*)&ar[0] = *(float4*)&As[k][ty * 4];
            *(float4*)&ar[4] = *(float4*)&As[k][64 + ty * 4];
            *(float4*)&br[0] = *(float4*)&Bs[k][tx * 4];
            *(float4*)&br[4] = *(float4*)&Bs[k][64 + tx * 4];
#pragma unroll
            for (int i = 0; i < 8; i++)
#pragma unroll
                for (int j = 0; j < 8; j++)
                    acc[i][j] = fmaf(ar[i], br[j], acc[i][j]);
        }
        __syncthreads();
    }

#pragma unroll
    for (int i = 0; i < 8; i++) {
        int m = m0 + ((i < 4) ? (ty * 4 + i) : (64 + ty * 4 + i - 4));
        if (m >= M) continue;
#pragma unroll
        for (int j = 0; j < 8; j++) {
            int n = n0 + ((j < 4) ? (tx * 4 + j) : (64 + tx * 4 + j - 4));
            if (n >= N) continue;
            float vv = acc[i][j];
            if (bias) vv += bias[n];
            if (ACT == 1) vv = 0.5f * vv * (1.f + erff(vv * 0.7071067811865476f));
            else if (ACT == 2) vv = fmaxf(vv, 0.f);
            C[(size_t)m * ldc + n] = vv;
        }
    }
}

// ---------------- elementwise / reduction kernels ---------------------------

__global__ void addpos_k(float* __restrict__ h, const float* __restrict__ pos) {
    size_t i = (size_t)blockIdx.x * 256 + threadIdx.x;
    if (i < (size_t)ROWS * NE) h[i] += pos[i % ((size_t)NS * NE)];
}

__global__ void add_k(float* __restrict__ a, const float* __restrict__ b, size_t n) {
    size_t i = (size_t)blockIdx.x * 256 + threadIdx.x;
    if (i < n) a[i] += b[i];
}

__global__ void zero_k(float* p, int n) {
    int i = blockIdx.x * 256 + threadIdx.x;
    if (i < n) p[i] = 0.f;
}

__global__ void phi_logits_k(float* __restrict__ G, const float* __restrict__ U,
                             float* __restrict__ part) {
    int row = blockIdx.x;
    int t = threadIdx.x;             // 128
    __shared__ float sh[128];
    const float* u = U + (size_t)row * NE;
    float s = 0.f;
#pragma unroll
    for (int j = 0; j < NE; j += 128) { float x = u[t + j]; s = fmaf(x, x, s); }
    sh[t] = s; __syncthreads();
    for (int o = 64; o > 0; o >>= 1) { if (t < o) sh[t] += sh[t + o]; __syncthreads(); }
    float norm2 = sh[0];
    const float scale  = 0.21022410381342865f;  // 512^-0.25
    const float scale2 = 0.04419417382415922f;  // 512^-0.5
    float* g = G + (size_t)row * NM;
    float l = fmaf(scale, g[t], -0.5f * scale2 * norm2);
    g[t] = l;
    __syncthreads();
    sh[t] = l; __syncthreads();
    for (int o = 64; o > 0; o >>= 1) { if (t < o) sh[t] = fmaxf(sh[t], sh[t + o]); __syncthreads(); }
    if (t == 0) part[row] = sh[0];
}

__global__ void maxred_k(const float* __restrict__ part, int n, float* __restrict__ out) {
    __shared__ float sh[1024];
    int t = threadIdx.x;
    float m = -INFINITY;
    for (int i = t; i < n; i += 1024) m = fmaxf(m, part[i]);
    sh[t] = m; __syncthreads();
    for (int o = 512; o > 0; o >>= 1) { if (t < o) sh[t] = fmaxf(sh[t], sh[t + o]); __syncthreads(); }
    if (t == 0) out[0] = sh[0];
}

__global__ void phiexp_k(float* __restrict__ G, const float* __restrict__ mx, size_t n) {
    size_t i = (size_t)blockIdx.x * 256 + threadIdx.x;
    if (i < n) G[i] = expf(G[i] - mx[0]) * 0.08838834764831845f; // 1/sqrt(128)
}

__global__ void colsum_k(const float* __restrict__ pk, float* __restrict__ z) {
    int b = blockIdx.x, chunk = blockIdx.y, m = threadIdx.x;
    const float* p = pk + (size_t)b * NS * NM + (size_t)chunk * 128 * NM + m;
    float s = 0.f;
    for (int i = 0; i < 128; i++) s += p[(size_t)i * NM];
    atomicAdd(&z[b * NM + m], s);
}

__global__ void divden_k(float* __restrict__ num, const float* __restrict__ pq,
                         const float* __restrict__ z) {
    int warp = threadIdx.x >> 5, lane = threadIdx.x & 31;
    int row = blockIdx.x * 8 + warp;
    int b = row / NS;
    const float* p  = pq + (size_t)row * NM;
    const float* zz = z + b * NM;
    float s = 0.f;
#pragma unroll
    for (int j = 0; j < 4; j++) s = fmaf(p[lane + 32 * j], zz[lane + 32 * j], s);
#pragma unroll
    for (int o = 16; o > 0; o >>= 1) s += __shfl_xor_sync(0xffffffffu, s, o);
    float inv = 1.f / (s + 1e-6f);
    float* nm = num + (size_t)row * NE;
#pragma unroll
    for (int j = 0; j < NE / 32; j++) nm[lane + 32 * j] *= inv;
}

__global__ void ln_k(const float* __restrict__ in, float* __restrict__ out,
                     const float* __restrict__ g, const float* __restrict__ b) {
    int row = blockIdx.x, t = threadIdx.x;
    __shared__ float sh[256];
    const float* a = in + (size_t)row * NE;
    float x0 = a[t], x1 = a[t + 256];
    sh[t] = x0 + x1; __syncthreads();
    for (int o = 128; o > 0; o >>= 1) { if (t < o) sh[t] += sh[t + o]; __syncthreads(); }
    float mu = sh[0] * (1.f / NE);
    __syncthreads();
    float d0 = x0 - mu, d1 = x1 - mu;
    sh[t] = d0 * d0 + d1 * d1; __syncthreads();
    for (int o = 128; o > 0; o >>= 1) { if (t < o) sh[t] += sh[t + o]; __syncthreads(); }
    float rstd = rsqrtf(sh[0] * (1.f / NE) + 1e-5f);
    out[(size_t)row * NE + t]       = d0 * rstd * g[t] + b[t];
    out[(size_t)row * NE + t + 256] = d1 * rstd * g[t + 256] + b[t + 256];
}

// ---------------- host-side dispatch ----------------------------------------

static void gemm(int ta, int act,
                 const float* A, int lda, size_t sA,
                 const float* Bm, int ldb, size_t sB,
                 float* C, int ldc, size_t sC,
                 const float* bias, int M, int N, int K, int batch)
{
    dim3 grid((N + BN - 1) / BN, (M + BM - 1) / BM, batch);
    dim3 blk(256);
    if (ta == 1)            gemm_k<1,0><<<grid,blk>>>(A,lda,sA,Bm,ldb,sB,C,ldc,sC,bias,M,N,K);
    else if (act == 1)      gemm_k<0,1><<<grid,blk>>>(A,lda,sA,Bm,ldb,sB,C,ldc,sC,bias,M,N,K);
    else if (act == 2)      gemm_k<0,2><<<grid,blk>>>(A,lda,sA,Bm,ldb,sB,C,ldc,sC,bias,M,N,K);
    else                    gemm_k<0,0><<<grid,blk>>>(A,lda,sA,Bm,ldb,sB,C,ldc,sC,bias,M,N,K);
}

template<int TRANS_A, int ACT>
static void tc_gemm(const float* A, int lda, size_t sA,
                    const float* Bm, int ldb, size_t sB,
                    float* C, int ldc, size_t sC,
                    const float* bias, int M, int N, int K, int batch)
{
    cudaFuncSetAttribute(tc_gemm_k<TRANS_A, ACT>,
                         cudaFuncAttributeMaxDynamicSharedMemorySize, TC_SMEM_BYTES);
    dim3 grid(N >> 7, M >> 7, batch);
    tc_gemm_k<TRANS_A, ACT><<<grid, 256, TC_SMEM_BYTES>>>(A, lda, sA, Bm, ldb, sB, C, ldc, sC, bias, K);
}

extern "C" void kernel_launch(void* const* d_in, const int* in_sizes, int n_in,
                              void* d_out, int out_size)
{
    const float* x    = (const float*)d_in[0];
    const float* Wi   = (const float*)d_in[1];
    const float* bi   = (const float*)d_in[2];
    const float* pos  = (const float*)d_in[3];
    const float* Wq   = (const float*)d_in[4];
    const float* bq   = (const float*)d_in[5];
    const float* Wk   = (const float*)d_in[6];
    const float* bk   = (const float*)d_in[7];
    const float* Wv   = (const float*)d_in[8];
    const float* bv   = (const float*)d_in[9];
    const float* Wo   = (const float*)d_in[10];
    const float* bo   = (const float*)d_in[11];
    const float* R    = (const float*)d_in[12];
    const float* lng  = (const float*)d_in[13];
    const float* lnb  = (const float*)d_in[14];
    const float* W1   = (const float*)d_in[15];
    const float* b1   = (const float*)d_in[16];
    const float* W2   = (const float*)d_in[17];
    const float* b2   = (const float*)d_in[18];
    const float* Wr1  = (const float*)d_in[19];
    const float* br1  = (const float*)d_in[20];
    const float* Wr2  = (const float*)d_in[21];
    const float* br2  = (const float*)d_in[22];
    float* out = (float*)d_out;

    float *h,*q,*k,*v,*pq,*pk,*kv,*z,*ff,*part,*mx,*r1;
    cudaGetSymbolAddress((void**)&h,  g_h);
    cudaGetSymbolAddress((void**)&q,  g_q);
    cudaGetSymbolAddress((void**)&k,  g_k);
    cudaGetSymbolAddress((void**)&v,  g_v);
    cudaGetSymbolAddress((void**)&pq, g_pq);
    cudaGetSymbolAddress((void**)&pk, g_pk);
    cudaGetSymbolAddress((void**)&kv, g_kv);
    cudaGetSymbolAddress((void**)&z,  g_z);
    cudaGetSymbolAddress((void**)&ff, g_ff);
    cudaGetSymbolAddress((void**)&part, g_part);
    cudaGetSymbolAddress((void**)&mx, g_max);
    cudaGetSymbolAddress((void**)&r1, g_r1);

    const size_t nHE = (size_t)ROWS * NE;
    const size_t nHM = (size_t)ROWS * NM;
    int ew_grid = (int)((nHE + 255) / 256);
    int pm_grid = (int)((nHM + 255) / 256);

    // h = x @ Wi + bi + pos   (K=64, tf32 tensor path)
    tc_gemm<0,0>(x, NDIN,0, Wi, NE,0, h, NE,0, bi, ROWS, NE, NDIN, 1);
    addpos_k<<<ew_grid,256>>>(h, pos);

    for (int i = 0; i < NL; i++) {
        const float* Wq_i = Wq + (size_t)i*NE*NE;   const float* bq_i = bq + (size_t)i*NE;
        const float* Wk_i = Wk + (size_t)i*NE*NE;   const float* bk_i = bk + (size_t)i*NE;
        const float* Wv_i = Wv + (size_t)i*NE*NE;   const float* bv_i = bv + (size_t)i*NE;
        const float* Wo_i = Wo + (size_t)i*NE*NE;   const float* bo_i = bo + (size_t)i*NE;
        const float* R_i  = R  + (size_t)i*NE*NM;
        const float* g_i  = lng + (size_t)i*NE;     const float* b_i  = lnb + (size_t)i*NE;
        const float* W1_i = W1 + (size_t)i*NE*HID;  const float* b1_i = b1 + (size_t)i*HID;
        const float* W2_i = W2 + (size_t)i*HID*NE;  const float* b2_i = b2 + (size_t)i*NE;

        // projections (tensor core tf32)
        tc_gemm<0,0>(h, NE,0, Wq_i, NE,0, q, NE,0, bq_i, ROWS, NE, NE, 1);
        tc_gemm<0,0>(h, NE,0, Wk_i, NE,0, k, NE,0, bk_i, ROWS, NE, NE, 1);
        tc_gemm<0,0>(h, NE,0, Wv_i, NE,0, v, NE,0, bv_i, ROWS, NE, NE, 1);

        // pq = phi(q*scale, R)
        tc_gemm<0,0>(q, NE,0, R_i, NM,0, pq, NM,0, nullptr, ROWS, NM, NE, 1);
        phi_logits_k<<<ROWS,128>>>(pq, q, part);
        maxred_k<<<1,1024>>>(part, ROWS, mx);
        phiexp_k<<<pm_grid,256>>>(pq, mx, nHM);

        // pk = phi(k*scale, R)
        tc_gemm<0,0>(k, NE,0, R_i, NM,0, pk, NM,0, nullptr, ROWS, NM, NE, 1);
        phi_logits_k<<<ROWS,128>>>(pk, k, part);
        maxred_k<<<1,1024>>>(part, ROWS, mx);
        phiexp_k<<<pm_grid,256>>>(pk, mx, nHM);

        // kv[b] = pk[b]^T @ v[b]   (batched, transA, tensor core, K=4096)
        tc_gemm<1,0>(pk, NM, (size_t)NS*NM, v, NE, (size_t)NS*NE,
                     kv, NE, (size_t)NM*NE, nullptr, NM, NE, NS, NB);

        // z[b] = sum_s pk[b,s,:]
        zero_k<<<(NB*NM+255)/256,256>>>(z, NB*NM);
        colsum_k<<<dim3(NB,32),128>>>(pk, z);

        // num -> q (batched, tensor core)
        tc_gemm<0,0>(pq, NM, (size_t)NS*NM, kv, NE, (size_t)NM*NE,
                     q, NE, (size_t)NS*NE, nullptr, NS, NE, NM, NB);

        // q /= (pq . z + 1e-6)
        divden_k<<<ROWS/8,256>>>(q, pq, z);

        // a -> k
        tc_gemm<0,0>(q, NE,0, Wo_i, NE,0, k, NE,0, bo_i, ROWS, NE, NE, 1);

        // y -> v (LayerNorm)
        ln_k<<<ROWS,256>>>(k, v, g_i, b_i);

        // ff1 = gelu(y @ W1 + b1)
        tc_gemm<0,1>(v, NE,0, W1_i, HID,0, ff, HID,0, b1_i, ROWS, HID, NE, 1);
        // ff2 -> q
        tc_gemm<0,0>(ff, HID,0, W2_i, NE,0, q, NE,0, b2_i, ROWS, NE, HID, 1);
        // h += ff2
        add_k<<<ew_grid,256>>>(h, q, nHE);
    }

    // head: pooled = h[:,0,:] (row stride S*E) — tiny, fp32 path
    gemm(0,2, h, NS*NE,0, Wr1, 256,0, r1, 256,0, br1, NB, 256, NE, 1);
    gemm(0,0, r1, 256,0, Wr2, 1,0, out, 1,0, br2, NB, 1, 256, 1);
}

// round 8
// speedup vs baseline: 6.5786x; 1.7143x over previous
#include <cuda_runtime.h>
#include <cuda_fp16.h>
#include <math.h>
#include <stdint.h>

#define NB 16
#define NS 4096
#define NDIN 64
#define NE 512
#define NM 128
#define NL 4
#define ROWS (NB*NS)        /* 65536 */
#define HID (4*NE)          /* 2048 */

// ---------------- scratch (device globals; no allocations allowed) ----------
__device__ float g_h [(size_t)ROWS*NE];
__device__ float g_q [(size_t)ROWS*NE];
__device__ float g_k [(size_t)ROWS*NE];
__device__ float g_pq[(size_t)ROWS*NM];
__device__ float g_pk[(size_t)ROWS*NM];
__device__ float g_z [NB*NM];
__device__ float g_part [ROWS];   // per-row max (pk pass)
__device__ float g_rowq [ROWS];   // per-row max for pq
__device__ float g_max [1];       // global max (pk)
__device__ float g_maxq[1];       // global max (pq)
__device__ float g_bmk [NB];      // per-batch max (pk)
__device__ float g_r1[16*256];

// fp16 mirrors
__device__ __half g_h16 [(size_t)ROWS*NE];
__device__ __half g_q16 [(size_t)ROWS*NE];
__device__ __half g_k16 [(size_t)ROWS*NE];
__device__ __half g_v16 [(size_t)ROWS*NE];
__device__ __half g_pq16[(size_t)ROWS*NM];
__device__ __half g_pk16[(size_t)ROWS*NM];
__device__ __half g_kv16[(size_t)NB*NM*NE];
__device__ __half g_ff16[(size_t)ROWS*HID];
__device__ __half g_x16 [(size_t)ROWS*NDIN];
__device__ __half g_wi16[NDIN*NE];
__device__ __half g_wq16[(size_t)NL*NE*NE];
__device__ __half g_wk16[(size_t)NL*NE*NE];
__device__ __half g_wv16[(size_t)NL*NE*NE];
__device__ __half g_wo16[(size_t)NL*NE*NE];
__device__ __half g_r16 [(size_t)NL*NE*NM];
__device__ __half g_w116[(size_t)NL*NE*HID];
__device__ __half g_w216[(size_t)NL*HID*NE];

// ================= helpers =================
__device__ __forceinline__ uint32_t smem_u32(const void* p) {
    uint32_t r;
    asm("{ .reg .u64 t; cvta.to.shared.u64 t, %1; cvt.u32.u64 %0, t; }" : "=r"(r) : "l"(p));
    return r;
}
__device__ __forceinline__ void cp_async16(uint32_t saddr, const void* g) {
    asm volatile("cp.async.cg.shared.global [%0], [%1], 16;" :: "r"(saddr), "l"(g));
}
__device__ __forceinline__ void ldsm_x4(uint32_t r[4], uint32_t addr) {
    asm volatile("ldmatrix.sync.aligned.m8n8.x4.shared.b16 {%0,%1,%2,%3}, [%4];"
                 : "=r"(r[0]), "=r"(r[1]), "=r"(r[2]), "=r"(r[3]) : "r"(addr));
}
__device__ __forceinline__ void ldsm_x4_t(uint32_t r[4], uint32_t addr) {
    asm volatile("ldmatrix.sync.aligned.m8n8.x4.trans.shared.b16 {%0,%1,%2,%3}, [%4];"
                 : "=r"(r[0]), "=r"(r[1]), "=r"(r[2]), "=r"(r[3]) : "r"(addr));
}
__device__ __forceinline__ void mma_f16(float c[4], const uint32_t a[4], const uint32_t b[2]) {
    asm volatile(
        "mma.sync.aligned.m16n8k16.row.col.f32.f16.f16.f32 "
        "{%0,%1,%2,%3}, {%4,%5,%6,%7}, {%8,%9}, {%0,%1,%2,%3};"
        : "+f"(c[0]), "+f"(c[1]), "+f"(c[2]), "+f"(c[3])
        : "r"(a[0]), "r"(a[1]), "r"(a[2]), "r"(a[3]), "r"(b[0]), "r"(b[1]));
}

// ================= fp16 mma GEMM =================
// C[M,N] = op(A)[M,K] @ B[K,N] (+bias)(+gelu). fp16 in, fp32 accum, fp32/fp16 out.
// CTA tile 128x128, BK=32, 4-stage cp.async pipeline, ldmatrix fragments.
// smem (halves): A nontrans [128 m][32 k] stride 40; A trans & B [32 k][128 mn] stride 136.

#define BKH 32
#define A_HS 40
#define T_HS 136
#define HG_STAGES 4

template<int TRANS_A>
__device__ __forceinline__ void h_fill(const __half* __restrict__ A, int lda,
                                       const __half* __restrict__ B, int ldb,
                                       int m0, int n0, int kof,
                                       uint32_t sa, uint32_t sb, int tid) {
    if (!TRANS_A) {
#pragma unroll
        for (int i = 0; i < 2; i++) {
            int lin = (i << 8) + tid;
            int row = lin >> 2, c = lin & 3;
            cp_async16(sa + (uint32_t)(row * A_HS + (c << 3)) * 2,
                       A + (size_t)(m0 + row) * lda + kof + (c << 3));
        }
    } else {
#pragma unroll
        for (int i = 0; i < 2; i++) {
            int lin = (i << 8) + tid;
            int row = lin >> 4, c = lin & 15;
            cp_async16(sa + (uint32_t)(row * T_HS + (c << 3)) * 2,
                       A + (size_t)(kof + row) * lda + m0 + (c << 3));
        }
    }
#pragma unroll
    for (int i = 0; i < 2; i++) {
        int lin = (i << 8) + tid;
        int row = lin >> 4, c = lin & 15;
        cp_async16(sb + (uint32_t)(row * T_HS + (c << 3)) * 2,
                   B + (size_t)(kof + row) * ldb + n0 + (c << 3));
    }
}

template<int TRANS_A, int ACT, int WF32, int WF16>
__global__ __launch_bounds__(256, 2)
void hgemm_k(const __half* __restrict__ A, int lda, size_t sAs,
             const __half* __restrict__ B, int ldb, size_t sBs,
             float* __restrict__ C, __half* __restrict__ C16, int ldc, size_t sCs,
             const float* __restrict__ bias, int K)
{
    constexpr int ATILE_B = TRANS_A ? (BKH * T_HS * 2) : (128 * A_HS * 2);
    constexpr int STAGE_B = ATILE_B + BKH * T_HS * 2;

    extern __shared__ __half hsm[];
    uint32_t smb = smem_u32(hsm);
    int tid = threadIdx.x;
    int wid = tid >> 5, lane = tid & 31;
    int group = lane >> 3, lr = lane & 7;
    int g = lane >> 2, t4 = lane & 3;

    A += (size_t)blockIdx.z * sAs;
    B += (size_t)blockIdx.z * sBs;
    int m0 = blockIdx.y << 7;
    int n0 = blockIdx.x << 7;
    int wm = wid & 1, wn = wid >> 1;

    float c[4][4][4];
#pragma unroll
    for (int a = 0; a < 4; a++)
#pragma unroll
        for (int b = 0; b < 4; b++)
#pragma unroll
            for (int r = 0; r < 4; r++) c[a][b][r] = 0.f;

    int nk = K >> 5;

#pragma unroll
    for (int s = 0; s < HG_STAGES - 1; s++) {
        if (s < nk) {
            uint32_t sa = smb + (uint32_t)s * STAGE_B;
            h_fill<TRANS_A>(A, lda, B, ldb, m0, n0, s << 5, sa, sa + ATILE_B, tid);
        }
        asm volatile("cp.async.commit_group;");
    }

    for (int kt = 0; kt < nk; kt++) {
        asm volatile("cp.async.wait_group %0;" :: "n"(HG_STAGES - 2));
        __syncthreads();

        int nxt = kt + HG_STAGES - 1;
        if (nxt < nk) {
            uint32_t sa = smb + (uint32_t)(nxt & (HG_STAGES - 1)) * STAGE_B;
            h_fill<TRANS_A>(A, lda, B, ldb, m0, n0, nxt << 5, sa, sa + ATILE_B, tid);
        }
        asm volatile("cp.async.commit_group;");

        uint32_t sa = smb + (uint32_t)(kt & (HG_STAGES - 1)) * STAGE_B;
        uint32_t sb = sa + ATILE_B;
#pragma unroll
        for (int ks = 0; ks < 2; ks++) {
            uint32_t af[4][4];
#pragma unroll
            for (int mi = 0; mi < 4; mi++) {
                uint32_t addr;
                if (!TRANS_A) {
                    int arow = (wm << 6) + (mi << 4) + ((group & 1) << 3) + lr;
                    int acol = (ks << 4) + ((group >> 1) << 3);
                    addr = sa + (uint32_t)(arow * A_HS + acol) * 2;
                    ldsm_x4(af[mi], addr);
                } else {
                    int krow = (ks << 4) + ((group >> 1) << 3) + lr;
                    int mcol = (wm << 6) + (mi << 4) + ((group & 1) << 3);
                    addr = sa + (uint32_t)(krow * T_HS + mcol) * 2;
                    ldsm_x4_t(af[mi], addr);
                }
            }
            uint32_t bf[2][4];
#pragma unroll
            for (int np = 0; np < 2; np++) {
                int krow = (ks << 4) + ((group & 1) << 3) + lr;
                int ncol = (wn << 5) + (np << 4) + ((group >> 1) << 3);
                ldsm_x4_t(bf[np], sb + (uint32_t)(krow * T_HS + ncol) * 2);
            }
#pragma unroll
            for (int mi = 0; mi < 4; mi++)
#pragma unroll
                for (int ni = 0; ni < 4; ni++)
                    mma_f16(c[mi][ni], af[mi], &bf[ni >> 1][(ni & 1) << 1]);
        }
    }

    // ---- epilogue ----
    const float GK = 0.7071067811865476f;
#pragma unroll
    for (int mi = 0; mi < 4; mi++) {
        size_t rowoff0 = (size_t)blockIdx.z * sCs + (size_t)(m0 + (wm << 6) + (mi << 4) + g) * ldc;
        size_t rowoff1 = rowoff0 + (size_t)8 * ldc;
#pragma unroll
        for (int ni = 0; ni < 4; ni++) {
            int nn = n0 + (wn << 5) + (ni << 3) + (t4 << 1);
            float v0 = c[mi][ni][0], v1 = c[mi][ni][1];
            float v2 = c[mi][ni][2], v3 = c[mi][ni][3];
            if (bias) {
                float b0 = __ldg(bias + nn), b1 = __ldg(bias + nn + 1);
                v0 += b0; v1 += b1; v2 += b0; v3 += b1;
            }
            if (ACT == 1) {
                v0 = 0.5f * v0 * (1.f + erff(v0 * GK));
                v1 = 0.5f * v1 * (1.f + erff(v1 * GK));
                v2 = 0.5f * v2 * (1.f + erff(v2 * GK));
                v3 = 0.5f * v3 * (1.f + erff(v3 * GK));
            }
            if (WF32) {
                *(float2*)(C + rowoff0 + nn) = make_float2(v0, v1);
                *(float2*)(C + rowoff1 + nn) = make_float2(v2, v3);
            }
            if (WF16) {
                *(__half2*)(C16 + rowoff0 + nn) = __floats2half2_rn(v0, v1);
                *(__half2*)(C16 + rowoff1 + nn) = __floats2half2_rn(v2, v3);
            }
        }
    }
}

// ================= fp32 fallback SGEMM (head only) =================
#define BM 128
#define BN 128
#define BK 8

template<int ACT>
__global__ __launch_bounds__(256)
void gemm_k(const float* __restrict__ A, int lda,
            const float* __restrict__ Bm, int ldb,
            float* __restrict__ C, int ldc,
            const float* __restrict__ bias,
            int M, int N, int K)
{
    int m0 = blockIdx.y * BM;
    int n0 = blockIdx.x * BN;

    __shared__ float As[BK][BM];
    __shared__ float Bs[BK][BN];

    int tid = threadIdx.x;
    int tx = tid & 15, ty = tid >> 4;

    float acc[8][8];
#pragma unroll
    for (int i = 0; i < 8; i++)
#pragma unroll
        for (int j = 0; j < 8; j++) acc[i][j] = 0.f;

    float ar[8], br[8];

    for (int k0 = 0; k0 < K; k0 += BK) {
        {
            int m  = tid >> 1;
            int kk = (tid & 1) * 4;
            bool mok = (m0 + m) < M;
            const float* src = A + (size_t)(m0 + m) * lda + k0 + kk;
#pragma unroll
            for (int i = 0; i < 4; i++)
                As[kk + i][m] = mok ? src[i] : 0.f;
        }
        {
            int k = tid >> 5;
            int n = (tid & 31) * 4;
            const float* src = Bm + (size_t)(k0 + k) * ldb + n0 + n;
#pragma unroll
            for (int i = 0; i < 4; i++) {
                float vv = 0.f;
                if (n0 + n + i < N) vv = src[i];
                Bs[k][n + i] = vv;
            }
        }
        __syncthreads();
#pragma unroll
        for (int k = 0; k < BK; k++) {
            *(float4*)&ar[0] = *(float4*)&As[k][ty * 4];
            *(float4*)&ar[4] = *(float4*)&As[k][64 + ty * 4];
            *(float4*)&br[0] = *(float4*)&Bs[k][tx * 4];
            *(float4*)&br[4] = *(float4*)&Bs[k][64 + tx * 4];
#pragma unroll
            for (int i = 0; i < 8; i++)
#pragma unroll
                for (int j = 0; j < 8; j++)
                    acc[i][j] = fmaf(ar[i], br[j], acc[i][j]);
        }
        __syncthreads();
    }

#pragma unroll
    for (int i = 0; i < 8; i++) {
        int m = m0 + ((i < 4) ? (ty * 4 + i) : (64 + ty * 4 + i - 4));
        if (m >= M) continue;
#pragma unroll
        for (int j = 0; j < 8; j++) {
            int n = n0 + ((j < 4) ? (tx * 4 + j) : (64 + tx * 4 + j - 4));
            if (n >= N) continue;
            float vv = acc[i][j];
            if (bias) vv += bias[n];
            if (ACT == 2) vv = fmaxf(vv, 0.f);
            C[(size_t)m * ldc + n] = vv;
        }
    }
}

// ---------------- elementwise / reduction kernels ---------------------------

__global__ void conv16_k(const float* __restrict__ in, __half* __restrict__ out, size_t n) {
    size_t i = ((size_t)blockIdx.x * 256 + threadIdx.x) * 4;
    if (i < n) {
        float4 v = *(const float4*)(in + i);
        *(__half2*)(out + i)     = __floats2half2_rn(v.x, v.y);
        *(__half2*)(out + i + 2) = __floats2half2_rn(v.z, v.w);
    }
}

__global__ void addpos_k(float* __restrict__ h, __half* __restrict__ h16,
                         const float* __restrict__ pos) {
    size_t i = (size_t)blockIdx.x * 256 + threadIdx.x;
    if (i < (size_t)ROWS * NE) {
        float v = h[i] + pos[i % ((size_t)NS * NE)];
        h[i] = v;
        h16[i] = __float2half_rn(v);
    }
}

__global__ void add_k(float* __restrict__ a, __half* __restrict__ a16,
                      const float* __restrict__ b, size_t n) {
    size_t i = (size_t)blockIdx.x * 256 + threadIdx.x;
    if (i < n) {
        float v = a[i] + b[i];
        a[i] = v;
        a16[i] = __float2half_rn(v);
    }
}

__global__ void zero_k(float* p, int n) {
    int i = blockIdx.x * 256 + threadIdx.x;
    if (i < n) p[i] = 0.f;
}

// logits in-place over G = u@R; per-row max into part[]
__global__ void phi_logits_k(float* __restrict__ G, const float* __restrict__ U,
                             float* __restrict__ part) {
    int row = blockIdx.x;
    int t = threadIdx.x;             // 128
    __shared__ float sh[128];
    const float* u = U + (size_t)row * NE;
    float s = 0.f;
#pragma unroll
    for (int j = 0; j < NE; j += 128) { float x = u[t + j]; s = fmaf(x, x, s); }
    sh[t] = s; __syncthreads();
    for (int o = 64; o > 0; o >>= 1) { if (t < o) sh[t] += sh[t + o]; __syncthreads(); }
    float norm2 = sh[0];
    const float scale  = 0.21022410381342865f;  // 512^-0.25
    const float scale2 = 0.04419417382415922f;  // 512^-0.5
    float* gg = G + (size_t)row * NM;
    float l = fmaf(scale, gg[t], -0.5f * scale2 * norm2);
    gg[t] = l;
    __syncthreads();
    sh[t] = l; __syncthreads();
    for (int o = 64; o > 0; o >>= 1) { if (t < o) sh[t] = fmaxf(sh[t], sh[t + o]); __syncthreads(); }
    if (t == 0) part[row] = sh[0];
}

__global__ void maxred_k(const float* __restrict__ part, int n, float* __restrict__ out) {
    __shared__ float sh[1024];
    int t = threadIdx.x;
    float m = -INFINITY;
    for (int i = t; i < n; i += 1024) m = fmaxf(m, part[i]);
    sh[t] = m; __syncthreads();
    for (int o = 512; o > 0; o >>= 1) { if (t < o) sh[t] = fmaxf(sh[t], sh[t + o]); __syncthreads(); }
    if (t == 0) out[0] = sh[0];
}

// per-batch max: block b reduces part[b*NS .. b*NS+NS)
__global__ void maxredB_k(const float* __restrict__ part, float* __restrict__ out) {
    __shared__ float sh[1024];
    int t = threadIdx.x, b = blockIdx.x;
    const float* p = part + (size_t)b * NS;
    float m = -INFINITY;
    for (int i = t; i < NS; i += 1024) m = fmaxf(m, p[i]);
    sh[t] = m; __syncthreads();
    for (int o = 512; o > 0; o >>= 1) { if (t < o) sh[t] = fmaxf(sh[t], sh[t + o]); __syncthreads(); }
    if (t == 0) out[b] = sh[0];
}

// pk path: fp32 = exp(l-gmax)/sqrt(M) (z/den path, reference-exact);
// fp16 = exp(l-batchmax[b])/sqrt(M) (kv path, no flush; factor folded into divden)
__global__ void phiexp_pk_k(float* __restrict__ G, __half* __restrict__ G16,
                            const float* __restrict__ bmax,
                            const float* __restrict__ mx, size_t n) {
    size_t i = (size_t)blockIdx.x * 256 + threadIdx.x;
    if (i < n) {
        float l = G[i];
        float bm = bmax[i >> 19];    // NS*NM = 2^19 elements per batch
        G[i]  = expf(l - mx[0]) * 0.08838834764831845f; // 1/sqrt(128)
        G16[i] = __float2half_rn(expf(l - bm) * 0.08838834764831845f);
    }
}

// pq path: fp32 = exp(l-gmax)/sqrt(M) (den); fp16 = exp(l-rowmax)/sqrt(M) (num)
__global__ void phiexp_pq_k(float* __restrict__ G, __half* __restrict__ G16,
                            const float* __restrict__ rowmax,
                            const float* __restrict__ mx, size_t n) {
    size_t i = (size_t)blockIdx.x * 256 + threadIdx.x;
    if (i < n) {
        float l = G[i];
        float rm = rowmax[i >> 7];   // NM = 128
        G[i]  = expf(l - mx[0]) * 0.08838834764831845f;
        G16[i] = __float2half_rn(expf(l - rm) * 0.08838834764831845f);
    }
}

__global__ void colsum_k(const float* __restrict__ pk, float* __restrict__ z) {
    int b = blockIdx.x, chunk = blockIdx.y, m = threadIdx.x;
    const float* p = pk + (size_t)b * NS * NM + (size_t)chunk * 128 * NM + m;
    float s = 0.f;
    for (int i = 0; i < 128; i++) s += p[(size_t)i * NM];
    atomicAdd(&z[b * NM + m], s);
}

// num16 = num_scaled * exp(rowmax_q-gmax_q + batchmax_k-gmax_k) / (pq.z + 1e-6)
__global__ void divden_k(const float* __restrict__ num, __half* __restrict__ num16,
                         const float* __restrict__ pq, const float* __restrict__ z,
                         const float* __restrict__ rowmax, const float* __restrict__ mxq,
                         const float* __restrict__ bmk, const float* __restrict__ mxk) {
    int warp = threadIdx.x >> 5, lane = threadIdx.x & 31;
    int row = blockIdx.x * 8 + warp;
    int b = row / NS;
    const float* p  = pq + (size_t)row * NM;
    const float* zz = z + b * NM;
    float s = 0.f;
#pragma unroll
    for (int j = 0; j < 4; j++) s = fmaf(p[lane + 32 * j], zz[lane + 32 * j], s);
#pragma unroll
    for (int o = 16; o > 0; o >>= 1) s += __shfl_xor_sync(0xffffffffu, s, o);
    float factor = expf((rowmax[row] - mxq[0]) + (bmk[b] - mxk[0]));
    float inv = factor / (s + 1e-6f);
    const float* nm = num + (size_t)row * NE;
    __half* nm16 = num16 + (size_t)row * NE;
#pragma unroll
    for (int j = 0; j < NE / 32; j++)
        nm16[lane + 32 * j] = __float2half_rn(nm[lane + 32 * j] * inv);
}

// LayerNorm over E=512; writes fp16 only (consumer is FF1 GEMM)
__global__ void ln_k(const float* __restrict__ in, __half* __restrict__ out16,
                     const float* __restrict__ g, const float* __restrict__ b) {
    int row = blockIdx.x, t = threadIdx.x;
    __shared__ float sh[256];
    const float* a = in + (size_t)row * NE;
    float x0 = a[t], x1 = a[t + 256];
    sh[t] = x0 + x1; __syncthreads();
    for (int o = 128; o > 0; o >>= 1) { if (t < o) sh[t] += sh[t + o]; __syncthreads(); }
    float mu = sh[0] * (1.f / NE);
    __syncthreads();
    float d0 = x0 - mu, d1 = x1 - mu;
    sh[t] = d0 * d0 + d1 * d1; __syncthreads();
    for (int o = 128; o > 0; o >>= 1) { if (t < o) sh[t] += sh[t + o]; __syncthreads(); }
    float rstd = rsqrtf(sh[0] * (1.f / NE) + 1e-5f);
    out16[(size_t)row * NE + t]       = __float2half_rn(d0 * rstd * g[t] + b[t]);
    out16[(size_t)row * NE + t + 256] = __float2half_rn(d1 * rstd * g[t + 256] + b[t + 256]);
}

// ---------------- host-side dispatch ----------------------------------------

template<int TRANS_A, int ACT, int WF32, int WF16>
static void hgemm(const __half* A, int lda, size_t sA,
                  const __half* Bm, int ldb, size_t sB,
                  float* C, __half* C16, int ldc, size_t sC,
                  const float* bias, int M, int N, int K, int batch)
{
    constexpr int ATILE_B = TRANS_A ? (BKH * T_HS * 2) : (128 * A_HS * 2);
    constexpr int SMEM = HG_STAGES * (ATILE_B + BKH * T_HS * 2);
    cudaFuncSetAttribute(hgemm_k<TRANS_A, ACT, WF32, WF16>,
                         cudaFuncAttributeMaxDynamicSharedMemorySize, SMEM);
    dim3 grid(N >> 7, M >> 7, batch);
    hgemm_k<TRANS_A, ACT, WF32, WF16><<<grid, 256, SMEM>>>(
        A, lda, sA, Bm, ldb, sB, C, C16, ldc, sC, bias, K);
}

static void conv16(const float* in, __half* out, size_t n) {
    conv16_k<<<(unsigned)((n / 4 + 255) / 256), 256>>>(in, out, n);
}

extern "C" void kernel_launch(void* const* d_in, const int* in_sizes, int n_in,
                              void* d_out, int out_size)
{
    const float* x    = (const float*)d_in[0];
    const float* Wi   = (const float*)d_in[1];
    const float* bi   = (const float*)d_in[2];
    const float* pos  = (const float*)d_in[3];
    const float* Wq   = (const float*)d_in[4];
    const float* bq   = (const float*)d_in[5];
    const float* Wk   = (const float*)d_in[6];
    const float* bk   = (const float*)d_in[7];
    const float* Wv   = (const float*)d_in[8];
    const float* bv   = (const float*)d_in[9];
    const float* Wo   = (const float*)d_in[10];
    const float* bo   = (const float*)d_in[11];
    const float* R    = (const float*)d_in[12];
    const float* lng  = (const float*)d_in[13];
    const float* lnb  = (const float*)d_in[14];
    const float* W1   = (const float*)d_in[15];
    const float* b1   = (const float*)d_in[16];
    const float* W2   = (const float*)d_in[17];
    const float* b2   = (const float*)d_in[18];
    const float* Wr1  = (const float*)d_in[19];
    const float* br1  = (const float*)d_in[20];
    const float* Wr2  = (const float*)d_in[21];
    const float* br2  = (const float*)d_in[22];
    float* out = (float*)d_out;

    float *h,*q,*k,*pq,*pk,*z,*part,*rowq,*mx,*mxq,*bmk,*r1;
    __half *h16,*q16,*k16,*v16,*pq16,*pk16,*kv16,*ff16,*x16;
    __half *wi16,*wq16,*wk16,*wv16,*wo16,*r16,*w116,*w216;
    cudaGetSymbolAddress((void**)&h,  g_h);
    cudaGetSymbolAddress((void**)&q,  g_q);
    cudaGetSymbolAddress((void**)&k,  g_k);
    cudaGetSymbolAddress((void**)&pq, g_pq);
    cudaGetSymbolAddress((void**)&pk, g_pk);
    cudaGetSymbolAddress((void**)&z,  g_z);
    cudaGetSymbolAddress((void**)&part, g_part);
    cudaGetSymbolAddress((void**)&rowq, g_rowq);
    cudaGetSymbolAddress((void**)&mx, g_max);
    cudaGetSymbolAddress((void**)&mxq, g_maxq);
    cudaGetSymbolAddress((void**)&bmk, g_bmk);
    cudaGetSymbolAddress((void**)&r1, g_r1);
    cudaGetSymbolAddress((void**)&h16,  g_h16);
    cudaGetSymbolAddress((void**)&q16,  g_q16);
    cudaGetSymbolAddress((void**)&k16,  g_k16);
    cudaGetSymbolAddress((void**)&v16,  g_v16);
    cudaGetSymbolAddress((void**)&pq16, g_pq16);
    cudaGetSymbolAddress((void**)&pk16, g_pk16);
    cudaGetSymbolAddress((void**)&kv16, g_kv16);
    cudaGetSymbolAddress((void**)&ff16, g_ff16);
    cudaGetSymbolAddress((void**)&x16,  g_x16);
    cudaGetSymbolAddress((void**)&wi16, g_wi16);
    cudaGetSymbolAddress((void**)&wq16, g_wq16);
    cudaGetSymbolAddress((void**)&wk16, g_wk16);
    cudaGetSymbolAddress((void**)&wv16, g_wv16);
    cudaGetSymbolAddress((void**)&wo16, g_wo16);
    cudaGetSymbolAddress((void**)&r16,  g_r16);
    cudaGetSymbolAddress((void**)&w116, g_w116);
    cudaGetSymbolAddress((void**)&w216, g_w216);

    const size_t nHE = (size_t)ROWS * NE;
    const size_t nHM = (size_t)ROWS * NM;
    int ew_grid = (int)((nHE + 255) / 256);
    int pm_grid = (int)((nHM + 255) / 256);

    // ---- fp16 weight/input mirrors ----
    conv16(x,  x16, (size_t)ROWS * NDIN);
    conv16(Wi, wi16, (size_t)NDIN * NE);
    conv16(Wq, wq16, (size_t)NL * NE * NE);
    conv16(Wk, wk16, (size_t)NL * NE * NE);
    conv16(Wv, wv16, (size_t)NL * NE * NE);
    conv16(Wo, wo16, (size_t)NL * NE * NE);
    conv16(R,  r16,  (size_t)NL * NE * NM);
    conv16(W1, w116, (size_t)NL * NE * HID);
    conv16(W2, w216, (size_t)NL * HID * NE);

    // h = x @ Wi + bi ; then += pos (dual-write h16)
    hgemm<0,0,1,0>(x16, NDIN,0, wi16, NE,0, h, nullptr, NE,0, bi, ROWS, NE, NDIN, 1);
    addpos_k<<<ew_grid,256>>>(h, h16, pos);

    for (int i = 0; i < NL; i++) {
        const __half* wq_i = wq16 + (size_t)i*NE*NE;  const float* bq_i = bq + (size_t)i*NE;
        const __half* wk_i = wk16 + (size_t)i*NE*NE;  const float* bk_i = bk + (size_t)i*NE;
        const __half* wv_i = wv16 + (size_t)i*NE*NE;  const float* bv_i = bv + (size_t)i*NE;
        const __half* wo_i = wo16 + (size_t)i*NE*NE;  const float* bo_i = bo + (size_t)i*NE;
        const __half* r_i  = r16  + (size_t)i*NE*NM;
        const float* g_i  = lng + (size_t)i*NE;       const float* b_i  = lnb + (size_t)i*NE;
        const __half* w1_i = w116 + (size_t)i*NE*HID; const float* b1_i = b1 + (size_t)i*HID;
        const __half* w2_i = w216 + (size_t)i*HID*NE; const float* b2_i = b2 + (size_t)i*NE;

        // projections
        hgemm<0,0,1,1>(h16, NE,0, wq_i, NE,0, q, q16, NE,0, bq_i, ROWS, NE, NE, 1);
        hgemm<0,0,1,1>(h16, NE,0, wk_i, NE,0, k, k16, NE,0, bk_i, ROWS, NE, NE, 1);
        hgemm<0,0,0,1>(h16, NE,0, wv_i, NE,0, nullptr, v16, NE,0, bv_i, ROWS, NE, NE, 1);

        // pq = phi(q*scale, R)  (rowmax in rowq, gmax in mxq)
        hgemm<0,0,1,0>(q16, NE,0, r_i, NM,0, pq, nullptr, NM,0, nullptr, ROWS, NM, NE, 1);
        phi_logits_k<<<ROWS,128>>>(pq, q, rowq);
        maxred_k<<<1,1024>>>(rowq, ROWS, mxq);
        phiexp_pq_k<<<pm_grid,256>>>(pq, pq16, rowq, mxq, nHM);

        // pk = phi(k*scale, R)  (rowmax in part, gmax in mx, batchmax in bmk)
        hgemm<0,0,1,0>(k16, NE,0, r_i, NM,0, pk, nullptr, NM,0, nullptr, ROWS, NM, NE, 1);
        phi_logits_k<<<ROWS,128>>>(pk, k, part);
        maxred_k<<<1,1024>>>(part, ROWS, mx);
        maxredB_k<<<NB,1024>>>(part, bmk);
        phiexp_pk_k<<<pm_grid,256>>>(pk, pk16, bmk, mx, nHM);

        // kv[b] = pk16[b]^T @ v16[b]   (batched, transA, fp16, K=4096; batch-normalized)
        hgemm<1,0,0,1>(pk16, NM, (size_t)NS*NM, v16, NE, (size_t)NS*NE,
                       nullptr, kv16, NE, (size_t)NM*NE, nullptr, NM, NE, NS, NB);

        // z[b] = sum_s pk[b,s,:]  (fp32, gmax-normalized: reference-exact den)
        zero_k<<<(NB*NM+255)/256,256>>>(z, NB*NM);
        colsum_k<<<dim3(NB,32),128>>>(pk, z);

        // num_scaled -> q (batched; pq16 row-normalized, kv16 batch-normalized)
        hgemm<0,0,1,0>(pq16, NM, (size_t)NS*NM, kv16, NE, (size_t)NM*NE,
                       q, nullptr, NE, (size_t)NS*NE, nullptr, NS, NE, NM, NB);

        // q16 = q * exp(rowq-mxq + bmk-mx) / (pq . z + 1e-6)
        divden_k<<<ROWS/8,256>>>(q, q16, pq, z, rowq, mxq, bmk, mx);

        // a -> k (fp32, LN input)
        hgemm<0,0,1,0>(q16, NE,0, wo_i, NE,0, k, nullptr, NE,0, bo_i, ROWS, NE, NE, 1);

        // y -> v16 (LayerNorm, fp16 out)
        ln_k<<<ROWS,256>>>(k, v16, g_i, b_i);

        // ff1 = gelu(y @ W1 + b1) -> ff16
        hgemm<0,1,0,1>(v16, NE,0, w1_i, HID,0, nullptr, ff16, HID,0, b1_i, ROWS, HID, NE, 1);
        // ff2 -> q (fp32)
        hgemm<0,0,1,0>(ff16, HID,0, w2_i, NE,0, q, nullptr, NE,0, b2_i, ROWS, NE, HID, 1);
        // h += ff2 (dual-write h16)
        add_k<<<ew_grid,256>>>(h, h16, q, nHE);
    }

    // head: pooled = h[:,0,:] (row stride S*E) — tiny, fp32 path
    {
        dim3 g1((256 + BN - 1) / BN, (NB + BM - 1) / BM);
        gemm_k<2><<<g1, 256>>>(h, NS*NE, Wr1, 256, r1, 256, br1, NB, 256, NE);
        dim3 g2(1, 1);
        gemm_k<0><<<g2, 256>>>(r1, 256, Wr2, 1, out, 1, br2, NB, 1, 256);
    }
}

// round 9
// speedup vs baseline: 7.4516x; 1.1327x over previous
#include <cuda_runtime.h>
#include <cuda_fp16.h>
#include <math.h>
#include <stdint.h>

#define NB 16
#define NS 4096
#define NDIN 64
#define NE 512
#define NM 128
#define NL 4
#define ROWS (NB*NS)        /* 65536 */
#define HID (4*NE)          /* 2048 */

// ---------------- scratch (device globals; no allocations allowed) ----------
__device__ float g_h [(size_t)ROWS*NE];
__device__ float g_k [(size_t)ROWS*NE];
__device__ float g_pq[(size_t)ROWS*NM];
__device__ float g_pk[(size_t)ROWS*NM];
__device__ float g_z [NB*NM];
__device__ float g_part [ROWS];   // per-row max (pk pass)
__device__ float g_rowq [ROWS];   // per-row max for pq
__device__ float g_nq  [ROWS];    // per-row sum-of-squares (q)
__device__ float g_nk  [ROWS];    // per-row sum-of-squares (k)
__device__ float g_inv [ROWS];    // per-row 1/den factor
__device__ float g_max [1];       // global max (pk)
__device__ float g_maxq[1];       // global max (pq)
__device__ float g_bmk [NB];      // per-batch max (pk)
__device__ float g_r1[16*256];

// fp16 mirrors
__device__ __half g_h16 [(size_t)ROWS*NE];
__device__ __half g_q16 [(size_t)ROWS*NE];
__device__ __half g_k16 [(size_t)ROWS*NE];
__device__ __half g_v16 [(size_t)ROWS*NE];
__device__ __half g_pq16[(size_t)ROWS*NM];
__device__ __half g_pk16[(size_t)ROWS*NM];
__device__ __half g_kv16[(size_t)NB*NM*NE];
__device__ __half g_ff16[(size_t)ROWS*HID];
__device__ __half g_x16 [(size_t)ROWS*NDIN];
__device__ __half g_wi16[NDIN*NE];
__device__ __half g_wq16[(size_t)NL*NE*NE];
__device__ __half g_wk16[(size_t)NL*NE*NE];
__device__ __half g_wv16[(size_t)NL*NE*NE];
__device__ __half g_wo16[(size_t)NL*NE*NE];
__device__ __half g_r16 [(size_t)NL*NE*NM];
__device__ __half g_w116[(size_t)NL*NE*HID];
__device__ __half g_w216[(size_t)NL*HID*NE];

// ================= helpers =================
__device__ __forceinline__ uint32_t smem_u32(const void* p) {
    uint32_t r;
    asm("{ .reg .u64 t; cvta.to.shared.u64 t, %1; cvt.u32.u64 %0, t; }" : "=r"(r) : "l"(p));
    return r;
}
__device__ __forceinline__ void cp_async16(uint32_t saddr, const void* g) {
    asm volatile("cp.async.cg.shared.global [%0], [%1], 16;" :: "r"(saddr), "l"(g));
}
__device__ __forceinline__ void ldsm_x4(uint32_t r[4], uint32_t addr) {
    asm volatile("ldmatrix.sync.aligned.m8n8.x4.shared.b16 {%0,%1,%2,%3}, [%4];"
                 : "=r"(r[0]), "=r"(r[1]), "=r"(r[2]), "=r"(r[3]) : "r"(addr));
}
__device__ __forceinline__ void ldsm_x4_t(uint32_t r[4], uint32_t addr) {
    asm volatile("ldmatrix.sync.aligned.m8n8.x4.trans.shared.b16 {%0,%1,%2,%3}, [%4];"
                 : "=r"(r[0]), "=r"(r[1]), "=r"(r[2]), "=r"(r[3]) : "r"(addr));
}
__device__ __forceinline__ void mma_f16(float c[4], const uint32_t a[4], const uint32_t b[2]) {
    asm volatile(
        "mma.sync.aligned.m16n8k16.row.col.f32.f16.f16.f32 "
        "{%0,%1,%2,%3}, {%4,%5,%6,%7}, {%8,%9}, {%0,%1,%2,%3};"
        : "+f"(c[0]), "+f"(c[1]), "+f"(c[2]), "+f"(c[3])
        : "r"(a[0]), "r"(a[1]), "r"(a[2]), "r"(a[3]), "r"(b[0]), "r"(b[1]));
}

// ================= fp16 mma GEMM with fused epilogues =================
// MODE 0: plain (bias, ACT, WF32/WF16 writes)
// MODE 1: SUMSQ  — write C16; atomicAdd per-row sum of squares into aux1
// MODE 2: PHI    — logit = acc*SCALE - 0.5*scale2*aux1[row]; write fp32 C;
//                  per-row max into aux2 (smem stage reduction; needs grid.x==1)
// MODE 3: SCALEROW — acc *= aux1[absrow]; write C16
// MODE 4: RESID  — acc += bias + C[row]; write fp32 C + C16

#define BKH 32
#define A_HS 40
#define T_HS 136
#define HG_STAGES 4

template<int TRANS_A>
__device__ __forceinline__ void h_fill(const __half* __restrict__ A, int lda,
                                       const __half* __restrict__ B, int ldb,
                                       int m0, int n0, int kof,
                                       uint32_t sa, uint32_t sb, int tid) {
    if (!TRANS_A) {
#pragma unroll
        for (int i = 0; i < 2; i++) {
            int lin = (i << 8) + tid;
            int row = lin >> 2, c = lin & 3;
            cp_async16(sa + (uint32_t)(row * A_HS + (c << 3)) * 2,
                       A + (size_t)(m0 + row) * lda + kof + (c << 3));
        }
    } else {
#pragma unroll
        for (int i = 0; i < 2; i++) {
            int lin = (i << 8) + tid;
            int row = lin >> 4, c = lin & 15;
            cp_async16(sa + (uint32_t)(row * T_HS + (c << 3)) * 2,
                       A + (size_t)(kof + row) * lda + m0 + (c << 3));
        }
    }
#pragma unroll
    for (int i = 0; i < 2; i++) {
        int lin = (i << 8) + tid;
        int row = lin >> 4, c = lin & 15;
        cp_async16(sb + (uint32_t)(row * T_HS + (c << 3)) * 2,
                   B + (size_t)(kof + row) * ldb + n0 + (c << 3));
    }
}

template<int TRANS_A, int ACT, int WF32, int WF16, int MODE>
__global__ __launch_bounds__(256, 2)
void hgemm_k(const __half* __restrict__ A, int lda, size_t sAs,
             const __half* __restrict__ B, int ldb, size_t sBs,
             float* __restrict__ C, __half* __restrict__ C16, int ldc, size_t sCs,
             const float* __restrict__ bias, int K,
             float* __restrict__ aux1, float* __restrict__ aux2)
{
    constexpr int ATILE_B = TRANS_A ? (BKH * T_HS * 2) : (128 * A_HS * 2);
    constexpr int STAGE_B = ATILE_B + BKH * T_HS * 2;

    extern __shared__ __half hsm[];
    uint32_t smb = smem_u32(hsm);
    int tid = threadIdx.x;
    int wid = tid >> 5, lane = tid & 31;
    int group = lane >> 3, lr = lane & 7;
    int g = lane >> 2, t4 = lane & 3;

    A += (size_t)blockIdx.z * sAs;
    B += (size_t)blockIdx.z * sBs;
    int m0 = blockIdx.y << 7;
    int n0 = blockIdx.x << 7;
    int wm = wid & 1, wn = wid >> 1;

    float c[4][4][4];
#pragma unroll
    for (int a = 0; a < 4; a++)
#pragma unroll
        for (int b = 0; b < 4; b++)
#pragma unroll
            for (int r = 0; r < 4; r++) c[a][b][r] = 0.f;

    int nk = K >> 5;

#pragma unroll
    for (int s = 0; s < HG_STAGES - 1; s++) {
        if (s < nk) {
            uint32_t sa = smb + (uint32_t)s * STAGE_B;
            h_fill<TRANS_A>(A, lda, B, ldb, m0, n0, s << 5, sa, sa + ATILE_B, tid);
        }
        asm volatile("cp.async.commit_group;");
    }

    for (int kt = 0; kt < nk; kt++) {
        asm volatile("cp.async.wait_group %0;" :: "n"(HG_STAGES - 2));
        __syncthreads();

        int nxt = kt + HG_STAGES - 1;
        if (nxt < nk) {
            uint32_t sa = smb + (uint32_t)(nxt & (HG_STAGES - 1)) * STAGE_B;
            h_fill<TRANS_A>(A, lda, B, ldb, m0, n0, nxt << 5, sa, sa + ATILE_B, tid);
        }
        asm volatile("cp.async.commit_group;");

        uint32_t sa = smb + (uint32_t)(kt & (HG_STAGES - 1)) * STAGE_B;
        uint32_t sb = sa + ATILE_B;
#pragma unroll
        for (int ks = 0; ks < 2; ks++) {
            uint32_t af[4][4];
#pragma unroll
            for (int mi = 0; mi < 4; mi++) {
                uint32_t addr;
                if (!TRANS_A) {
                    int arow = (wm << 6) + (mi << 4) + ((group & 1) << 3) + lr;
                    int acol = (ks << 4) + ((group >> 1) << 3);
                    addr = sa + (uint32_t)(arow * A_HS + acol) * 2;
                    ldsm_x4(af[mi], addr);
                } else {
                    int krow = (ks << 4) + ((group >> 1) << 3) + lr;
                    int mcol = (wm << 6) + (mi << 4) + ((group & 1) << 3);
                    addr = sa + (uint32_t)(krow * T_HS + mcol) * 2;
                    ldsm_x4_t(af[mi], addr);
                }
            }
            uint32_t bf[2][4];
#pragma unroll
            for (int np = 0; np < 2; np++) {
                int krow = (ks << 4) + ((group & 1) << 3) + lr;
                int ncol = (wn << 5) + (np << 4) + ((group >> 1) << 3);
                ldsm_x4_t(bf[np], sb + (uint32_t)(krow * T_HS + ncol) * 2);
            }
#pragma unroll
            for (int mi = 0; mi < 4; mi++)
#pragma unroll
                for (int ni = 0; ni < 4; ni++)
                    mma_f16(c[mi][ni], af[mi], &bf[ni >> 1][(ni & 1) << 1]);
        }
    }

    // ---- epilogue ----
    if (MODE == 2) __syncthreads();          // smem reused as logit stage
    float* stage = (float*)hsm;
    int auxrows = (int)(sCs / (size_t)ldc);  // rows-per-batch for aux indexing
    const float GK = 0.7071067811865476f;
    const float PSCALE = 0.21022410381342865f;   // 512^-0.25
    const float PS2    = 0.02209708691207961f;   // 0.5 * 512^-0.5
#pragma unroll
    for (int mi = 0; mi < 4; mi++) {
        int r = (wm << 6) + (mi << 4) + g;
        size_t rowoff0 = (size_t)blockIdx.z * sCs + (size_t)(m0 + r) * ldc;
        size_t rowoff1 = rowoff0 + (size_t)8 * ldc;
        int ar0 = blockIdx.z * auxrows + m0 + r;
        int ar1 = ar0 + 8;
        float n2a = 0.f, n2b = 0.f, iv0 = 0.f, iv1 = 0.f;
        if (MODE == 2) { n2a = aux1[ar0]; n2b = aux1[ar1]; }
        if (MODE == 3) { iv0 = aux1[ar0]; iv1 = aux1[ar1]; }
        float ssq0 = 0.f, ssq1 = 0.f;
#pragma unroll
        for (int ni = 0; ni < 4; ni++) {
            int nn = n0 + (wn << 5) + (ni << 3) + (t4 << 1);
            float v0 = c[mi][ni][0], v1 = c[mi][ni][1];
            float v2 = c[mi][ni][2], v3 = c[mi][ni][3];
            if (bias) {
                float b0 = __ldg(bias + nn), b1 = __ldg(bias + nn + 1);
                v0 += b0; v1 += b1; v2 += b0; v3 += b1;
            }
            if (ACT == 1) {
                v0 = 0.5f * v0 * (1.f + erff(v0 * GK));
                v1 = 0.5f * v1 * (1.f + erff(v1 * GK));
                v2 = 0.5f * v2 * (1.f + erff(v2 * GK));
                v3 = 0.5f * v3 * (1.f + erff(v3 * GK));
            }
            if (MODE == 1) {
                ssq0 += v0 * v0 + v1 * v1;
                ssq1 += v2 * v2 + v3 * v3;
            }
            if (MODE == 2) {
                v0 = fmaf(v0, PSCALE, -PS2 * n2a);
                v1 = fmaf(v1, PSCALE, -PS2 * n2a);
                v2 = fmaf(v2, PSCALE, -PS2 * n2b);
                v3 = fmaf(v3, PSCALE, -PS2 * n2b);
                stage[r * 132 + nn] = v0;       stage[r * 132 + nn + 1] = v1;
                stage[(r + 8) * 132 + nn] = v2; stage[(r + 8) * 132 + nn + 1] = v3;
            }
            if (MODE == 3) { v0 *= iv0; v1 *= iv0; v2 *= iv1; v3 *= iv1; }
            if (MODE == 4) {
                float2 r0 = *(float2*)(C + rowoff0 + nn);
                float2 r1 = *(float2*)(C + rowoff1 + nn);
                v0 += r0.x; v1 += r0.y; v2 += r1.x; v3 += r1.y;
            }
            if (WF32) {
                *(float2*)(C + rowoff0 + nn) = make_float2(v0, v1);
                *(float2*)(C + rowoff1 + nn) = make_float2(v2, v3);
            }
            if (WF16) {
                *(__half2*)(C16 + rowoff0 + nn) = __floats2half2_rn(v0, v1);
                *(__half2*)(C16 + rowoff1 + nn) = __floats2half2_rn(v2, v3);
            }
        }
        if (MODE == 1) {
            ssq0 += __shfl_xor_sync(0xffffffffu, ssq0, 1);
            ssq0 += __shfl_xor_sync(0xffffffffu, ssq0, 2);
            ssq1 += __shfl_xor_sync(0xffffffffu, ssq1, 1);
            ssq1 += __shfl_xor_sync(0xffffffffu, ssq1, 2);
            if (t4 == 0) {
                atomicAdd(&aux1[ar0], ssq0);
                atomicAdd(&aux1[ar1], ssq1);
            }
        }
    }
    if (MODE == 2) {
        __syncthreads();
        int rr = tid >> 1, hh = tid & 1;
        const float* rp = stage + rr * 132 + (hh << 6);
        float m = -INFINITY;
#pragma unroll
        for (int j = 0; j < 64; j++) m = fmaxf(m, rp[j]);
        m = fmaxf(m, __shfl_xor_sync(0xffffffffu, m, 1));
        if (hh == 0) aux2[m0 + rr] = m;
    }
}

// ================= fp32 fallback SGEMM (head only) =================
#define BM 128
#define BN 128
#define BK 8

template<int ACT>
__global__ __launch_bounds__(256)
void gemm_k(const float* __restrict__ A, int lda,
            const float* __restrict__ Bm, int ldb,
            float* __restrict__ C, int ldc,
            const float* __restrict__ bias,
            int M, int N, int K)
{
    int m0 = blockIdx.y * BM;
    int n0 = blockIdx.x * BN;

    __shared__ float As[BK][BM];
    __shared__ float Bs[BK][BN];

    int tid = threadIdx.x;
    int tx = tid & 15, ty = tid >> 4;

    float acc[8][8];
#pragma unroll
    for (int i = 0; i < 8; i++)
#pragma unroll
        for (int j = 0; j < 8; j++) acc[i][j] = 0.f;

    float ar[8], br[8];

    for (int k0 = 0; k0 < K; k0 += BK) {
        {
            int m  = tid >> 1;
            int kk = (tid & 1) * 4;
            bool mok = (m0 + m) < M;
            const float* src = A + (size_t)(m0 + m) * lda + k0 + kk;
#pragma unroll
            for (int i = 0; i < 4; i++)
                As[kk + i][m] = mok ? src[i] : 0.f;
        }
        {
            int k = tid >> 5;
            int n = (tid & 31) * 4;
            const float* src = Bm + (size_t)(k0 + k) * ldb + n0 + n;
#pragma unroll
            for (int i = 0; i < 4; i++) {
                float vv = 0.f;
                if (n0 + n + i < N) vv = src[i];
                Bs[k][n + i] = vv;
            }
        }
        __syncthreads();
#pragma unroll
        for (int k = 0; k < BK; k++) {
            *(float4*)&ar[0] = *(float4*)&As[k][ty * 4];
            *(float4*)&ar[4] = *(float4*)&As[k][64 + ty * 4];
            *(float4*)&br[0] = *(float4*)&Bs[k][tx * 4];
            *(float4*)&br[4] = *(float4*)&Bs[k][64 + tx * 4];
#pragma unroll
            for (int i = 0; i < 8; i++)
#pragma unroll
                for (int j = 0; j < 8; j++)
                    acc[i][j] = fmaf(ar[i], br[j], acc[i][j]);
        }
        __syncthreads();
    }

#pragma unroll
    for (int i = 0; i < 8; i++) {
        int m = m0 + ((i < 4) ? (ty * 4 + i) : (64 + ty * 4 + i - 4));
        if (m >= M) continue;
#pragma unroll
        for (int j = 0; j < 8; j++) {
            int n = n0 + ((j < 4) ? (tx * 4 + j) : (64 + tx * 4 + j - 4));
            if (n >= N) continue;
            float vv = acc[i][j];
            if (bias) vv += bias[n];
            if (ACT == 2) vv = fmaxf(vv, 0.f);
            C[(size_t)m * ldc + n] = vv;
        }
    }
}

// ---------------- elementwise / reduction kernels ---------------------------

__global__ void conv16_k(const float* __restrict__ in, __half* __restrict__ out, size_t n) {
    size_t i = ((size_t)blockIdx.x * 256 + threadIdx.x) * 4;
    if (i < n) {
        float4 v = *(const float4*)(in + i);
        *(__half2*)(out + i)     = __floats2half2_rn(v.x, v.y);
        *(__half2*)(out + i + 2) = __floats2half2_rn(v.z, v.w);
    }
}

__global__ void addpos_k(float* __restrict__ h, __half* __restrict__ h16,
                         const float* __restrict__ pos) {
    size_t i = (size_t)blockIdx.x * 256 + threadIdx.x;
    if (i < (size_t)ROWS * NE) {
        float v = h[i] + pos[i % ((size_t)NS * NE)];
        h[i] = v;
        h16[i] = __float2half_rn(v);
    }
}

__global__ void zero_k(float* p, int n) {
    int i = blockIdx.x * 256 + threadIdx.x;
    if (i < n) p[i] = 0.f;
}

__global__ void maxred_k(const float* __restrict__ part, int n, float* __restrict__ out) {
    __shared__ float sh[1024];
    int t = threadIdx.x;
    float m = -INFINITY;
    for (int i = t; i < n; i += 1024) m = fmaxf(m, part[i]);
    sh[t] = m; __syncthreads();
    for (int o = 512; o > 0; o >>= 1) { if (t < o) sh[t] = fmaxf(sh[t], sh[t + o]); __syncthreads(); }
    if (t == 0) out[0] = sh[0];
}

// per-batch max: block b reduces part[b*NS .. b*NS+NS)
__global__ void maxredB_k(const float* __restrict__ part, float* __restrict__ out) {
    __shared__ float sh[1024];
    int t = threadIdx.x, b = blockIdx.x;
    const float* p = part + (size_t)b * NS;
    float m = -INFINITY;
    for (int i = t; i < NS; i += 1024) m = fmaxf(m, p[i]);
    sh[t] = m; __syncthreads();
    for (int o = 512; o > 0; o >>= 1) { if (t < o) sh[t] = fmaxf(sh[t], sh[t + o]); __syncthreads(); }
    if (t == 0) out[b] = sh[0];
}

// pk path: fp32 = exp(l-gmax)/sqrt(M) (z/den path); fp16 = exp(l-batchmax)/sqrt(M)
__global__ void phiexp_pk_k(float* __restrict__ G, __half* __restrict__ G16,
                            const float* __restrict__ bmax,
                            const float* __restrict__ mx, size_t n) {
    size_t i = (size_t)blockIdx.x * 256 + threadIdx.x;
    if (i < n) {
        float l = G[i];
        float bm = bmax[i >> 19];    // NS*NM = 2^19 per batch
        G[i]  = expf(l - mx[0]) * 0.08838834764831845f;
        G16[i] = __float2half_rn(expf(l - bm) * 0.08838834764831845f);
    }
}

// pq path: fp32 = exp(l-gmax)/sqrt(M) (den); fp16 = exp(l-rowmax)/sqrt(M) (num)
__global__ void phiexp_pq_k(float* __restrict__ G, __half* __restrict__ G16,
                            const float* __restrict__ rowmax,
                            const float* __restrict__ mx, size_t n) {
    size_t i = (size_t)blockIdx.x * 256 + threadIdx.x;
    if (i < n) {
        float l = G[i];
        float rm = rowmax[i >> 7];   // NM = 128
        G[i]  = expf(l - mx[0]) * 0.08838834764831845f;
        G16[i] = __float2half_rn(expf(l - rm) * 0.08838834764831845f);
    }
}

__global__ void colsum_k(const float* __restrict__ pk, float* __restrict__ z) {
    int b = blockIdx.x, chunk = blockIdx.y, m = threadIdx.x;
    const float* p = pk + (size_t)b * NS * NM + (size_t)chunk * 128 * NM + m;
    float s = 0.f;
    for (int i = 0; i < 128; i++) s += p[(size_t)i * NM];
    atomicAdd(&z[b * NM + m], s);
}

// inv[row] = exp(rowq-mxq + bmk-mx) / (pq . z + 1e-6)
__global__ void den_k(const float* __restrict__ pq, const float* __restrict__ z,
                      const float* __restrict__ rowq, const float* __restrict__ mxq,
                      const float* __restrict__ bmk, const float* __restrict__ mxk,
                      float* __restrict__ inv) {
    int warp = threadIdx.x >> 5, lane = threadIdx.x & 31;
    int row = blockIdx.x * 8 + warp;
    int b = row / NS;
    const float* p  = pq + (size_t)row * NM;
    const float* zz = z + b * NM;
    float s = 0.f;
#pragma unroll
    for (int j = 0; j < 4; j++) s = fmaf(p[lane + 32 * j], zz[lane + 32 * j], s);
#pragma unroll
    for (int o = 16; o > 0; o >>= 1) s += __shfl_xor_sync(0xffffffffu, s, o);
    if (lane == 0) {
        float factor = expf((rowq[row] - mxq[0]) + (bmk[b] - mxk[0]));
        inv[row] = factor / (s + 1e-6f);
    }
}

// LayerNorm over E=512; writes fp16 only (consumer is FF1 GEMM)
__global__ void ln_k(const float* __restrict__ in, __half* __restrict__ out16,
                     const float* __restrict__ g, const float* __restrict__ b) {
    int row = blockIdx.x, t = threadIdx.x;
    __shared__ float sh[256];
    const float* a = in + (size_t)row * NE;
    float x0 = a[t], x1 = a[t + 256];
    sh[t] = x0 + x1; __syncthreads();
    for (int o = 128; o > 0; o >>= 1) { if (t < o) sh[t] += sh[t + o]; __syncthreads(); }
    float mu = sh[0] * (1.f / NE);
    __syncthreads();
    float d0 = x0 - mu, d1 = x1 - mu;
    sh[t] = d0 * d0 + d1 * d1; __syncthreads();
    for (int o = 128; o > 0; o >>= 1) { if (t < o) sh[t] += sh[t + o]; __syncthreads(); }
    float rstd = rsqrtf(sh[0] * (1.f / NE) + 1e-5f);
    out16[(size_t)row * NE + t]       = __float2half_rn(d0 * rstd * g[t] + b[t]);
    out16[(size_t)row * NE + t + 256] = __float2half_rn(d1 * rstd * g[t + 256] + b[t + 256]);
}

// ---------------- host-side dispatch ----------------------------------------

template<int TRANS_A, int ACT, int WF32, int WF16, int MODE>
static void hgemm(const __half* A, int lda, size_t sA,
                  const __half* Bm, int ldb, size_t sB,
                  float* C, __half* C16, int ldc, size_t sC,
                  const float* bias, int M, int N, int K, int batch,
                  float* aux1 = nullptr, float* aux2 = nullptr)
{
    constexpr int ATILE_B = TRANS_A ? (BKH * T_HS * 2) : (128 * A_HS * 2);
    constexpr int SMEM = HG_STAGES * (ATILE_B + BKH * T_HS * 2);
    cudaFuncSetAttribute(hgemm_k<TRANS_A, ACT, WF32, WF16, MODE>,
                         cudaFuncAttributeMaxDynamicSharedMemorySize, SMEM);
    dim3 grid(N >> 7, M >> 7, batch);
    hgemm_k<TRANS_A, ACT, WF32, WF16, MODE><<<grid, 256, SMEM>>>(
        A, lda, sA, Bm, ldb, sB, C, C16, ldc, sC, bias, K, aux1, aux2);
}

static void conv16(const float* in, __half* out, size_t n) {
    conv16_k<<<(unsigned)((n / 4 + 255) / 256), 256>>>(in, out, n);
}

extern "C" void kernel_launch(void* const* d_in, const int* in_sizes, int n_in,
                              void* d_out, int out_size)
{
    const float* x    = (const float*)d_in[0];
    const float* Wi   = (const float*)d_in[1];
    const float* bi   = (const float*)d_in[2];
    const float* pos  = (const float*)d_in[3];
    const float* Wq   = (const float*)d_in[4];
    const float* bq   = (const float*)d_in[5];
    const float* Wk   = (const float*)d_in[6];
    const float* bk   = (const float*)d_in[7];
    const float* Wv   = (const float*)d_in[8];
    const float* bv   = (const float*)d_in[9];
    const float* Wo   = (const float*)d_in[10];
    const float* bo   = (const float*)d_in[11];
    const float* R    = (const float*)d_in[12];
    const float* lng  = (const float*)d_in[13];
    const float* lnb  = (const float*)d_in[14];
    const float* W1   = (const float*)d_in[15];
    const float* b1   = (const float*)d_in[16];
    const float* W2   = (const float*)d_in[17];
    const float* b2   = (const float*)d_in[18];
    const float* Wr1  = (const float*)d_in[19];
    const float* br1  = (const float*)d_in[20];
    const float* Wr2  = (const float*)d_in[21];
    const float* br2  = (const float*)d_in[22];
    float* out = (float*)d_out;

    float *h,*k,*pq,*pk,*z,*part,*rowq,*nq,*nk,*inv,*mx,*mxq,*bmk,*r1;
    __half *h16,*q16,*k16,*v16,*pq16,*pk16,*kv16,*ff16,*x16;
    __half *wi16,*wq16,*wk16,*wv16,*wo16,*r16,*w116,*w216;
    cudaGetSymbolAddress((void**)&h,  g_h);
    cudaGetSymbolAddress((void**)&k,  g_k);
    cudaGetSymbolAddress((void**)&pq, g_pq);
    cudaGetSymbolAddress((void**)&pk, g_pk);
    cudaGetSymbolAddress((void**)&z,  g_z);
    cudaGetSymbolAddress((void**)&part, g_part);
    cudaGetSymbolAddress((void**)&rowq, g_rowq);
    cudaGetSymbolAddress((void**)&nq, g_nq);
    cudaGetSymbolAddress((void**)&nk, g_nk);
    cudaGetSymbolAddress((void**)&inv, g_inv);
    cudaGetSymbolAddress((void**)&mx, g_max);
    cudaGetSymbolAddress((void**)&mxq, g_maxq);
    cudaGetSymbolAddress((void**)&bmk, g_bmk);
    cudaGetSymbolAddress((void**)&r1, g_r1);
    cudaGetSymbolAddress((void**)&h16,  g_h16);
    cudaGetSymbolAddress((void**)&q16,  g_q16);
    cudaGetSymbolAddress((void**)&k16,  g_k16);
    cudaGetSymbolAddress((void**)&v16,  g_v16);
    cudaGetSymbolAddress((void**)&pq16, g_pq16);
    cudaGetSymbolAddress((void**)&pk16, g_pk16);
    cudaGetSymbolAddress((void**)&kv16, g_kv16);
    cudaGetSymbolAddress((void**)&ff16, g_ff16);
    cudaGetSymbolAddress((void**)&x16,  g_x16);
    cudaGetSymbolAddress((void**)&wi16, g_wi16);
    cudaGetSymbolAddress((void**)&wq16, g_wq16);
    cudaGetSymbolAddress((void**)&wk16, g_wk16);
    cudaGetSymbolAddress((void**)&wv16, g_wv16);
    cudaGetSymbolAddress((void**)&wo16, g_wo16);
    cudaGetSymbolAddress((void**)&r16,  g_r16);
    cudaGetSymbolAddress((void**)&w116, g_w116);
    cudaGetSymbolAddress((void**)&w216, g_w216);

    const size_t nHE = (size_t)ROWS * NE;
    const size_t nHM = (size_t)ROWS * NM;
    int ew_grid = (int)((nHE + 255) / 256);
    int pm_grid = (int)((nHM + 255) / 256);

    // ---- fp16 weight/input mirrors ----
    conv16(x,  x16, (size_t)ROWS * NDIN);
    conv16(Wi, wi16, (size_t)NDIN * NE);
    conv16(Wq, wq16, (size_t)NL * NE * NE);
    conv16(Wk, wk16, (size_t)NL * NE * NE);
    conv16(Wv, wv16, (size_t)NL * NE * NE);
    conv16(Wo, wo16, (size_t)NL * NE * NE);
    conv16(R,  r16,  (size_t)NL * NE * NM);
    conv16(W1, w116, (size_t)NL * NE * HID);
    conv16(W2, w216, (size_t)NL * HID * NE);

    // h = x @ Wi + bi ; then += pos (dual-write h16)
    hgemm<0,0,1,0,0>(x16, NDIN,0, wi16, NE,0, h, nullptr, NE,0, bi, ROWS, NE, NDIN, 1);
    addpos_k<<<ew_grid,256>>>(h, h16, pos);

    for (int i = 0; i < NL; i++) {
        const __half* wq_i = wq16 + (size_t)i*NE*NE;  const float* bq_i = bq + (size_t)i*NE;
        const __half* wk_i = wk16 + (size_t)i*NE*NE;  const float* bk_i = bk + (size_t)i*NE;
        const __half* wv_i = wv16 + (size_t)i*NE*NE;  const float* bv_i = bv + (size_t)i*NE;
        const __half* wo_i = wo16 + (size_t)i*NE*NE;  const float* bo_i = bo + (size_t)i*NE;
        const __half* r_i  = r16  + (size_t)i*NE*NM;
        const float* g_i  = lng + (size_t)i*NE;       const float* b_i  = lnb + (size_t)i*NE;
        const __half* w1_i = w116 + (size_t)i*NE*HID; const float* b1_i = b1 + (size_t)i*HID;
        const __half* w2_i = w216 + (size_t)i*HID*NE; const float* b2_i = b2 + (size_t)i*NE;

        // zero sumsq accumulators
        zero_k<<<ROWS/256,256>>>(nq, ROWS);
        zero_k<<<ROWS/256,256>>>(nk, ROWS);

        // projections: Q/K with fused per-row sumsq (fp16 out only), V plain
        hgemm<0,0,0,1,1>(h16, NE,0, wq_i, NE,0, nullptr, q16, NE,0, bq_i, ROWS, NE, NE, 1, nq);
        hgemm<0,0,0,1,1>(h16, NE,0, wk_i, NE,0, nullptr, k16, NE,0, bk_i, ROWS, NE, NE, 1, nk);
        hgemm<0,0,0,1,0>(h16, NE,0, wv_i, NE,0, nullptr, v16, NE,0, bv_i, ROWS, NE, NE, 1);

        // phi-q: fused logits + rowmax (fp32 logits in pq, rowmax in rowq)
        hgemm<0,0,1,0,2>(q16, NE,0, r_i, NM,0, pq, nullptr, NM,0, nullptr, ROWS, NM, NE, 1, nq, rowq);
        maxred_k<<<1,1024>>>(rowq, ROWS, mxq);
        phiexp_pq_k<<<pm_grid,256>>>(pq, pq16, rowq, mxq, nHM);

        // phi-k: fused logits + rowmax (rowmax in part)
        hgemm<0,0,1,0,2>(k16, NE,0, r_i, NM,0, pk, nullptr, NM,0, nullptr, ROWS, NM, NE, 1, nk, part);
        maxred_k<<<1,1024>>>(part, ROWS, mx);
        maxredB_k<<<NB,1024>>>(part, bmk);
        phiexp_pk_k<<<pm_grid,256>>>(pk, pk16, bmk, mx, nHM);

        // kv[b] = pk16[b]^T @ v16[b]   (batched, transA, batch-normalized)
        hgemm<1,0,0,1,0>(pk16, NM, (size_t)NS*NM, v16, NE, (size_t)NS*NE,
                         nullptr, kv16, NE, (size_t)NM*NE, nullptr, NM, NE, NS, NB);

        // z[b] = sum_s pk[b,s,:]  (fp32, gmax-normalized)
        zero_k<<<(NB*NM+255)/256,256>>>(z, NB*NM);
        colsum_k<<<dim3(NB,32),128>>>(pk, z);

        // inv[row] = factor / den  (precomputed before num GEMM)
        den_k<<<ROWS/8,256>>>(pq, z, rowq, mxq, bmk, mx, inv);

        // num GEMM with fused row scaling -> q16 directly
        hgemm<0,0,0,1,3>(pq16, NM, (size_t)NS*NM, kv16, NE, (size_t)NM*NE,
                         nullptr, q16, NE, (size_t)NS*NE, nullptr, NS, NE, NM, NB, inv);

        // a -> k (fp32, LN input)
        hgemm<0,0,1,0,0>(q16, NE,0, wo_i, NE,0, k, nullptr, NE,0, bo_i, ROWS, NE, NE, 1);

        // y -> v16 (LayerNorm, fp16 out)
        ln_k<<<ROWS,256>>>(k, v16, g_i, b_i);

        // ff1 = gelu(y @ W1 + b1) -> ff16
        hgemm<0,1,0,1,0>(v16, NE,0, w1_i, HID,0, nullptr, ff16, HID,0, b1_i, ROWS, HID, NE, 1);
        // ff2 with fused residual: h = ff2 + b2 + h ; dual-write h16
        hgemm<0,0,1,1,4>(ff16, HID,0, w2_i, NE,0, h, h16, NE,0, b2_i, ROWS, NE, HID, 1);
    }

    // head: pooled = h[:,0,:] (row stride S*E) — tiny, fp32 path
    {
        dim3 g1((256 + BN - 1) / BN, (NB + BM - 1) / BM);
        gemm_k<2><<<g1, 256>>>(h, NS*NE, Wr1, 256, r1, 256, br1, NB, 256, NE);
        dim3 g2(1, 1);
        gemm_k<0><<<g2, 256>>>(r1, 256, Wr2, 1, out, 1, br2, NB, 1, 256);
    }
}

// round 10
// speedup vs baseline: 7.4688x; 1.0023x over previous
#include <cuda_runtime.h>
#include <cuda_fp16.h>
#include <math.h>
#include <stdint.h>

#define NB 16
#define NS 4096
#define NDIN 64
#define NE 512
#define NM 128
#define NL 4
#define ROWS (NB*NS)        /* 65536 */
#define HID (4*NE)          /* 2048 */

// ---------------- scratch (device globals; no allocations allowed) ----------
__device__ float g_h [(size_t)ROWS*NE];
__device__ float g_k [(size_t)ROWS*NE];
__device__ float g_pk[(size_t)ROWS*NM];   // pk logits (fp32)
__device__ float g_z [NB*NM];
__device__ float g_part [ROWS];   // per-row max (pk pass)
__device__ float g_rowq [ROWS];   // per-row max for pq
__device__ float g_nq  [ROWS];    // per-row sum-of-squares (q)
__device__ float g_nk  [ROWS];    // per-row sum-of-squares (k)
__device__ float g_inv [ROWS];    // per-row 1/den factor
__device__ float g_max [1];       // global max (pk)
__device__ float g_maxq[1];       // global max (pq)
__device__ float g_bmk [NB];      // per-batch max (pk)
__device__ float g_r1[16*256];

// fp16 mirrors
__device__ __half g_h16 [(size_t)ROWS*NE];
__device__ __half g_q16 [(size_t)ROWS*NE];
__device__ __half g_k16 [(size_t)ROWS*NE];
__device__ __half g_v16 [(size_t)ROWS*NE];
__device__ __half g_pq16[(size_t)ROWS*NM];
__device__ __half g_pk16[(size_t)ROWS*NM];
__device__ __half g_kv16[(size_t)NB*NM*NE];
__device__ __half g_ff16[(size_t)ROWS*HID];
__device__ __half g_x16 [(size_t)ROWS*NDIN];
__device__ __half g_wi16[NDIN*NE];
__device__ __half g_wq16[(size_t)NL*NE*NE];
__device__ __half g_wk16[(size_t)NL*NE*NE];
__device__ __half g_wv16[(size_t)NL*NE*NE];
__device__ __half g_wo16[(size_t)NL*NE*NE];
__device__ __half g_r16 [(size_t)NL*NE*NM];
__device__ __half g_w116[(size_t)NL*NE*HID];
__device__ __half g_w216[(size_t)NL*HID*NE];

// ================= helpers =================
__device__ __forceinline__ uint32_t smem_u32(const void* p) {
    uint32_t r;
    asm("{ .reg .u64 t; cvta.to.shared.u64 t, %1; cvt.u32.u64 %0, t; }" : "=r"(r) : "l"(p));
    return r;
}
__device__ __forceinline__ void cp_async16(uint32_t saddr, const void* g) {
    asm volatile("cp.async.cg.shared.global [%0], [%1], 16;" :: "r"(saddr), "l"(g));
}
__device__ __forceinline__ void ldsm_x4(uint32_t r[4], uint32_t addr) {
    asm volatile("ldmatrix.sync.aligned.m8n8.x4.shared.b16 {%0,%1,%2,%3}, [%4];"
                 : "=r"(r[0]), "=r"(r[1]), "=r"(r[2]), "=r"(r[3]) : "r"(addr));
}
__device__ __forceinline__ void ldsm_x4_t(uint32_t r[4], uint32_t addr) {
    asm volatile("ldmatrix.sync.aligned.m8n8.x4.trans.shared.b16 {%0,%1,%2,%3}, [%4];"
                 : "=r"(r[0]), "=r"(r[1]), "=r"(r[2]), "=r"(r[3]) : "r"(addr));
}
__device__ __forceinline__ void mma_f16(float c[4], const uint32_t a[4], const uint32_t b[2]) {
    asm volatile(
        "mma.sync.aligned.m16n8k16.row.col.f32.f16.f16.f32 "
        "{%0,%1,%2,%3}, {%4,%5,%6,%7}, {%8,%9}, {%0,%1,%2,%3};"
        : "+f"(c[0]), "+f"(c[1]), "+f"(c[2]), "+f"(c[3])
        : "r"(a[0]), "r"(a[1]), "r"(a[2]), "r"(a[3]), "r"(b[0]), "r"(b[1]));
}

// ================= fp16 mma GEMM with fused epilogues =================
// MODE 0: plain (bias, ACT, WF32/WF16 writes)
// MODE 1: SUMSQ  — write C16; atomicAdd per-row sum of squares into aux1
// MODE 2: PHI    — logit = acc*SCALE - 0.5*scale2*aux1[row]; write fp32 C (logits);
//                  per-row max into aux2 (needs grid.x==1)
// MODE 3: SCALEROW — acc *= aux1[absrow]; write C16
// MODE 4: RESID  — acc += bias + C[row]; write fp32 C + C16
// MODE 5: PHIEXP — like MODE 2 but ALSO writes C16 = exp(logit - rowmax)/sqrt(M)
//                  directly (no fp32 C, no generic C16 write)

#define BKH 32
#define A_HS 40
#define T_HS 136
#define HG_STAGES 4

template<int TRANS_A>
__device__ __forceinline__ void h_fill(const __half* __restrict__ A, int lda,
                                       const __half* __restrict__ B, int ldb,
                                       int m0, int n0, int kof,
                                       uint32_t sa, uint32_t sb, int tid) {
    if (!TRANS_A) {
#pragma unroll
        for (int i = 0; i < 2; i++) {
            int lin = (i << 8) + tid;
            int row = lin >> 2, c = lin & 3;
            cp_async16(sa + (uint32_t)(row * A_HS + (c << 3)) * 2,
                       A + (size_t)(m0 + row) * lda + kof + (c << 3));
        }
    } else {
#pragma unroll
        for (int i = 0; i < 2; i++) {
            int lin = (i << 8) + tid;
            int row = lin >> 4, c = lin & 15;
            cp_async16(sa + (uint32_t)(row * T_HS + (c << 3)) * 2,
                       A + (size_t)(kof + row) * lda + m0 + (c << 3));
        }
    }
#pragma unroll
    for (int i = 0; i < 2; i++) {
        int lin = (i << 8) + tid;
        int row = lin >> 4, c = lin & 15;
        cp_async16(sb + (uint32_t)(row * T_HS + (c << 3)) * 2,
                   B + (size_t)(kof + row) * ldb + n0 + (c << 3));
    }
}

template<int TRANS_A, int ACT, int WF32, int WF16, int MODE>
__global__ __launch_bounds__(256, 2)
void hgemm_k(const __half* __restrict__ A, int lda, size_t sAs,
             const __half* __restrict__ B, int ldb, size_t sBs,
             float* __restrict__ C, __half* __restrict__ C16, int ldc, size_t sCs,
             const float* __restrict__ bias, int K,
             float* __restrict__ aux1, float* __restrict__ aux2)
{
    constexpr int ATILE_B = TRANS_A ? (BKH * T_HS * 2) : (128 * A_HS * 2);
    constexpr int STAGE_B = ATILE_B + BKH * T_HS * 2;

    extern __shared__ __half hsm[];
    uint32_t smb = smem_u32(hsm);
    int tid = threadIdx.x;
    int wid = tid >> 5, lane = tid & 31;
    int group = lane >> 3, lr = lane & 7;
    int g = lane >> 2, t4 = lane & 3;

    A += (size_t)blockIdx.z * sAs;
    B += (size_t)blockIdx.z * sBs;
    int m0 = blockIdx.y << 7;
    int n0 = blockIdx.x << 7;
    int wm = wid & 1, wn = wid >> 1;

    float c[4][4][4];
#pragma unroll
    for (int a = 0; a < 4; a++)
#pragma unroll
        for (int b = 0; b < 4; b++)
#pragma unroll
            for (int r = 0; r < 4; r++) c[a][b][r] = 0.f;

    int nk = K >> 5;

#pragma unroll
    for (int s = 0; s < HG_STAGES - 1; s++) {
        if (s < nk) {
            uint32_t sa = smb + (uint32_t)s * STAGE_B;
            h_fill<TRANS_A>(A, lda, B, ldb, m0, n0, s << 5, sa, sa + ATILE_B, tid);
        }
        asm volatile("cp.async.commit_group;");
    }

    for (int kt = 0; kt < nk; kt++) {
        asm volatile("cp.async.wait_group %0;" :: "n"(HG_STAGES - 2));
        __syncthreads();

        int nxt = kt + HG_STAGES - 1;
        if (nxt < nk) {
            uint32_t sa = smb + (uint32_t)(nxt & (HG_STAGES - 1)) * STAGE_B;
            h_fill<TRANS_A>(A, lda, B, ldb, m0, n0, nxt << 5, sa, sa + ATILE_B, tid);
        }
        asm volatile("cp.async.commit_group;");

        uint32_t sa = smb + (uint32_t)(kt & (HG_STAGES - 1)) * STAGE_B;
        uint32_t sb = sa + ATILE_B;
#pragma unroll
        for (int ks = 0; ks < 2; ks++) {
            uint32_t af[4][4];
#pragma unroll
            for (int mi = 0; mi < 4; mi++) {
                uint32_t addr;
                if (!TRANS_A) {
                    int arow = (wm << 6) + (mi << 4) + ((group & 1) << 3) + lr;
                    int acol = (ks << 4) + ((group >> 1) << 3);
                    addr = sa + (uint32_t)(arow * A_HS + acol) * 2;
                    ldsm_x4(af[mi], addr);
                } else {
                    int krow = (ks << 4) + ((group >> 1) << 3) + lr;
                    int mcol = (wm << 6) + (mi << 4) + ((group & 1) << 3);
                    addr = sa + (uint32_t)(krow * T_HS + mcol) * 2;
                    ldsm_x4_t(af[mi], addr);
                }
            }
            uint32_t bf[2][4];
#pragma unroll
            for (int np = 0; np < 2; np++) {
                int krow = (ks << 4) + ((group & 1) << 3) + lr;
                int ncol = (wn << 5) + (np << 4) + ((group >> 1) << 3);
                ldsm_x4_t(bf[np], sb + (uint32_t)(krow * T_HS + ncol) * 2);
            }
#pragma unroll
            for (int mi = 0; mi < 4; mi++)
#pragma unroll
                for (int ni = 0; ni < 4; ni++)
                    mma_f16(c[mi][ni], af[mi], &bf[ni >> 1][(ni & 1) << 1]);
        }
    }

    // ---- epilogue ----
    if (MODE == 2 || MODE == 5) __syncthreads();     // smem reused as logit stage
    float* stage = (float*)hsm;
    int auxrows = (int)(sCs / (size_t)ldc);  // rows-per-batch for aux indexing
    const float GK = 0.7071067811865476f;
    const float PSCALE = 0.21022410381342865f;   // 512^-0.25
    const float PS2    = 0.02209708691207961f;   // 0.5 * 512^-0.5
#pragma unroll
    for (int mi = 0; mi < 4; mi++) {
        int r = (wm << 6) + (mi << 4) + g;
        size_t rowoff0 = (size_t)blockIdx.z * sCs + (size_t)(m0 + r) * ldc;
        size_t rowoff1 = rowoff0 + (size_t)8 * ldc;
        int ar0 = blockIdx.z * auxrows + m0 + r;
        int ar1 = ar0 + 8;
        float n2a = 0.f, n2b = 0.f, iv0 = 0.f, iv1 = 0.f;
        if (MODE == 2 || MODE == 5) { n2a = aux1[ar0]; n2b = aux1[ar1]; }
        if (MODE == 3) { iv0 = aux1[ar0]; iv1 = aux1[ar1]; }
        float ssq0 = 0.f, ssq1 = 0.f;
#pragma unroll
        for (int ni = 0; ni < 4; ni++) {
            int nn = n0 + (wn << 5) + (ni << 3) + (t4 << 1);
            float v0 = c[mi][ni][0], v1 = c[mi][ni][1];
            float v2 = c[mi][ni][2], v3 = c[mi][ni][3];
            if (bias) {
                float b0 = __ldg(bias + nn), b1 = __ldg(bias + nn + 1);
                v0 += b0; v1 += b1; v2 += b0; v3 += b1;
            }
            if (ACT == 1) {
                v0 = 0.5f * v0 * (1.f + erff(v0 * GK));
                v1 = 0.5f * v1 * (1.f + erff(v1 * GK));
                v2 = 0.5f * v2 * (1.f + erff(v2 * GK));
                v3 = 0.5f * v3 * (1.f + erff(v3 * GK));
            }
            if (MODE == 1) {
                ssq0 += v0 * v0 + v1 * v1;
                ssq1 += v2 * v2 + v3 * v3;
            }
            if (MODE == 2 || MODE == 5) {
                v0 = fmaf(v0, PSCALE, -PS2 * n2a);
                v1 = fmaf(v1, PSCALE, -PS2 * n2a);
                v2 = fmaf(v2, PSCALE, -PS2 * n2b);
                v3 = fmaf(v3, PSCALE, -PS2 * n2b);
                stage[r * 132 + nn] = v0;       stage[r * 132 + nn + 1] = v1;
                stage[(r + 8) * 132 + nn] = v2; stage[(r + 8) * 132 + nn + 1] = v3;
            }
            if (MODE == 3) { v0 *= iv0; v1 *= iv0; v2 *= iv1; v3 *= iv1; }
            if (MODE == 4) {
                float2 r0 = *(float2*)(C + rowoff0 + nn);
                float2 r1 = *(float2*)(C + rowoff1 + nn);
                v0 += r0.x; v1 += r0.y; v2 += r1.x; v3 += r1.y;
            }
            if (WF32) {
                *(float2*)(C + rowoff0 + nn) = make_float2(v0, v1);
                *(float2*)(C + rowoff1 + nn) = make_float2(v2, v3);
            }
            if (WF16) {
                *(__half2*)(C16 + rowoff0 + nn) = __floats2half2_rn(v0, v1);
                *(__half2*)(C16 + rowoff1 + nn) = __floats2half2_rn(v2, v3);
            }
        }
        if (MODE == 1) {
            ssq0 += __shfl_xor_sync(0xffffffffu, ssq0, 1);
            ssq0 += __shfl_xor_sync(0xffffffffu, ssq0, 2);
            ssq1 += __shfl_xor_sync(0xffffffffu, ssq1, 1);
            ssq1 += __shfl_xor_sync(0xffffffffu, ssq1, 2);
            if (t4 == 0) {
                atomicAdd(&aux1[ar0], ssq0);
                atomicAdd(&aux1[ar1], ssq1);
            }
        }
    }
    if (MODE == 2 || MODE == 5) {
        __syncthreads();
        int rr = tid >> 1, hh = tid & 1;
        const float* rp = stage + rr * 132 + (hh << 6);
        float m = -INFINITY;
#pragma unroll
        for (int j = 0; j < 64; j++) m = fmaxf(m, rp[j]);
        m = fmaxf(m, __shfl_xor_sync(0xffffffffu, m, 1));   // both lanes hold full row max
        if (hh == 0) aux2[m0 + rr] = m;
        if (MODE == 5) {
            // write pq16 = exp(logit - rowmax) / sqrt(M) directly
            __half* dst = C16 + (size_t)(m0 + rr) * ldc + (hh << 6);
#pragma unroll
            for (int j = 0; j < 64; j += 2) {
                float e0 = expf(rp[j]     - m) * 0.08838834764831845f;
                float e1 = expf(rp[j + 1] - m) * 0.08838834764831845f;
                *(__half2*)(dst + j) = __floats2half2_rn(e0, e1);
            }
        }
    }
}

// ================= fp32 fallback SGEMM (head only) =================
#define BM 128
#define BN 128
#define BK 8

template<int ACT>
__global__ __launch_bounds__(256)
void gemm_k(const float* __restrict__ A, int lda,
            const float* __restrict__ Bm, int ldb,
            float* __restrict__ C, int ldc,
            const float* __restrict__ bias,
            int M, int N, int K)
{
    int m0 = blockIdx.y * BM;
    int n0 = blockIdx.x * BN;

    __shared__ float As[BK][BM];
    __shared__ float Bs[BK][BN];

    int tid = threadIdx.x;
    int tx = tid & 15, ty = tid >> 4;

    float acc[8][8];
#pragma unroll
    for (int i = 0; i < 8; i++)
#pragma unroll
        for (int j = 0; j < 8; j++) acc[i][j] = 0.f;

    float ar[8], br[8];

    for (int k0 = 0; k0 < K; k0 += BK) {
        {
            int m  = tid >> 1;
            int kk = (tid & 1) * 4;
            bool mok = (m0 + m) < M;
            const float* src = A + (size_t)(m0 + m) * lda + k0 + kk;
#pragma unroll
            for (int i = 0; i < 4; i++)
                As[kk + i][m] = mok ? src[i] : 0.f;
        }
        {
            int k = tid >> 5;
            int n = (tid & 31) * 4;
            const float* src = Bm + (size_t)(k0 + k) * ldb + n0 + n;
#pragma unroll
            for (int i = 0; i < 4; i++) {
                float vv = 0.f;
                if (n0 + n + i < N) vv = src[i];
                Bs[k][n + i] = vv;
            }
        }
        __syncthreads();
#pragma unroll
        for (int k = 0; k < BK; k++) {
            *(float4*)&ar[0] = *(float4*)&As[k][ty * 4];
            *(float4*)&ar[4] = *(float4*)&As[k][64 + ty * 4];
            *(float4*)&br[0] = *(float4*)&Bs[k][tx * 4];
            *(float4*)&br[4] = *(float4*)&Bs[k][64 + tx * 4];
#pragma unroll
            for (int i = 0; i < 8; i++)
#pragma unroll
                for (int j = 0; j < 8; j++)
                    acc[i][j] = fmaf(ar[i], br[j], acc[i][j]);
        }
        __syncthreads();
    }

#pragma unroll
    for (int i = 0; i < 8; i++) {
        int m = m0 + ((i < 4) ? (ty * 4 + i) : (64 + ty * 4 + i - 4));
        if (m >= M) continue;
#pragma unroll
        for (int j = 0; j < 8; j++) {
            int n = n0 + ((j < 4) ? (tx * 4 + j) : (64 + tx * 4 + j - 4));
            if (n >= N) continue;
            float vv = acc[i][j];
            if (bias) vv += bias[n];
            if (ACT == 2) vv = fmaxf(vv, 0.f);
            C[(size_t)m * ldc + n] = vv;
        }
    }
}

// ---------------- elementwise / reduction kernels ---------------------------

__global__ void conv16_k(const float* __restrict__ in, __half* __restrict__ out, size_t n) {
    size_t i = ((size_t)blockIdx.x * 256 + threadIdx.x) * 4;
    if (i < n) {
        float4 v = *(const float4*)(in + i);
        *(__half2*)(out + i)     = __floats2half2_rn(v.x, v.y);
        *(__half2*)(out + i + 2) = __floats2half2_rn(v.z, v.w);
    }
}

__global__ void addpos_k(float* __restrict__ h, __half* __restrict__ h16,
                         const float* __restrict__ pos) {
    size_t i = (size_t)blockIdx.x * 256 + threadIdx.x;
    if (i < (size_t)ROWS * NE) {
        float v = h[i] + pos[i % ((size_t)NS * NE)];
        h[i] = v;
        h16[i] = __float2half_rn(v);
    }
}

__global__ void zero_k(float* p, int n) {
    int i = blockIdx.x * 256 + threadIdx.x;
    if (i < n) p[i] = 0.f;
}

__global__ void maxred_k(const float* __restrict__ part, int n, float* __restrict__ out) {
    __shared__ float sh[1024];
    int t = threadIdx.x;
    float m = -INFINITY;
    for (int i = t; i < n; i += 1024) m = fmaxf(m, part[i]);
    sh[t] = m; __syncthreads();
    for (int o = 512; o > 0; o >>= 1) { if (t < o) sh[t] = fmaxf(sh[t], sh[t + o]); __syncthreads(); }
    if (t == 0) out[0] = sh[0];
}

// per-batch max: block b reduces part[b*NS .. b*NS+NS)
__global__ void maxredB_k(const float* __restrict__ part, float* __restrict__ out) {
    __shared__ float sh[1024];
    int t = threadIdx.x, b = blockIdx.x;
    const float* p = part + (size_t)b * NS;
    float m = -INFINITY;
    for (int i = t; i < NS; i += 1024) m = fmaxf(m, p[i]);
    sh[t] = m; __syncthreads();
    for (int o = 512; o > 0; o >>= 1) { if (t < o) sh[t] = fmaxf(sh[t], sh[t + o]); __syncthreads(); }
    if (t == 0) out[b] = sh[0];
}

// pk: read fp32 logits, write fp16 exp(l - batchmax)/sqrt(M) ONLY
__global__ void phiexp_pk_k(const float* __restrict__ G, __half* __restrict__ G16,
                            const float* __restrict__ bmax, size_t n) {
    size_t i = (size_t)blockIdx.x * 256 + threadIdx.x;
    if (i < n) {
        float bm = bmax[i >> 19];    // NS*NM = 2^19 per batch
        G16[i] = __float2half_rn(expf(G[i] - bm) * 0.08838834764831845f);
    }
}

// z'[b,m] = sum_s pk16[b,s,m]  (fp16 reads, fp32 accum)
__global__ void colsum16_k(const __half* __restrict__ pk16, float* __restrict__ z) {
    int b = blockIdx.x, chunk = blockIdx.y, m = threadIdx.x;
    const __half* p = pk16 + (size_t)b * NS * NM + (size_t)chunk * 128 * NM + m;
    float s = 0.f;
    for (int i = 0; i < 128; i++) s += __half2float(p[(size_t)i * NM]);
    atomicAdd(&z[b * NM + m], s);
}

// inv[row] = G / (G*s + 1e-6),  G = exp(rowq-mxq + bmk-mx),  s = pq16 . z'
__global__ void den_k(const __half* __restrict__ pq16, const float* __restrict__ z,
                      const float* __restrict__ rowq, const float* __restrict__ mxq,
                      const float* __restrict__ bmk, const float* __restrict__ mxk,
                      float* __restrict__ inv) {
    int warp = threadIdx.x >> 5, lane = threadIdx.x & 31;
    int row = blockIdx.x * 8 + warp;
    int b = row / NS;
    const __half* p = pq16 + (size_t)row * NM;
    const float* zz = z + b * NM;
    float s = 0.f;
#pragma unroll
    for (int j = 0; j < 4; j++)
        s = fmaf(__half2float(p[lane + 32 * j]), zz[lane + 32 * j], s);
#pragma unroll
    for (int o = 16; o > 0; o >>= 1) s += __shfl_xor_sync(0xffffffffu, s, o);
    if (lane == 0) {
        float G = expf((rowq[row] - mxq[0]) + (bmk[b] - mxk[0]));
        inv[row] = G / (fmaf(G, s, 1e-6f));
    }
}

// LayerNorm over E=512; writes fp16 only (consumer is FF1 GEMM)
__global__ void ln_k(const float* __restrict__ in, __half* __restrict__ out16,
                     const float* __restrict__ g, const float* __restrict__ b) {
    int row = blockIdx.x, t = threadIdx.x;
    __shared__ float sh[256];
    const float* a = in + (size_t)row * NE;
    float x0 = a[t], x1 = a[t + 256];
    sh[t] = x0 + x1; __syncthreads();
    for (int o = 128; o > 0; o >>= 1) { if (t < o) sh[t] += sh[t + o]; __syncthreads(); }
    float mu = sh[0] * (1.f / NE);
    __syncthreads();
    float d0 = x0 - mu, d1 = x1 - mu;
    sh[t] = d0 * d0 + d1 * d1; __syncthreads();
    for (int o = 128; o > 0; o >>= 1) { if (t < o) sh[t] += sh[t + o]; __syncthreads(); }
    float rstd = rsqrtf(sh[0] * (1.f / NE) + 1e-5f);
    out16[(size_t)row * NE + t]       = __float2half_rn(d0 * rstd * g[t] + b[t]);
    out16[(size_t)row * NE + t + 256] = __float2half_rn(d1 * rstd * g[t + 256] + b[t + 256]);
}

// ---------------- host-side dispatch ----------------------------------------

template<int TRANS_A, int ACT, int WF32, int WF16, int MODE>
static void hgemm(const __half* A, int lda, size_t sA,
                  const __half* Bm, int ldb, size_t sB,
                  float* C, __half* C16, int ldc, size_t sC,
                  const float* bias, int M, int N, int K, int batch,
                  float* aux1 = nullptr, float* aux2 = nullptr)
{
    constexpr int ATILE_B = TRANS_A ? (BKH * T_HS * 2) : (128 * A_HS * 2);
    constexpr int SMEM = HG_STAGES * (ATILE_B + BKH * T_HS * 2);
    cudaFuncSetAttribute(hgemm_k<TRANS_A, ACT, WF32, WF16, MODE>,
                         cudaFuncAttributeMaxDynamicSharedMemorySize, SMEM);
    dim3 grid(N >> 7, M >> 7, batch);
    hgemm_k<TRANS_A, ACT, WF32, WF16, MODE><<<grid, 256, SMEM>>>(
        A, lda, sA, Bm, ldb, sB, C, C16, ldc, sC, bias, K, aux1, aux2);
}

static void conv16(const float* in, __half* out, size_t n) {
    conv16_k<<<(unsigned)((n / 4 + 255) / 256), 256>>>(in, out, n);
}

extern "C" void kernel_launch(void* const* d_in, const int* in_sizes, int n_in,
                              void* d_out, int out_size)
{
    const float* x    = (const float*)d_in[0];
    const float* Wi   = (const float*)d_in[1];
    const float* bi   = (const float*)d_in[2];
    const float* pos  = (const float*)d_in[3];
    const float* Wq   = (const float*)d_in[4];
    const float* bq   = (const float*)d_in[5];
    const float* Wk   = (const float*)d_in[6];
    const float* bk   = (const float*)d_in[7];
    const float* Wv   = (const float*)d_in[8];
    const float* bv   = (const float*)d_in[9];
    const float* Wo   = (const float*)d_in[10];
    const float* bo   = (const float*)d_in[11];
    const float* R    = (const float*)d_in[12];
    const float* lng  = (const float*)d_in[13];
    const float* lnb  = (const float*)d_in[14];
    const float* W1   = (const float*)d_in[15];
    const float* b1   = (const float*)d_in[16];
    const float* W2   = (const float*)d_in[17];
    const float* b2   = (const float*)d_in[18];
    const float* Wr1  = (const float*)d_in[19];
    const float* br1  = (const float*)d_in[20];
    const float* Wr2  = (const float*)d_in[21];
    const float* br2  = (const float*)d_in[22];
    float* out = (float*)d_out;

    float *h,*k,*pk,*z,*part,*rowq,*nq,*nk,*inv,*mx,*mxq,*bmk,*r1;
    __half *h16,*q16,*k16,*v16,*pq16,*pk16,*kv16,*ff16,*x16;
    __half *wi16,*wq16,*wk16,*wv16,*wo16,*r16,*w116,*w216;
    cudaGetSymbolAddress((void**)&h,  g_h);
    cudaGetSymbolAddress((void**)&k,  g_k);
    cudaGetSymbolAddress((void**)&pk, g_pk);
    cudaGetSymbolAddress((void**)&z,  g_z);
    cudaGetSymbolAddress((void**)&part, g_part);
    cudaGetSymbolAddress((void**)&rowq, g_rowq);
    cudaGetSymbolAddress((void**)&nq, g_nq);
    cudaGetSymbolAddress((void**)&nk, g_nk);
    cudaGetSymbolAddress((void**)&inv, g_inv);
    cudaGetSymbolAddress((void**)&mx, g_max);
    cudaGetSymbolAddress((void**)&mxq, g_maxq);
    cudaGetSymbolAddress((void**)&bmk, g_bmk);
    cudaGetSymbolAddress((void**)&r1, g_r1);
    cudaGetSymbolAddress((void**)&h16,  g_h16);
    cudaGetSymbolAddress((void**)&q16,  g_q16);
    cudaGetSymbolAddress((void**)&k16,  g_k16);
    cudaGetSymbolAddress((void**)&v16,  g_v16);
    cudaGetSymbolAddress((void**)&pq16, g_pq16);
    cudaGetSymbolAddress((void**)&pk16, g_pk16);
    cudaGetSymbolAddress((void**)&kv16, g_kv16);
    cudaGetSymbolAddress((void**)&ff16, g_ff16);
    cudaGetSymbolAddress((void**)&x16,  g_x16);
    cudaGetSymbolAddress((void**)&wi16, g_wi16);
    cudaGetSymbolAddress((void**)&wq16, g_wq16);
    cudaGetSymbolAddress((void**)&wk16, g_wk16);
    cudaGetSymbolAddress((void**)&wv16, g_wv16);
    cudaGetSymbolAddress((void**)&wo16, g_wo16);
    cudaGetSymbolAddress((void**)&r16,  g_r16);
    cudaGetSymbolAddress((void**)&w116, g_w116);
    cudaGetSymbolAddress((void**)&w216, g_w216);

    const size_t nHE = (size_t)ROWS * NE;
    const size_t nHM = (size_t)ROWS * NM;
    int ew_grid = (int)((nHE + 255) / 256);
    int pm_grid = (int)((nHM + 255) / 256);

    // ---- fp16 weight/input mirrors ----
    conv16(x,  x16, (size_t)ROWS * NDIN);
    conv16(Wi, wi16, (size_t)NDIN * NE);
    conv16(Wq, wq16, (size_t)NL * NE * NE);
    conv16(Wk, wk16, (size_t)NL * NE * NE);
    conv16(Wv, wv16, (size_t)NL * NE * NE);
    conv16(Wo, wo16, (size_t)NL * NE * NE);
    conv16(R,  r16,  (size_t)NL * NE * NM);
    conv16(W1, w116, (size_t)NL * NE * HID);
    conv16(W2, w216, (size_t)NL * HID * NE);

    // h = x @ Wi + bi ; then += pos (dual-write h16)
    hgemm<0,0,1,0,0>(x16, NDIN,0, wi16, NE,0, h, nullptr, NE,0, bi, ROWS, NE, NDIN, 1);
    addpos_k<<<ew_grid,256>>>(h, h16, pos);

    for (int i = 0; i < NL; i++) {
        const __half* wq_i = wq16 + (size_t)i*NE*NE;  const float* bq_i = bq + (size_t)i*NE;
        const __half* wk_i = wk16 + (size_t)i*NE*NE;  const float* bk_i = bk + (size_t)i*NE;
        const __half* wv_i = wv16 + (size_t)i*NE*NE;  const float* bv_i = bv + (size_t)i*NE;
        const __half* wo_i = wo16 + (size_t)i*NE*NE;  const float* bo_i = bo + (size_t)i*NE;
        const __half* r_i  = r16  + (size_t)i*NE*NM;
        const float* g_i  = lng + (size_t)i*NE;       const float* b_i  = lnb + (size_t)i*NE;
        const __half* w1_i = w116 + (size_t)i*NE*HID; const float* b1_i = b1 + (size_t)i*HID;
        const __half* w2_i = w216 + (size_t)i*HID*NE; const float* b2_i = b2 + (size_t)i*NE;

        // zero sumsq accumulators
        zero_k<<<ROWS/256,256>>>(nq, ROWS);
        zero_k<<<ROWS/256,256>>>(nk, ROWS);

        // projections: Q/K with fused per-row sumsq (fp16 out only), V plain
        hgemm<0,0,0,1,1>(h16, NE,0, wq_i, NE,0, nullptr, q16, NE,0, bq_i, ROWS, NE, NE, 1, nq);
        hgemm<0,0,0,1,1>(h16, NE,0, wk_i, NE,0, nullptr, k16, NE,0, bk_i, ROWS, NE, NE, 1, nk);
        hgemm<0,0,0,1,0>(h16, NE,0, wv_i, NE,0, nullptr, v16, NE,0, bv_i, ROWS, NE, NE, 1);

        // phi-q FULLY FUSED: logits + rowmax + exp -> pq16 (row-normalized); rowmax -> rowq
        hgemm<0,0,0,0,5>(q16, NE,0, r_i, NM,0, nullptr, pq16, NM,0, nullptr, ROWS, NM, NE, 1, nq, rowq);
        maxred_k<<<1,1024>>>(rowq, ROWS, mxq);

        // phi-k: fused logits + rowmax (logits fp32 in pk, rowmax in part)
        hgemm<0,0,1,0,2>(k16, NE,0, r_i, NM,0, pk, nullptr, NM,0, nullptr, ROWS, NM, NE, 1, nk, part);
        maxred_k<<<1,1024>>>(part, ROWS, mx);
        maxredB_k<<<NB,1024>>>(part, bmk);
        phiexp_pk_k<<<pm_grid,256>>>(pk, pk16, bmk, nHM);

        // kv[b] = pk16[b]^T @ v16[b]   (batched, transA, batch-normalized)
        hgemm<1,0,0,1,0>(pk16, NM, (size_t)NS*NM, v16, NE, (size_t)NS*NE,
                         nullptr, kv16, NE, (size_t)NM*NE, nullptr, NM, NE, NS, NB);

        // z'[b] = sum_s pk16[b,s,:]  (batch-normalized colsums)
        zero_k<<<(NB*NM+255)/256,256>>>(z, NB*NM);
        colsum16_k<<<dim3(NB,32),128>>>(pk16, z);

        // inv[row] = G / (G*(pq16.z') + 1e-6)
        den_k<<<ROWS/8,256>>>(pq16, z, rowq, mxq, bmk, mx, inv);

        // num GEMM with fused row scaling -> q16 directly
        hgemm<0,0,0,1,3>(pq16, NM, (size_t)NS*NM, kv16, NE, (size_t)NM*NE,
                         nullptr, q16, NE, (size_t)NS*NE, nullptr, NS, NE, NM, NB, inv);

        // a -> k (fp32, LN input)
        hgemm<0,0,1,0,0>(q16, NE,0, wo_i, NE,0, k, nullptr, NE,0, bo_i, ROWS, NE, NE, 1);

        // y -> v16 (LayerNorm, fp16 out)
        ln_k<<<ROWS,256>>>(k, v16, g_i, b_i);

        // ff1 = gelu(y @ W1 + b1) -> ff16
        hgemm<0,1,0,1,0>(v16, NE,0, w1_i, HID,0, nullptr, ff16, HID,0, b1_i, ROWS, HID, NE, 1);
        // ff2 with fused residual: h = ff2 + b2 + h ; dual-write h16
        hgemm<0,0,1,1,4>(ff16, HID,0, w2_i, NE,0, h, h16, NE,0, b2_i, ROWS, NE, HID, 1);
    }

    // head: pooled = h[:,0,:] (row stride S*E) — tiny, fp32 path
    {
        dim3 g1((256 + BN - 1) / BN, (NB + BM - 1) / BM);
        gemm_k<2><<<g1, 256>>>(h, NS*NE, Wr1, 256, r1, 256, br1, NB, 256, NE);
        dim3 g2(1, 1);
        gemm_k<0><<<g2, 256>>>(r1, 256, Wr2, 1, out, 1, br2, NB, 1, 256);
    }
}

// round 11
// speedup vs baseline: 8.0905x; 1.0832x over previous
#include <cuda_runtime.h>
#include <cuda_fp16.h>
#include <math.h>
#include <stdint.h>

#define NB 16
#define NS 4096
#define NDIN 64
#define NE 512
#define NM 128
#define NL 4
#define ROWS (NB*NS)        /* 65536 */
#define HID (4*NE)          /* 2048 */

// ---------------- scratch (device globals; no allocations allowed) ----------
__device__ float g_h [(size_t)ROWS*NE];
__device__ float g_k [(size_t)ROWS*NE];
__device__ float g_pk[(size_t)ROWS*NM];   // pk logits (fp32)
__device__ float g_z [NB*NM];
__device__ float g_part [ROWS];   // per-row max (pk pass)
__device__ float g_rowq [ROWS];   // per-row max for pq
__device__ float g_nq  [ROWS];    // per-row sum-of-squares (q)
__device__ float g_nk  [ROWS];    // per-row sum-of-squares (k)
__device__ float g_inv [ROWS];    // per-row 1/den factor
__device__ float g_max [1];       // global max (pk)
__device__ float g_maxq[1];       // global max (pq)
__device__ float g_bmk [NB];      // per-batch max (pk)
__device__ float g_r1[16*256];

// fp16 mirrors
__device__ __half g_h16 [(size_t)ROWS*NE];
__device__ __half g_q16 [(size_t)ROWS*NE];
__device__ __half g_k16 [(size_t)ROWS*NE];
__device__ __half g_v16 [(size_t)ROWS*NE];
__device__ __half g_pq16[(size_t)ROWS*NM];
__device__ __half g_pk16[(size_t)ROWS*NM];
__device__ __half g_kv16[(size_t)NB*NM*NE];
__device__ __half g_ff16[(size_t)ROWS*HID];
__device__ __half g_x16 [(size_t)ROWS*NDIN];
__device__ __half g_wi16[NDIN*NE];
__device__ __half g_wq16[(size_t)NL*NE*NE];
__device__ __half g_wk16[(size_t)NL*NE*NE];
__device__ __half g_wv16[(size_t)NL*NE*NE];
__device__ __half g_wo16[(size_t)NL*NE*NE];
__device__ __half g_r16 [(size_t)NL*NE*NM];
__device__ __half g_w116[(size_t)NL*NE*HID];
__device__ __half g_w216[(size_t)NL*HID*NE];

// ================= helpers =================
__device__ __forceinline__ uint32_t smem_u32(const void* p) {
    uint32_t r;
    asm("{ .reg .u64 t; cvta.to.shared.u64 t, %1; cvt.u32.u64 %0, t; }" : "=r"(r) : "l"(p));
    return r;
}
__device__ __forceinline__ void cp_async16(uint32_t saddr, const void* g) {
    asm volatile("cp.async.cg.shared.global [%0], [%1], 16;" :: "r"(saddr), "l"(g));
}
__device__ __forceinline__ void ldsm_x4(uint32_t r[4], uint32_t addr) {
    asm volatile("ldmatrix.sync.aligned.m8n8.x4.shared.b16 {%0,%1,%2,%3}, [%4];"
                 : "=r"(r[0]), "=r"(r[1]), "=r"(r[2]), "=r"(r[3]) : "r"(addr));
}
__device__ __forceinline__ void ldsm_x4_t(uint32_t r[4], uint32_t addr) {
    asm volatile("ldmatrix.sync.aligned.m8n8.x4.trans.shared.b16 {%0,%1,%2,%3}, [%4];"
                 : "=r"(r[0]), "=r"(r[1]), "=r"(r[2]), "=r"(r[3]) : "r"(addr));
}
__device__ __forceinline__ void mma_f16(float c[4], const uint32_t a[4], const uint32_t b[2]) {
    asm volatile(
        "mma.sync.aligned.m16n8k16.row.col.f32.f16.f16.f32 "
        "{%0,%1,%2,%3}, {%4,%5,%6,%7}, {%8,%9}, {%0,%1,%2,%3};"
        : "+f"(c[0]), "+f"(c[1]), "+f"(c[2]), "+f"(c[3])
        : "r"(a[0]), "r"(a[1]), "r"(a[2]), "r"(a[3]), "r"(b[0]), "r"(b[1]));
}

// ================= fp16 mma GEMM with fused epilogues =================
// 128 threads / 4 warps; CTA tile 128x128; warp tile 64x64 (2x2 warps).
// MODE 0: plain (bias, ACT, WF32/WF16 writes)
// MODE 1: SUMSQ  — write C16; atomicAdd per-row sum of squares into aux1
// MODE 2: PHI    — logit = acc*SCALE - 0.5*scale2*aux1[row]; write fp32 C (logits);
//                  per-row max into aux2 (needs grid.x==1)
// MODE 3: SCALEROW — acc *= aux1[absrow]; write C16
// MODE 4: RESID  — acc += bias + C[row]; write fp32 C + C16
// MODE 5: PHIEXP — like MODE 2 but writes C16 = exp(logit - rowmax)/sqrt(M) directly

#define BKH 32
#define A_HS 40
#define T_HS 136
#define HG_STAGES 4

template<int TRANS_A>
__device__ __forceinline__ void h_fill(const __half* __restrict__ A, int lda,
                                       const __half* __restrict__ B, int ldb,
                                       int m0, int n0, int kof,
                                       uint32_t sa, uint32_t sb, int tid) {
    if (!TRANS_A) {
#pragma unroll
        for (int i = 0; i < 4; i++) {
            int lin = (i << 7) + tid;
            int row = lin >> 2, c = lin & 3;
            cp_async16(sa + (uint32_t)(row * A_HS + (c << 3)) * 2,
                       A + (size_t)(m0 + row) * lda + kof + (c << 3));
        }
    } else {
#pragma unroll
        for (int i = 0; i < 4; i++) {
            int lin = (i << 7) + tid;
            int row = lin >> 4, c = lin & 15;
            cp_async16(sa + (uint32_t)(row * T_HS + (c << 3)) * 2,
                       A + (size_t)(kof + row) * lda + m0 + (c << 3));
        }
    }
#pragma unroll
    for (int i = 0; i < 4; i++) {
        int lin = (i << 7) + tid;
        int row = lin >> 4, c = lin & 15;
        cp_async16(sb + (uint32_t)(row * T_HS + (c << 3)) * 2,
                   B + (size_t)(kof + row) * ldb + n0 + (c << 3));
    }
}

template<int TRANS_A, int ACT, int WF32, int WF16, int MODE>
__global__ __launch_bounds__(128, 2)
void hgemm_k(const __half* __restrict__ A, int lda, size_t sAs,
             const __half* __restrict__ B, int ldb, size_t sBs,
             float* __restrict__ C, __half* __restrict__ C16, int ldc, size_t sCs,
             const float* __restrict__ bias, int K,
             float* __restrict__ aux1, float* __restrict__ aux2)
{
    constexpr int ATILE_B = TRANS_A ? (BKH * T_HS * 2) : (128 * A_HS * 2);
    constexpr int STAGE_B = ATILE_B + BKH * T_HS * 2;

    extern __shared__ __half hsm[];
    uint32_t smb = smem_u32(hsm);
    int tid = threadIdx.x;
    int wid = tid >> 5, lane = tid & 31;
    int group = lane >> 3, lr = lane & 7;
    int g = lane >> 2, t4 = lane & 3;

    A += (size_t)blockIdx.z * sAs;
    B += (size_t)blockIdx.z * sBs;
    int m0 = blockIdx.y << 7;
    int n0 = blockIdx.x << 7;
    int wm = wid & 1, wn = wid >> 1;

    float c[4][8][4];
#pragma unroll
    for (int a = 0; a < 4; a++)
#pragma unroll
        for (int b = 0; b < 8; b++)
#pragma unroll
            for (int r = 0; r < 4; r++) c[a][b][r] = 0.f;

    int nk = K >> 5;

#pragma unroll
    for (int s = 0; s < HG_STAGES - 1; s++) {
        if (s < nk) {
            uint32_t sa = smb + (uint32_t)s * STAGE_B;
            h_fill<TRANS_A>(A, lda, B, ldb, m0, n0, s << 5, sa, sa + ATILE_B, tid);
        }
        asm volatile("cp.async.commit_group;");
    }

    for (int kt = 0; kt < nk; kt++) {
        asm volatile("cp.async.wait_group %0;" :: "n"(HG_STAGES - 2));
        __syncthreads();

        int nxt = kt + HG_STAGES - 1;
        if (nxt < nk) {
            uint32_t sa = smb + (uint32_t)(nxt & (HG_STAGES - 1)) * STAGE_B;
            h_fill<TRANS_A>(A, lda, B, ldb, m0, n0, nxt << 5, sa, sa + ATILE_B, tid);
        }
        asm volatile("cp.async.commit_group;");

        uint32_t sa = smb + (uint32_t)(kt & (HG_STAGES - 1)) * STAGE_B;
        uint32_t sb = sa + ATILE_B;
#pragma unroll
        for (int ks = 0; ks < 2; ks++) {
            uint32_t af[4][4];
#pragma unroll
            for (int mi = 0; mi < 4; mi++) {
                uint32_t addr;
                if (!TRANS_A) {
                    int arow = (wm << 6) + (mi << 4) + ((group & 1) << 3) + lr;
                    int acol = (ks << 4) + ((group >> 1) << 3);
                    addr = sa + (uint32_t)(arow * A_HS + acol) * 2;
                    ldsm_x4(af[mi], addr);
                } else {
                    int krow = (ks << 4) + ((group >> 1) << 3) + lr;
                    int mcol = (wm << 6) + (mi << 4) + ((group & 1) << 3);
                    addr = sa + (uint32_t)(krow * T_HS + mcol) * 2;
                    ldsm_x4_t(af[mi], addr);
                }
            }
            uint32_t bf[4][4];
#pragma unroll
            for (int np = 0; np < 4; np++) {
                int krow = (ks << 4) + ((group & 1) << 3) + lr;
                int ncol = (wn << 6) + (np << 4) + ((group >> 1) << 3);
                ldsm_x4_t(bf[np], sb + (uint32_t)(krow * T_HS + ncol) * 2);
            }
#pragma unroll
            for (int mi = 0; mi < 4; mi++)
#pragma unroll
                for (int ni = 0; ni < 8; ni++)
                    mma_f16(c[mi][ni], af[mi], &bf[ni >> 1][(ni & 1) << 1]);
        }
    }

    // ---- epilogue ----
    if (MODE == 2 || MODE == 5) __syncthreads();     // smem reused as logit stage
    float* stage = (float*)hsm;
    int auxrows = (int)(sCs / (size_t)ldc);
    const float GK = 0.7071067811865476f;
    const float PSCALE = 0.21022410381342865f;   // 512^-0.25
    const float PS2    = 0.02209708691207961f;   // 0.5 * 512^-0.5
#pragma unroll
    for (int mi = 0; mi < 4; mi++) {
        int r = (wm << 6) + (mi << 4) + g;
        size_t rowoff0 = (size_t)blockIdx.z * sCs + (size_t)(m0 + r) * ldc;
        size_t rowoff1 = rowoff0 + (size_t)8 * ldc;
        int ar0 = blockIdx.z * auxrows + m0 + r;
        int ar1 = ar0 + 8;
        float n2a = 0.f, n2b = 0.f, iv0 = 0.f, iv1 = 0.f;
        if (MODE == 2 || MODE == 5) { n2a = aux1[ar0]; n2b = aux1[ar1]; }
        if (MODE == 3) { iv0 = aux1[ar0]; iv1 = aux1[ar1]; }
        float ssq0 = 0.f, ssq1 = 0.f;
#pragma unroll
        for (int ni = 0; ni < 8; ni++) {
            int nn = n0 + (wn << 6) + (ni << 3) + (t4 << 1);
            float v0 = c[mi][ni][0], v1 = c[mi][ni][1];
            float v2 = c[mi][ni][2], v3 = c[mi][ni][3];
            if (bias) {
                float b0 = __ldg(bias + nn), b1 = __ldg(bias + nn + 1);
                v0 += b0; v1 += b1; v2 += b0; v3 += b1;
            }
            if (ACT == 1) {
                v0 = 0.5f * v0 * (1.f + erff(v0 * GK));
                v1 = 0.5f * v1 * (1.f + erff(v1 * GK));
                v2 = 0.5f * v2 * (1.f + erff(v2 * GK));
                v3 = 0.5f * v3 * (1.f + erff(v3 * GK));
            }
            if (MODE == 1) {
                ssq0 += v0 * v0 + v1 * v1;
                ssq1 += v2 * v2 + v3 * v3;
            }
            if (MODE == 2 || MODE == 5) {
                int rl = (wm << 6) + (mi << 4) + g;
                v0 = fmaf(v0, PSCALE, -PS2 * n2a);
                v1 = fmaf(v1, PSCALE, -PS2 * n2a);
                v2 = fmaf(v2, PSCALE, -PS2 * n2b);
                v3 = fmaf(v3, PSCALE, -PS2 * n2b);
                int nl = (wn << 6) + (ni << 3) + (t4 << 1);
                stage[rl * 132 + nl] = v0;       stage[rl * 132 + nl + 1] = v1;
                stage[(rl + 8) * 132 + nl] = v2; stage[(rl + 8) * 132 + nl + 1] = v3;
            }
            if (MODE == 3) { v0 *= iv0; v1 *= iv0; v2 *= iv1; v3 *= iv1; }
            if (MODE == 4) {
                float2 r0 = *(float2*)(C + rowoff0 + nn);
                float2 r1 = *(float2*)(C + rowoff1 + nn);
                v0 += r0.x; v1 += r0.y; v2 += r1.x; v3 += r1.y;
            }
            if (WF32) {
                *(float2*)(C + rowoff0 + nn) = make_float2(v0, v1);
                *(float2*)(C + rowoff1 + nn) = make_float2(v2, v3);
            }
            if (WF16) {
                *(__half2*)(C16 + rowoff0 + nn) = __floats2half2_rn(v0, v1);
                *(__half2*)(C16 + rowoff1 + nn) = __floats2half2_rn(v2, v3);
            }
        }
        if (MODE == 1) {
            ssq0 += __shfl_xor_sync(0xffffffffu, ssq0, 1);
            ssq0 += __shfl_xor_sync(0xffffffffu, ssq0, 2);
            ssq1 += __shfl_xor_sync(0xffffffffu, ssq1, 1);
            ssq1 += __shfl_xor_sync(0xffffffffu, ssq1, 2);
            if (t4 == 0) {
                atomicAdd(&aux1[ar0], ssq0);
                atomicAdd(&aux1[ar1], ssq1);
            }
        }
    }
    if (MODE == 2 || MODE == 5) {
        __syncthreads();
        int rr = tid;                        // one thread per row (128)
        const float* rp = stage + rr * 132;
        float m = -INFINITY;
#pragma unroll
        for (int j = 0; j < 128; j++) m = fmaxf(m, rp[j]);
        aux2[m0 + rr] = m;
        if (MODE == 5) {
            __half* dst = C16 + (size_t)(m0 + rr) * ldc;
#pragma unroll
            for (int j = 0; j < 128; j += 2) {
                float e0 = expf(rp[j]     - m) * 0.08838834764831845f;
                float e1 = expf(rp[j + 1] - m) * 0.08838834764831845f;
                *(__half2*)(dst + j) = __floats2half2_rn(e0, e1);
            }
        }
    }
}

// ================= fp32 fallback SGEMM (head only) =================
#define BM 128
#define BN 128
#define BK 8

template<int ACT>
__global__ __launch_bounds__(256)
void gemm_k(const float* __restrict__ A, int lda,
            const float* __restrict__ Bm, int ldb,
            float* __restrict__ C, int ldc,
            const float* __restrict__ bias,
            int M, int N, int K)
{
    int m0 = blockIdx.y * BM;
    int n0 = blockIdx.x * BN;

    __shared__ float As[BK][BM];
    __shared__ float Bs[BK][BN];

    int tid = threadIdx.x;
    int tx = tid & 15, ty = tid >> 4;

    float acc[8][8];
#pragma unroll
    for (int i = 0; i < 8; i++)
#pragma unroll
        for (int j = 0; j < 8; j++) acc[i][j] = 0.f;

    float ar[8], br[8];

    for (int k0 = 0; k0 < K; k0 += BK) {
        {
            int m  = tid >> 1;
            int kk = (tid & 1) * 4;
            bool mok = (m0 + m) < M;
            const float* src = A + (size_t)(m0 + m) * lda + k0 + kk;
#pragma unroll
            for (int i = 0; i < 4; i++)
                As[kk + i][m] = mok ? src[i] : 0.f;
        }
        {
            int k = tid >> 5;
            int n = (tid & 31) * 4;
            const float* src = Bm + (size_t)(k0 + k) * ldb + n0 + n;
#pragma unroll
            for (int i = 0; i < 4; i++) {
                float vv = 0.f;
                if (n0 + n + i < N) vv = src[i];
                Bs[k][n + i] = vv;
            }
        }
        __syncthreads();
#pragma unroll
        for (int k = 0; k < BK; k++) {
            *(float4*)&ar[0] = *(float4*)&As[k][ty * 4];
            *(float4*)&ar[4] = *(float4*)&As[k][64 + ty * 4];
            *(float4*)&br[0] = *(float4*)&Bs[k][tx * 4];
            *(float4*)&br[4] = *(float4*)&Bs[k][64 + tx * 4];
#pragma unroll
            for (int i = 0; i < 8; i++)
#pragma unroll
                for (int j = 0; j < 8; j++)
                    acc[i][j] = fmaf(ar[i], br[j], acc[i][j]);
        }
        __syncthreads();
    }

#pragma unroll
    for (int i = 0; i < 8; i++) {
        int m = m0 + ((i < 4) ? (ty * 4 + i) : (64 + ty * 4 + i - 4));
        if (m >= M) continue;
#pragma unroll
        for (int j = 0; j < 8; j++) {
            int n = n0 + ((j < 4) ? (tx * 4 + j) : (64 + tx * 4 + j - 4));
            if (n >= N) continue;
            float vv = acc[i][j];
            if (bias) vv += bias[n];
            if (ACT == 2) vv = fmaxf(vv, 0.f);
            C[(size_t)m * ldc + n] = vv;
        }
    }
}

// ---------------- elementwise / reduction kernels ---------------------------

__global__ void conv16_k(const float* __restrict__ in, __half* __restrict__ out, size_t n) {
    size_t i = ((size_t)blockIdx.x * 256 + threadIdx.x) * 4;
    if (i < n) {
        float4 v = *(const float4*)(in + i);
        *(__half2*)(out + i)     = __floats2half2_rn(v.x, v.y);
        *(__half2*)(out + i + 2) = __floats2half2_rn(v.z, v.w);
    }
}

__global__ void addpos_k(float* __restrict__ h, __half* __restrict__ h16,
                         const float* __restrict__ pos) {
    size_t i = (size_t)blockIdx.x * 256 + threadIdx.x;
    if (i < (size_t)ROWS * NE) {
        float v = h[i] + pos[i % ((size_t)NS * NE)];
        h[i] = v;
        h16[i] = __float2half_rn(v);
    }
}

__global__ void zero_k(float* p, int n) {
    int i = blockIdx.x * 256 + threadIdx.x;
    if (i < n) p[i] = 0.f;
}

__global__ void maxred_k(const float* __restrict__ part, int n, float* __restrict__ out) {
    __shared__ float sh[1024];
    int t = threadIdx.x;
    float m = -INFINITY;
    for (int i = t; i < n; i += 1024) m = fmaxf(m, part[i]);
    sh[t] = m; __syncthreads();
    for (int o = 512; o > 0; o >>= 1) { if (t < o) sh[t] = fmaxf(sh[t], sh[t + o]); __syncthreads(); }
    if (t == 0) out[0] = sh[0];
}

__global__ void maxredB_k(const float* __restrict__ part, float* __restrict__ out) {
    __shared__ float sh[1024];
    int t = threadIdx.x, b = blockIdx.x;
    const float* p = part + (size_t)b * NS;
    float m = -INFINITY;
    for (int i = t; i < NS; i += 1024) m = fmaxf(m, p[i]);
    sh[t] = m; __syncthreads();
    for (int o = 512; o > 0; o >>= 1) { if (t < o) sh[t] = fmaxf(sh[t], sh[t + o]); __syncthreads(); }
    if (t == 0) out[b] = sh[0];
}

// pk: read fp32 logits, write fp16 exp(l - batchmax)/sqrt(M)
__global__ void phiexp_pk_k(const float* __restrict__ G, __half* __restrict__ G16,
                            const float* __restrict__ bmax, size_t n) {
    size_t i = (size_t)blockIdx.x * 256 + threadIdx.x;
    if (i < n) {
        float bm = bmax[i >> 19];
        G16[i] = __float2half_rn(expf(G[i] - bm) * 0.08838834764831845f);
    }
}

// z'[b,m] = sum_s pk16[b,s,m]
__global__ void colsum16_k(const __half* __restrict__ pk16, float* __restrict__ z) {
    int b = blockIdx.x, chunk = blockIdx.y, m = threadIdx.x;
    const __half* p = pk16 + (size_t)b * NS * NM + (size_t)chunk * 128 * NM + m;
    float s = 0.f;
    for (int i = 0; i < 128; i++) s += __half2float(p[(size_t)i * NM]);
    atomicAdd(&z[b * NM + m], s);
}

// inv[row] = G / (G*s + 1e-6),  G = exp(rowq-mxq + bmk-mx),  s = pq16 . z'
__global__ void den_k(const __half* __restrict__ pq16, const float* __restrict__ z,
                      const float* __restrict__ rowq, const float* __restrict__ mxq,
                      const float* __restrict__ bmk, const float* __restrict__ mxk,
                      float* __restrict__ inv) {
    int warp = threadIdx.x >> 5, lane = threadIdx.x & 31;
    int row = blockIdx.x * 8 + warp;
    int b = row / NS;
    const __half* p = pq16 + (size_t)row * NM;
    const float* zz = z + b * NM;
    float s = 0.f;
#pragma unroll
    for (int j = 0; j < 4; j++)
        s = fmaf(__half2float(p[lane + 32 * j]), zz[lane + 32 * j], s);
#pragma unroll
    for (int o = 16; o > 0; o >>= 1) s += __shfl_xor_sync(0xffffffffu, s, o);
    if (lane == 0) {
        float G = expf((rowq[row] - mxq[0]) + (bmk[b] - mxk[0]));
        inv[row] = G / (fmaf(G, s, 1e-6f));
    }
}

// LayerNorm over E=512; writes fp16 only
__global__ void ln_k(const float* __restrict__ in, __half* __restrict__ out16,
                     const float* __restrict__ g, const float* __restrict__ b) {
    int row = blockIdx.x, t = threadIdx.x;
    __shared__ float sh[256];
    const float* a = in + (size_t)row * NE;
    float x0 = a[t], x1 = a[t + 256];
    sh[t] = x0 + x1; __syncthreads();
    for (int o = 128; o > 0; o >>= 1) { if (t < o) sh[t] += sh[t + o]; __syncthreads(); }
    float mu = sh[0] * (1.f / NE);
    __syncthreads();
    float d0 = x0 - mu, d1 = x1 - mu;
    sh[t] = d0 * d0 + d1 * d1; __syncthreads();
    for (int o = 128; o > 0; o >>= 1) { if (t < o) sh[t] += sh[t + o]; __syncthreads(); }
    float rstd = rsqrtf(sh[0] * (1.f / NE) + 1e-5f);
    out16[(size_t)row * NE + t]       = __float2half_rn(d0 * rstd * g[t] + b[t]);
    out16[(size_t)row * NE + t + 256] = __float2half_rn(d1 * rstd * g[t + 256] + b[t + 256]);
}

// ---------------- host-side dispatch ----------------------------------------

template<int TRANS_A, int ACT, int WF32, int WF16, int MODE>
static void hgemm(const __half* A, int lda, size_t sA,
                  const __half* Bm, int ldb, size_t sB,
                  float* C, __half* C16, int ldc, size_t sC,
                  const float* bias, int M, int N, int K, int batch,
                  float* aux1 = nullptr, float* aux2 = nullptr)
{
    constexpr int ATILE_B = TRANS_A ? (BKH * T_HS * 2) : (128 * A_HS * 2);
    constexpr int SMEM = HG_STAGES * (ATILE_B + BKH * T_HS * 2);
    cudaFuncSetAttribute(hgemm_k<TRANS_A, ACT, WF32, WF16, MODE>,
                         cudaFuncAttributeMaxDynamicSharedMemorySize, SMEM);
    dim3 grid(N >> 7, M >> 7, batch);
    hgemm_k<TRANS_A, ACT, WF32, WF16, MODE><<<grid, 128, SMEM>>>(
        A, lda, sA, Bm, ldb, sB, C, C16, ldc, sC, bias, K, aux1, aux2);
}

static void conv16(const float* in, __half* out, size_t n) {
    conv16_k<<<(unsigned)((n / 4 + 255) / 256), 256>>>(in, out, n);
}

extern "C" void kernel_launch(void* const* d_in, const int* in_sizes, int n_in,
                              void* d_out, int out_size)
{
    const float* x    = (const float*)d_in[0];
    const float* Wi   = (const float*)d_in[1];
    const float* bi   = (const float*)d_in[2];
    const float* pos  = (const float*)d_in[3];
    const float* Wq   = (const float*)d_in[4];
    const float* bq   = (const float*)d_in[5];
    const float* Wk   = (const float*)d_in[6];
    const float* bk   = (const float*)d_in[7];
    const float* Wv   = (const float*)d_in[8];
    const float* bv   = (const float*)d_in[9];
    const float* Wo   = (const float*)d_in[10];
    const float* bo   = (const float*)d_in[11];
    const float* R    = (const float*)d_in[12];
    const float* lng  = (const float*)d_in[13];
    const float* lnb  = (const float*)d_in[14];
    const float* W1   = (const float*)d_in[15];
    const float* b1   = (const float*)d_in[16];
    const float* W2   = (const float*)d_in[17];
    const float* b2   = (const float*)d_in[18];
    const float* Wr1  = (const float*)d_in[19];
    const float* br1  = (const float*)d_in[20];
    const float* Wr2  = (const float*)d_in[21];
    const float* br2  = (const float*)d_in[22];
    float* out = (float*)d_out;

    float *h,*k,*pk,*z,*part,*rowq,*nq,*nk,*inv,*mx,*mxq,*bmk,*r1;
    __half *h16,*q16,*k16,*v16,*pq16,*pk16,*kv16,*ff16,*x16;
    __half *wi16,*wq16,*wk16,*wv16,*wo16,*r16,*w116,*w216;
    cudaGetSymbolAddress((void**)&h,  g_h);
    cudaGetSymbolAddress((void**)&k,  g_k);
    cudaGetSymbolAddress((void**)&pk, g_pk);
    cudaGetSymbolAddress((void**)&z,  g_z);
    cudaGetSymbolAddress((void**)&part, g_part);
    cudaGetSymbolAddress((void**)&rowq, g_rowq);
    cudaGetSymbolAddress((void**)&nq, g_nq);
    cudaGetSymbolAddress((void**)&nk, g_nk);
    cudaGetSymbolAddress((void**)&inv, g_inv);
    cudaGetSymbolAddress((void**)&mx, g_max);
    cudaGetSymbolAddress((void**)&mxq, g_maxq);
    cudaGetSymbolAddress((void**)&bmk, g_bmk);
    cudaGetSymbolAddress((void**)&r1, g_r1);
    cudaGetSymbolAddress((void**)&h16,  g_h16);
    cudaGetSymbolAddress((void**)&q16,  g_q16);
    cudaGetSymbolAddress((void**)&k16,  g_k16);
    cudaGetSymbolAddress((void**)&v16,  g_v16);
    cudaGetSymbolAddress((void**)&pq16, g_pq16);
    cudaGetSymbolAddress((void**)&pk16, g_pk16);
    cudaGetSymbolAddress((void**)&kv16, g_kv16);
    cudaGetSymbolAddress((void**)&ff16, g_ff16);
    cudaGetSymbolAddress((void**)&x16,  g_x16);
    cudaGetSymbolAddress((void**)&wi16, g_wi16);
    cudaGetSymbolAddress((void**)&wq16, g_wq16);
    cudaGetSymbolAddress((void**)&wk16, g_wk16);
    cudaGetSymbolAddress((void**)&wv16, g_wv16);
    cudaGetSymbolAddress((void**)&wo16, g_wo16);
    cudaGetSymbolAddress((void**)&r16,  g_r16);
    cudaGetSymbolAddress((void**)&w116, g_w116);
    cudaGetSymbolAddress((void**)&w216, g_w216);

    const size_t nHE = (size_t)ROWS * NE;
    const size_t nHM = (size_t)ROWS * NM;
    int ew_grid = (int)((nHE + 255) / 256);
    int pm_grid = (int)((nHM + 255) / 256);

    // ---- fp16 weight/input mirrors ----
    conv16(x,  x16, (size_t)ROWS * NDIN);
    conv16(Wi, wi16, (size_t)NDIN * NE);
    conv16(Wq, wq16, (size_t)NL * NE * NE);
    conv16(Wk, wk16, (size_t)NL * NE * NE);
    conv16(Wv, wv16, (size_t)NL * NE * NE);
    conv16(Wo, wo16, (size_t)NL * NE * NE);
    conv16(R,  r16,  (size_t)NL * NE * NM);
    conv16(W1, w116, (size_t)NL * NE * HID);
    conv16(W2, w216, (size_t)NL * HID * NE);

    // h = x @ Wi + bi ; then += pos (dual-write h16)
    hgemm<0,0,1,0,0>(x16, NDIN,0, wi16, NE,0, h, nullptr, NE,0, bi, ROWS, NE, NDIN, 1);
    addpos_k<<<ew_grid,256>>>(h, h16, pos);

    for (int i = 0; i < NL; i++) {
        const __half* wq_i = wq16 + (size_t)i*NE*NE;  const float* bq_i = bq + (size_t)i*NE;
        const __half* wk_i = wk16 + (size_t)i*NE*NE;  const float* bk_i = bk + (size_t)i*NE;
        const __half* wv_i = wv16 + (size_t)i*NE*NE;  const float* bv_i = bv + (size_t)i*NE;
        const __half* wo_i = wo16 + (size_t)i*NE*NE;  const float* bo_i = bo + (size_t)i*NE;
        const __half* r_i  = r16  + (size_t)i*NE*NM;
        const float* g_i  = lng + (size_t)i*NE;       const float* b_i  = lnb + (size_t)i*NE;
        const __half* w1_i = w116 + (size_t)i*NE*HID; const float* b1_i = b1 + (size_t)i*HID;
        const __half* w2_i = w216 + (size_t)i*HID*NE; const float* b2_i = b2 + (size_t)i*NE;

        // zero sumsq accumulators
        zero_k<<<ROWS/256,256>>>(nq, ROWS);
        zero_k<<<ROWS/256,256>>>(nk, ROWS);

        // projections: Q/K with fused per-row sumsq, V plain
        hgemm<0,0,0,1,1>(h16, NE,0, wq_i, NE,0, nullptr, q16, NE,0, bq_i, ROWS, NE, NE, 1, nq);
        hgemm<0,0,0,1,1>(h16, NE,0, wk_i, NE,0, nullptr, k16, NE,0, bk_i, ROWS, NE, NE, 1, nk);
        hgemm<0,0,0,1,0>(h16, NE,0, wv_i, NE,0, nullptr, v16, NE,0, bv_i, ROWS, NE, NE, 1);

        // phi-q FULLY FUSED: logits + rowmax + exp -> pq16 (row-normalized)
        hgemm<0,0,0,0,5>(q16, NE,0, r_i, NM,0, nullptr, pq16, NM,0, nullptr, ROWS, NM, NE, 1, nq, rowq);
        maxred_k<<<1,1024>>>(rowq, ROWS, mxq);

        // phi-k: fused logits + rowmax (logits fp32 in pk, rowmax in part)
        hgemm<0,0,1,0,2>(k16, NE,0, r_i, NM,0, pk, nullptr, NM,0, nullptr, ROWS, NM, NE, 1, nk, part);
        maxred_k<<<1,1024>>>(part, ROWS, mx);
        maxredB_k<<<NB,1024>>>(part, bmk);
        phiexp_pk_k<<<pm_grid,256>>>(pk, pk16, bmk, nHM);

        // kv[b] = pk16[b]^T @ v16[b]
        hgemm<1,0,0,1,0>(pk16, NM, (size_t)NS*NM, v16, NE, (size_t)NS*NE,
                         nullptr, kv16, NE, (size_t)NM*NE, nullptr, NM, NE, NS, NB);

        // z'[b] = sum_s pk16[b,s,:]
        zero_k<<<(NB*NM+255)/256,256>>>(z, NB*NM);
        colsum16_k<<<dim3(NB,32),128>>>(pk16, z);

        // inv[row] = G / (G*(pq16.z') + 1e-6)
        den_k<<<ROWS/8,256>>>(pq16, z, rowq, mxq, bmk, mx, inv);

        // num GEMM with fused row scaling -> q16
        hgemm<0,0,0,1,3>(pq16, NM, (size_t)NS*NM, kv16, NE, (size_t)NM*NE,
                         nullptr, q16, NE, (size_t)NS*NE, nullptr, NS, NE, NM, NB, inv);

        // a -> k (fp32, LN input)
        hgemm<0,0,1,0,0>(q16, NE,0, wo_i, NE,0, k, nullptr, NE,0, bo_i, ROWS, NE, NE, 1);

        // y -> v16 (LayerNorm)
        ln_k<<<ROWS,256>>>(k, v16, g_i, b_i);

        // ff1 = gelu(y @ W1 + b1) -> ff16
        hgemm<0,1,0,1,0>(v16, NE,0, w1_i, HID,0, nullptr, ff16, HID,0, b1_i, ROWS, HID, NE, 1);
        // ff2 with fused residual: h = ff2 + b2 + h ; dual-write h16
        hgemm<0,0,1,1,4>(ff16, HID,0, w2_i, NE,0, h, h16, NE,0, b2_i, ROWS, NE, HID, 1);
    }

    // head: pooled = h[:,0,:] — tiny, fp32 path
    {
        dim3 g1((256 + BN - 1) / BN, (NB + BM - 1) / BM);
        gemm_k<2><<<g1, 256>>>(h, NS*NE, Wr1, 256, r1, 256, br1, NB, 256, NE);
        dim3 g2(1, 1);
        gemm_k<0><<<g2, 256>>>(r1, 256, Wr2, 1, out, 1, br2, NB, 1, 256);
    }
}